// round 6
// baseline (speedup 1.0000x reference)
#include <cuda_runtime.h>
#include <cuda_fp16.h>
#include <cstdint>
#include <cstddef>

using u32 = uint32_t;
using u64 = uint64_t;
#define MTOT 8192

// ---------------- static scratch (no allocation) ----------------
__device__ __half g_xqh[MTOT * 1024], g_xql[MTOT * 1024];
__device__ __half g_xkh[MTOT * 1024], g_xkl[MTOT * 1024];
__device__ __half g_wqh[1024 * 1024], g_wql[1024 * 1024];
__device__ __half g_wkh[1024 * 1024], g_wkl[1024 * 1024];
__device__ __half g_wvh[1024 * 1024];
__device__ __half g_woh[1024 * 1024];
__device__ __half g_qh[MTOT * 1024], g_ql[MTOT * 1024];
__device__ __half g_kh[MTOT * 1024], g_kl[MTOT * 1024];
__device__ __half g_vh[MTOT * 1024];
__device__ __half g_vt[MTOT * 1024];
__device__ __half g_ch[MTOT * 1024], g_cl[MTOT * 1024];

// ---------------- helpers ----------------
__device__ __forceinline__ u32 smem_u32(const void* p) {
    u32 a;
    asm("{ .reg .u64 t; cvta.to.shared.u64 t, %1; cvt.u32.u64 %0, t; }"
        : "=r"(a) : "l"(p));
    return a;
}
__device__ __forceinline__ void split2(float f0, float f1, u32& h, u32& l) {
    __half a = __float2half_rn(f0), b = __float2half_rn(f1);
    h = (u32)__half_as_ushort(a) | ((u32)__half_as_ushort(b) << 16);
    __half c = __float2half_rn(f0 - __half2float(a));
    __half d = __float2half_rn(f1 - __half2float(b));
    l = (u32)__half_as_ushort(c) | ((u32)__half_as_ushort(d) << 16);
}
__device__ __forceinline__ u32 pack2(float f0, float f1) {
    __half2 hh = __floats2half2_rn(f0, f1);
    return *reinterpret_cast<u32*>(&hh);
}
__device__ __forceinline__ void cpa16(u32 s, const void* g) {
    asm volatile("cp.async.cg.shared.global [%0], [%1], 16;"
                 :: "r"(s), "l"((u64)__cvta_generic_to_global(g)));
}
__device__ __forceinline__ void ldm4(u32* r, u32 addr) {
    asm volatile("ldmatrix.sync.aligned.m8n8.x4.shared.b16 {%0,%1,%2,%3}, [%4];"
                 : "=r"(r[0]), "=r"(r[1]), "=r"(r[2]), "=r"(r[3]) : "r"(addr));
}
__device__ __forceinline__ void mma16816(float* d, const u32* a, const u32* b) {
    asm volatile(
        "mma.sync.aligned.m16n8k16.row.col.f32.f16.f16.f32 "
        "{%0,%1,%2,%3},{%4,%5,%6,%7},{%8,%9},{%0,%1,%2,%3};"
        : "+f"(d[0]), "+f"(d[1]), "+f"(d[2]), "+f"(d[3])
        : "r"(a[0]), "r"(a[1]), "r"(a[2]), "r"(a[3]), "r"(b[0]), "r"(b[1]));
}

// ---------------- kernel: split fp32 inputs to hi/lo fp16 ----------------
__global__ __launch_bounds__(256) void split_inputs_k(
    const float* __restrict__ q, const float* __restrict__ kk) {
    size_t idx = (size_t)blockIdx.x * 256 + threadIdx.x;  // 0..2M-1
    size_t i = idx & ((1u << 20) - 1);
    const float* src = (idx < (1u << 20)) ? q : kk;
    __half* dh = (idx < (1u << 20)) ? g_xqh : g_xkh;
    __half* dl = (idx < (1u << 20)) ? g_xql : g_xkl;
    size_t e = i * 8;
    float4 a = ((const float4*)(src + e))[0];
    float4 b = ((const float4*)(src + e))[1];
    float f[8] = {a.x, a.y, a.z, a.w, b.x, b.y, b.z, b.w};
    u32 ph[4], pl[4];
#pragma unroll
    for (int j = 0; j < 4; j++) split2(f[2 * j], f[2 * j + 1], ph[j], pl[j]);
    *(uint4*)(dh + e) = make_uint4(ph[0], ph[1], ph[2], ph[3]);
    *(uint4*)(dl + e) = make_uint4(pl[0], pl[1], pl[2], pl[3]);
}

// ---------------- kernel: factorized weights -> fp16 (split where needed) ---
__global__ __launch_bounds__(256) void build_weights_k(
    const float* __restrict__ wq_f, const float* __restrict__ wkv_f,
    const float* __restrict__ wo_f, const float* __restrict__ tgt,
    const float* __restrict__ src) {
    u32 n = blockIdx.x * 256 + threadIdx.x;  // 0..4M-1
    u32 seg = n >> 20, m = n & 1048575;
    const float* w;
    const float* f;
    __half *dh, *dl = nullptr;
    float scale = 1.f;
    if (seg == 0) { w = wq_f + (size_t)m * 8; f = tgt; dh = g_wqh; dl = g_wql; scale = 0.125f; }
    else if (seg == 1) { w = wkv_f + (size_t)m * 8; f = src; dh = g_wkh; dl = g_wkl; }
    else if (seg == 2) { w = wkv_f + ((size_t)1048576 + m) * 8; f = src; dh = g_wvh; }
    else { w = wo_f + (size_t)m * 8; f = tgt; dh = g_woh; }
    float acc = 0.f;
#pragma unroll
    for (int r = 0; r < 8; r++) acc += w[r] * f[r];
    acc *= scale;
    __half h = __float2half_rn(acc);
    dh[m] = h;
    if (dl) dl[m] = __float2half_rn(acc - __half2float(h));
}

// ---------------- mma.sync GEMM: C = sum_t A_t[M,K] @ B_t[N,K]^T ----------
// BM=128, BN=128, BK=32, 256 threads (8 warps as 4x2), 3-stage cp.async.
// EPI 0: fp32 -> CF. EPI 1: split fp16 -> CH/CL. EPI 2: plain fp16 -> CH.
template <int BN, int NTERM, int EPI>
__global__ __launch_bounds__(256) void gemmh(
    const __half* A0, const __half* B0, const __half* A1, const __half* B1,
    const __half* A2, const __half* B2, int K, int lda, int ldb,
    float* CF, __half* CH, __half* CL) {
    constexpr int ROWS = 128 + BN;
    constexpr int STAGE = ROWS * 64;
    constexpr int NPASS = ROWS / 64;
    constexpr int NT8 = BN / 16;
    extern __shared__ char smem[];
    const u32 sbase = smem_u32(smem);

    const int tid = threadIdx.x, lane = tid & 31, wid = tid >> 5;
    const int m0 = blockIdx.y * 128, n0 = blockIdx.x * BN;
    const __half* Aarr[3] = {A0, A1, A2};
    const __half* Barr[3] = {B0, B1, B2};

    const int nkc = K >> 5;
    const int NI = NTERM * nkc;

    float acc[2][NT8][4];
#pragma unroll
    for (int a = 0; a < 2; a++)
#pragma unroll
        for (int b = 0; b < NT8; b++)
#pragma unroll
            for (int c = 0; c < 4; c++) acc[a][b][c] = 0.f;

    auto load_stage = [&](int it, int bufi) {
        const int t = it / nkc, kc = it - t * nkc;
        const __half* Ab = Aarr[t] + (size_t)m0 * lda + kc * 32;
        const __half* Bb = Barr[t] + (size_t)n0 * ldb + kc * 32;
        const u32 sb = sbase + bufi * STAGE;
#pragma unroll
        for (int p = 0; p < NPASS; p++) {
            const int L = p * 256 + tid;
            const int row = L >> 2, c = L & 3;
            const __half* g = (row < 128)
                ? Ab + (size_t)row * lda + c * 8
                : Bb + (size_t)(row - 128) * ldb + c * 8;
            cpa16(sb + row * 64 + ((c ^ ((row >> 1) & 3)) << 4), g);
        }
    };

    load_stage(0, 0);
    asm volatile("cp.async.commit_group;");
    load_stage(1, 1);
    asm volatile("cp.async.commit_group;");
    const int wm = wid >> 1, wn = wid & 1;
    for (int it = 0; it < NI; it++) {
        if (it + 2 < NI) {
            int nx = it + 2;
            load_stage(nx, nx - (nx / 3) * 3);
        }
        asm volatile("cp.async.commit_group;");
        asm volatile("cp.async.wait_group 2;");
        __syncthreads();
        const u32 sb = sbase + (it - (it / 3) * 3) * STAGE;
#pragma unroll
        for (int kstep = 0; kstep < 2; kstep++) {
            u32 ra[2][4];
#pragma unroll
            for (int mt = 0; mt < 2; mt++) {
                int row = wm * 32 + mt * 16 + (lane & 15);
                int c = kstep * 2 + (lane >> 4);
                ldm4(ra[mt], sb + row * 64 + ((c ^ ((row >> 1) & 3)) << 4));
            }
            u32 rb[NT8][2];
#pragma unroll
            for (int np = 0; np < NT8 / 2; np++) {
                int i = lane & 7, seg = lane >> 3;
                int row = 128 + wn * (BN / 2) + np * 16 + (seg >> 1) * 8 + i;
                int c = kstep * 2 + (seg & 1);
                u32 r4[4];
                ldm4(r4, sb + row * 64 + ((c ^ ((row >> 1) & 3)) << 4));
                rb[np * 2][0] = r4[0]; rb[np * 2][1] = r4[1];
                rb[np * 2 + 1][0] = r4[2]; rb[np * 2 + 1][1] = r4[3];
            }
#pragma unroll
            for (int mt = 0; mt < 2; mt++)
#pragma unroll
                for (int nt = 0; nt < NT8; nt++)
                    mma16816(acc[mt][nt], ra[mt], rb[nt]);
        }
        __syncthreads();
    }

    const int r0 = m0 + wm * 32 + (lane >> 2);
    const int cb = n0 + wn * (BN / 2) + (lane & 3) * 2;
#pragma unroll
    for (int mt = 0; mt < 2; mt++)
#pragma unroll
        for (int nt = 0; nt < NT8; nt++) {
            int col = cb + nt * 8;
#pragma unroll
            for (int hh = 0; hh < 2; hh++) {
                int rr = r0 + mt * 16 + hh * 8;
                float f0 = acc[mt][nt][hh * 2], f1 = acc[mt][nt][hh * 2 + 1];
                size_t addr = (size_t)rr * 1024 + col;
                if constexpr (EPI == 0) {
                    *(float2*)(CF + addr) = make_float2(f0, f1);
                } else if constexpr (EPI == 1) {
                    u32 h, l;
                    split2(f0, f1, h, l);
                    *(u32*)(CH + addr) = h;
                    *(u32*)(CL + addr) = l;
                } else {
                    *(u32*)(CH + addr) = pack2(f0, f1);
                }
            }
        }
}

// ---------------- kernel: V transpose (s*8+b,1024) -> (bh*64+d, s) ----------
__global__ __launch_bounds__(256) void transpose_v_k() {
    __shared__ __half th[32][33];
    int z = blockIdx.z, b = z >> 4, h = z & 15;
    int s0 = blockIdx.x * 32, d0 = blockIdx.y * 32;
    int r = threadIdx.x >> 5, c = threadIdx.x & 31;
#pragma unroll
    for (int p = 0; p < 4; p++) {
        int rr = r + p * 8;
        th[rr][c] = g_vh[(size_t)((s0 + rr) * 8 + b) * 1024 + h * 64 + d0 + c];
    }
    __syncthreads();
#pragma unroll
    for (int p = 0; p < 4; p++) {
        int rr = r + p * 8;
        g_vt[(size_t)(z * 64 + d0 + rr) * 1024 + s0 + c] = th[c][rr];
    }
}

// ---------------- fused flash attention ----------------
// grid (T/128, B*H). 256 threads = 8 warps; warp owns 16 q rows.
// s-tiles of 64 keys, double-buffered: kh,kl,vt tiles (64x64 each).
// 3-term split S (qh.kh + ql.kh + qh.kl), online softmax, ctx += P.V.
__global__ __launch_bounds__(256) void attn_fused_k(const unsigned char* __restrict__ mask) {
    extern __shared__ char smem[];
    const u32 sbase = smem_u32(smem);
    const int tid = threadIdx.x, lane = tid & 31, w = tid >> 5;
    const int z = blockIdx.y, b = z >> 4, h = z & 15;
    const int t0 = blockIdx.x * 128;
    const int r = lane >> 2, cp = (lane & 3) * 2;
    constexpr int STAGE = 3 * 8192;

    u32 qa[2][4][4];
    {
        const int mrow = t0 + w * 16 + r;
#pragma unroll
        for (int c = 0; c < 4; c++)
#pragma unroll
            for (int i = 0; i < 4; i++) {
                int mm = mrow + (i & 1) * 8;
                int col = h * 64 + c * 16 + cp + (i >> 1) * 8;
                size_t ad = ((size_t)(mm * 8 + b)) * 1024 + col;
                qa[0][c][i] = *(const u32*)(g_qh + ad);
                qa[1][c][i] = *(const u32*)(g_ql + ad);
            }
    }

    float ctx[8][4];
#pragma unroll
    for (int j = 0; j < 8; j++)
#pragma unroll
        for (int c = 0; c < 4; c++) ctx[j][c] = 0.f;
    float m0 = -1e30f, m1 = -1e30f, l0 = 0.f, l1 = 0.f;

    auto load_stage = [&](int it) {
        const int st = it & 1;
        const int s0 = it * 64;
        const u32 sb = sbase + st * STAGE;
#pragma unroll
        for (int p = 0; p < 6; p++) {
            int L = p * 256 + tid;
            int tile = L >> 9, rr = (L >> 3) & 63, c = L & 7;
            const __half* g;
            if (tile == 0)
                g = g_kh + ((size_t)((s0 + rr) * 8 + b)) * 1024 + h * 64 + c * 8;
            else if (tile == 1)
                g = g_kl + ((size_t)((s0 + rr) * 8 + b)) * 1024 + h * 64 + c * 8;
            else
                g = g_vt + ((size_t)(z * 64 + rr)) * 1024 + s0 + c * 8;
            cpa16(sb + tile * 8192 + rr * 128 + ((c ^ (rr & 7)) << 4), g);
        }
        if (tid < 64)
            ((float*)(smem + 2 * STAGE + st * 256))[tid] =
                mask[b * 1024 + s0 + tid] ? -1e30f : 0.f;
    };

    load_stage(0);
    asm volatile("cp.async.commit_group;");
    int buf = 0;
    for (int it = 0; it < 16; it++) {
        if (it < 15) load_stage(it + 1);
        asm volatile("cp.async.commit_group;");
        asm volatile("cp.async.wait_group 1;");
        __syncthreads();
        const u32 sb = sbase + buf * STAGE;

        float sc[8][4];
#pragma unroll
        for (int j = 0; j < 8; j++)
#pragma unroll
            for (int c = 0; c < 4; c++) sc[j][c] = 0.f;

        const int i8 = lane & 7, seg = lane >> 3;
#pragma unroll
        for (int c = 0; c < 4; c++) {
            u32 bf[8][2];
#pragma unroll
            for (int np = 0; np < 4; np++) {
                int row = np * 16 + (seg >> 1) * 8 + i8;
                int cc = c * 2 + (seg & 1);
                u32 r4[4];
                ldm4(r4, sb + row * 128 + ((cc ^ (row & 7)) << 4));
                bf[np * 2][0] = r4[0]; bf[np * 2][1] = r4[1];
                bf[np * 2 + 1][0] = r4[2]; bf[np * 2 + 1][1] = r4[3];
            }
#pragma unroll
            for (int j = 0; j < 8; j++) mma16816(sc[j], qa[0][c], bf[j]);
#pragma unroll
            for (int j = 0; j < 8; j++) mma16816(sc[j], qa[1][c], bf[j]);
        }
#pragma unroll
        for (int c = 0; c < 4; c++) {
            u32 bf[8][2];
#pragma unroll
            for (int np = 0; np < 4; np++) {
                int row = np * 16 + (seg >> 1) * 8 + i8;
                int cc = c * 2 + (seg & 1);
                u32 r4[4];
                ldm4(r4, sb + 8192 + row * 128 + ((cc ^ (row & 7)) << 4));
                bf[np * 2][0] = r4[0]; bf[np * 2][1] = r4[1];
                bf[np * 2 + 1][0] = r4[2]; bf[np * 2 + 1][1] = r4[3];
            }
#pragma unroll
            for (int j = 0; j < 8; j++) mma16816(sc[j], qa[0][c], bf[j]);
        }

        const float* bias = (const float*)(smem + 2 * STAGE + buf * 256);
        float mx0 = -1e30f, mx1 = -1e30f;
#pragma unroll
        for (int j = 0; j < 8; j++) {
            int col = j * 8 + cp;
            float b0 = bias[col], b1 = bias[col + 1];
            sc[j][0] += b0; sc[j][1] += b1;
            sc[j][2] += b0; sc[j][3] += b1;
            mx0 = fmaxf(mx0, fmaxf(sc[j][0], sc[j][1]));
            mx1 = fmaxf(mx1, fmaxf(sc[j][2], sc[j][3]));
        }
        mx0 = fmaxf(mx0, __shfl_xor_sync(~0u, mx0, 1));
        mx0 = fmaxf(mx0, __shfl_xor_sync(~0u, mx0, 2));
        mx1 = fmaxf(mx1, __shfl_xor_sync(~0u, mx1, 1));
        mx1 = fmaxf(mx1, __shfl_xor_sync(~0u, mx1, 2));
        float nm0 = fmaxf(m0, mx0), nm1 = fmaxf(m1, mx1);
        float cr0 = __expf(m0 - nm0), cr1 = __expf(m1 - nm1);
        m0 = nm0; m1 = nm1;
        float sum0 = 0.f, sum1 = 0.f;
#pragma unroll
        for (int j = 0; j < 8; j++) {
            sc[j][0] = __expf(sc[j][0] - nm0);
            sc[j][1] = __expf(sc[j][1] - nm0);
            sc[j][2] = __expf(sc[j][2] - nm1);
            sc[j][3] = __expf(sc[j][3] - nm1);
            sum0 += sc[j][0] + sc[j][1];
            sum1 += sc[j][2] + sc[j][3];
        }
        sum0 += __shfl_xor_sync(~0u, sum0, 1);
        sum0 += __shfl_xor_sync(~0u, sum0, 2);
        sum1 += __shfl_xor_sync(~0u, sum1, 1);
        sum1 += __shfl_xor_sync(~0u, sum1, 2);
        l0 = l0 * cr0 + sum0;
        l1 = l1 * cr1 + sum1;
#pragma unroll
        for (int j = 0; j < 8; j++) {
            ctx[j][0] *= cr0; ctx[j][1] *= cr0;
            ctx[j][2] *= cr1; ctx[j][3] *= cr1;
        }

        u32 pa[4][4];
#pragma unroll
        for (int c = 0; c < 4; c++) {
            pa[c][0] = pack2(sc[2 * c][0], sc[2 * c][1]);
            pa[c][1] = pack2(sc[2 * c][2], sc[2 * c][3]);
            pa[c][2] = pack2(sc[2 * c + 1][0], sc[2 * c + 1][1]);
            pa[c][3] = pack2(sc[2 * c + 1][2], sc[2 * c + 1][3]);
        }

#pragma unroll
        for (int c = 0; c < 4; c++) {
            u32 bv[8][2];
#pragma unroll
            for (int np = 0; np < 4; np++) {
                int row = np * 16 + (seg >> 1) * 8 + i8;
                int cc = c * 2 + (seg & 1);
                u32 r4[4];
                ldm4(r4, sb + 16384 + row * 128 + ((cc ^ (row & 7)) << 4));
                bv[np * 2][0] = r4[0]; bv[np * 2][1] = r4[1];
                bv[np * 2 + 1][0] = r4[2]; bv[np * 2 + 1][1] = r4[3];
            }
#pragma unroll
            for (int j = 0; j < 8; j++) mma16816(ctx[j], pa[c], bv[j]);
        }
        __syncthreads();
        buf ^= 1;
    }

    const float inv0 = 1.f / l0, inv1 = 1.f / l1;
    const int mrow = t0 + w * 16 + r;
#pragma unroll
    for (int j = 0; j < 8; j++) {
        int col = h * 64 + j * 8 + cp;
        u32 hh, ll;
        split2(ctx[j][0] * inv0, ctx[j][1] * inv0, hh, ll);
        size_t a0 = ((size_t)(mrow * 8 + b)) * 1024 + col;
        *(u32*)(g_ch + a0) = hh;
        *(u32*)(g_cl + a0) = ll;
        split2(ctx[j][2] * inv1, ctx[j][3] * inv1, hh, ll);
        size_t a1 = ((size_t)((mrow + 8) * 8 + b)) * 1024 + col;
        *(u32*)(g_ch + a1) = hh;
        *(u32*)(g_cl + a1) = ll;
    }
}

// ---------------- launch ----------------
extern "C" void kernel_launch(void* const* d_in, const int* in_sizes, int n_in,
                              void* d_out, int out_size) {
    const float* query = (const float*)d_in[0];
    const float* key = (const float*)d_in[1];
    const float* tgt = (const float*)d_in[2];
    const float* src = (const float*)d_in[3];
    const float* wq_f = (const float*)d_in[4];
    const float* wkv_f = (const float*)d_in[5];
    const float* wo_f = (const float*)d_in[6];
    const unsigned char* mask = (const unsigned char*)d_in[7];
    float* out = (float*)d_out;

#define SYM(v, s) cudaGetSymbolAddress((void**)&v, s)
    __half *xqh, *xql, *xkh, *xkl, *wqh, *wql, *wkh, *wkl, *wvh, *woh;
    __half *qh, *ql, *kh, *kl, *vh, *ch, *cl;
    SYM(xqh, g_xqh); SYM(xql, g_xql); SYM(xkh, g_xkh); SYM(xkl, g_xkl);
    SYM(wqh, g_wqh); SYM(wql, g_wql); SYM(wkh, g_wkh); SYM(wkl, g_wkl);
    SYM(wvh, g_wvh); SYM(woh, g_woh);
    SYM(qh, g_qh); SYM(ql, g_ql); SYM(kh, g_kh); SYM(kl, g_kl);
    SYM(vh, g_vh); SYM(ch, g_ch); SYM(cl, g_cl);

    const int SM128 = 3 * 256 * 64;        // 48 KB, 3-stage
    const int SMATT = 2 * 3 * 8192 + 512;  // 49.5 KB
    cudaFuncSetAttribute(attn_fused_k,
                         cudaFuncAttributeMaxDynamicSharedMemorySize, SMATT);
    cudaFuncSetAttribute(gemmh<128, 3, 1>,
                         cudaFuncAttributeMaxDynamicSharedMemorySize, SM128);
    cudaFuncSetAttribute(gemmh<128, 2, 2>,
                         cudaFuncAttributeMaxDynamicSharedMemorySize, SM128);
    cudaFuncSetAttribute(gemmh<128, 2, 0>,
                         cudaFuncAttributeMaxDynamicSharedMemorySize, SM128);

    split_inputs_k<<<8192, 256>>>(query, key);
    build_weights_k<<<16384, 256>>>(wq_f, wkv_f, wo_f, tgt, src);

    // q/k projections (3-term split, split fp16 out)
    gemmh<128, 3, 1><<<dim3(8, 64), 256, SM128>>>(
        xqh, wqh, xql, wqh, xqh, wql, 1024, 1024, 1024, nullptr, qh, ql);
    gemmh<128, 3, 1><<<dim3(8, 64), 256, SM128>>>(
        xkh, wkh, xkl, wkh, xkh, wkl, 1024, 1024, 1024, nullptr, kh, kl);
    // v projection (2-term, plain fp16 out)
    gemmh<128, 2, 2><<<dim3(8, 64), 256, SM128>>>(
        xkh, wvh, xkl, wvh, nullptr, nullptr, 1024, 1024, 1024, nullptr, vh, nullptr);

    transpose_v_k<<<dim3(32, 2, 128), 256>>>();

    // fused attention: scores(3-term) + mask + softmax + P@V(1-term)
    attn_fused_k<<<dim3(8, 128), 256, SMATT>>>(mask);

    // out = ctx @ wo^T (2-term: ch,cl vs woh), fp32 out
    gemmh<128, 2, 0><<<dim3(8, 64), 256, SM128>>>(
        ch, woh, cl, woh, nullptr, nullptr, 1024, 1024, 1024, out, nullptr, nullptr);
}

// round 7
// speedup vs baseline: 1.5042x; 1.5042x over previous
#include <cuda_runtime.h>
#include <cuda_fp16.h>
#include <cstdint>
#include <cstddef>

using u32 = uint32_t;
using u64 = uint64_t;
#define MTOT 8192

// ---------------- static scratch (no allocation) ----------------
__device__ __half g_xqh[MTOT * 1024], g_xql[MTOT * 1024];
__device__ __half g_xkh[MTOT * 1024], g_xkl[MTOT * 1024];
__device__ __half g_wqh[1024 * 1024], g_wql[1024 * 1024];
__device__ __half g_wkh[1024 * 1024], g_wkl[1024 * 1024];
__device__ __half g_wvh[1024 * 1024];
__device__ __half g_woh[1024 * 1024];
__device__ __half g_qh[MTOT * 1024], g_ql[MTOT * 1024];
__device__ __half g_kh[MTOT * 1024], g_kl[MTOT * 1024];
__device__ __half g_vh[MTOT * 1024];
__device__ __half g_vt[MTOT * 1024];
__device__ __half g_ch[MTOT * 1024], g_cl[MTOT * 1024];

// ---------------- helpers ----------------
__device__ __forceinline__ u32 smem_u32(const void* p) {
    u32 a;
    asm("{ .reg .u64 t; cvta.to.shared.u64 t, %1; cvt.u32.u64 %0, t; }"
        : "=r"(a) : "l"(p));
    return a;
}
__device__ __forceinline__ void split2(float f0, float f1, u32& h, u32& l) {
    __half a = __float2half_rn(f0), b = __float2half_rn(f1);
    h = (u32)__half_as_ushort(a) | ((u32)__half_as_ushort(b) << 16);
    __half c = __float2half_rn(f0 - __half2float(a));
    __half d = __float2half_rn(f1 - __half2float(b));
    l = (u32)__half_as_ushort(c) | ((u32)__half_as_ushort(d) << 16);
}
__device__ __forceinline__ u32 pack2(float f0, float f1) {
    __half2 hh = __floats2half2_rn(f0, f1);
    return *reinterpret_cast<u32*>(&hh);
}
__device__ __forceinline__ void cpa16(u32 s, const void* g) {
    asm volatile("cp.async.cg.shared.global [%0], [%1], 16;"
                 :: "r"(s), "l"((u64)__cvta_generic_to_global(g)));
}
__device__ __forceinline__ void ldm4(u32* r, u32 addr) {
    asm volatile("ldmatrix.sync.aligned.m8n8.x4.shared.b16 {%0,%1,%2,%3}, [%4];"
                 : "=r"(r[0]), "=r"(r[1]), "=r"(r[2]), "=r"(r[3]) : "r"(addr));
}
__device__ __forceinline__ void mma16816(float* d, const u32* a, const u32* b) {
    asm volatile(
        "mma.sync.aligned.m16n8k16.row.col.f32.f16.f16.f32 "
        "{%0,%1,%2,%3},{%4,%5,%6,%7},{%8,%9},{%0,%1,%2,%3};"
        : "+f"(d[0]), "+f"(d[1]), "+f"(d[2]), "+f"(d[3])
        : "r"(a[0]), "r"(a[1]), "r"(a[2]), "r"(a[3]), "r"(b[0]), "r"(b[1]));
}

// ---------------- kernel: split fp32 inputs to hi/lo fp16 ----------------
__global__ __launch_bounds__(256) void split_inputs_k(
    const float* __restrict__ q, const float* __restrict__ kk) {
    size_t idx = (size_t)blockIdx.x * 256 + threadIdx.x;  // 0..2M-1
    size_t i = idx & ((1u << 20) - 1);
    const float* src = (idx < (1u << 20)) ? q : kk;
    __half* dh = (idx < (1u << 20)) ? g_xqh : g_xkh;
    __half* dl = (idx < (1u << 20)) ? g_xql : g_xkl;
    size_t e = i * 8;
    float4 a = ((const float4*)(src + e))[0];
    float4 b = ((const float4*)(src + e))[1];
    float f[8] = {a.x, a.y, a.z, a.w, b.x, b.y, b.z, b.w};
    u32 ph[4], pl[4];
#pragma unroll
    for (int j = 0; j < 4; j++) split2(f[2 * j], f[2 * j + 1], ph[j], pl[j]);
    *(uint4*)(dh + e) = make_uint4(ph[0], ph[1], ph[2], ph[3]);
    *(uint4*)(dl + e) = make_uint4(pl[0], pl[1], pl[2], pl[3]);
}

// ---------------- kernel: factorized weights -> fp16 (split where needed) ---
__global__ __launch_bounds__(256) void build_weights_k(
    const float* __restrict__ wq_f, const float* __restrict__ wkv_f,
    const float* __restrict__ wo_f, const float* __restrict__ tgt,
    const float* __restrict__ src) {
    u32 n = blockIdx.x * 256 + threadIdx.x;  // 0..4M-1
    u32 seg = n >> 20, m = n & 1048575;
    const float* w;
    const float* f;
    __half *dh, *dl = nullptr;
    float scale = 1.f;
    if (seg == 0) { w = wq_f + (size_t)m * 8; f = tgt; dh = g_wqh; dl = g_wql; scale = 0.125f; }
    else if (seg == 1) { w = wkv_f + (size_t)m * 8; f = src; dh = g_wkh; dl = g_wkl; }
    else if (seg == 2) { w = wkv_f + ((size_t)1048576 + m) * 8; f = src; dh = g_wvh; }
    else { w = wo_f + (size_t)m * 8; f = tgt; dh = g_woh; }
    float acc = 0.f;
#pragma unroll
    for (int r = 0; r < 8; r++) acc += w[r] * f[r];
    acc *= scale;
    __half h = __float2half_rn(acc);
    dh[m] = h;
    if (dl) dl[m] = __float2half_rn(acc - __half2float(h));
}

// ---------------- fused-term mma.sync GEMM --------------------------------
// C = Ah@Bh^T + Al@Bh^T (+ Ah@Bl^T if NTILE==4). M=8192, N=1024, K=1024.
// BM=128, BN=128, BK=32. Stage holds {Ah, Al, Bh[, Bl]} tiles; B-frag regs
// are reused across term passes. 2-stage cp.async. 256 thr = 8 warps (4x2).
// EPI 0: fp32 -> CF. EPI 1: split fp16 -> CH/CL. EPI 2: plain fp16 -> CH.
template <int NTILE, int EPI>
__global__ __launch_bounds__(256, 2) void gemmf(
    const __half* __restrict__ Ah, const __half* __restrict__ Al,
    const __half* __restrict__ Bh, const __half* __restrict__ Bl,
    float* CF, __half* CH, __half* CL) {
    constexpr int STAGE = NTILE * 128 * 64;
    constexpr int NPASS = NTILE * 2;
    extern __shared__ char smem[];
    const u32 sbase = smem_u32(smem);

    const int tid = threadIdx.x, lane = tid & 31, wid = tid >> 5;
    const int m0 = blockIdx.y * 128, n0 = blockIdx.x * 128;
    const __half* tiles[4];
    tiles[0] = Ah + (size_t)m0 * 1024;
    tiles[1] = Al + (size_t)m0 * 1024;
    tiles[2] = Bh + (size_t)n0 * 1024;
    tiles[3] = (NTILE == 4) ? Bl + (size_t)n0 * 1024 : Bh;

    float acc[2][8][4];
#pragma unroll
    for (int a = 0; a < 2; a++)
#pragma unroll
        for (int b = 0; b < 8; b++)
#pragma unroll
            for (int c = 0; c < 4; c++) acc[a][b][c] = 0.f;

    auto load_stage = [&](int kc, int bufi) {
        const u32 sb = sbase + bufi * STAGE;
#pragma unroll
        for (int p = 0; p < NPASS; p++) {
            const int L = p * 256 + tid;
            const int row = L >> 2, c = L & 3;
            const __half* g = tiles[row >> 7] + (size_t)(row & 127) * 1024 +
                              kc * 32 + c * 8;
            cpa16(sb + row * 64 + ((c ^ ((row >> 1) & 3)) << 4), g);
        }
    };

    load_stage(0, 0);
    asm volatile("cp.async.commit_group;");
    int buf = 0;
    const int wm = wid >> 1, wn = wid & 1;
    for (int kc = 0; kc < 32; kc++) {
        if (kc + 1 < 32) load_stage(kc + 1, buf ^ 1);
        asm volatile("cp.async.commit_group;");
        asm volatile("cp.async.wait_group 1;");
        __syncthreads();
        const u32 sb = sbase + buf * STAGE;
        const int i8 = lane & 7, seg = lane >> 3;
#pragma unroll
        for (int kstep = 0; kstep < 2; kstep++) {
            // A fragments: Ah rows [0,128), Al rows [128,256)
            u32 ra0[2][4], ra1[2][4];
#pragma unroll
            for (int mt = 0; mt < 2; mt++) {
                int row = wm * 32 + mt * 16 + (lane & 15);
                int c = kstep * 2 + (lane >> 4);
                u32 sw = (u32)((c ^ ((row >> 1) & 3)) << 4);
                ldm4(ra0[mt], sb + row * 64 + sw);
                ldm4(ra1[mt], sb + (row + 128) * 64 + sw);
            }
            // B fragments from Bh (rows 256+)
            u32 rb[8][2];
#pragma unroll
            for (int np = 0; np < 4; np++) {
                int row = 256 + wn * 64 + np * 16 + (seg >> 1) * 8 + i8;
                int c = kstep * 2 + (seg & 1);
                u32 r4[4];
                ldm4(r4, sb + row * 64 + ((c ^ ((row >> 1) & 3)) << 4));
                rb[np * 2][0] = r4[0]; rb[np * 2][1] = r4[1];
                rb[np * 2 + 1][0] = r4[2]; rb[np * 2 + 1][1] = r4[3];
            }
#pragma unroll
            for (int mt = 0; mt < 2; mt++)
#pragma unroll
                for (int nt = 0; nt < 8; nt++)
                    mma16816(acc[mt][nt], ra0[mt], rb[nt]);
#pragma unroll
            for (int mt = 0; mt < 2; mt++)
#pragma unroll
                for (int nt = 0; nt < 8; nt++)
                    mma16816(acc[mt][nt], ra1[mt], rb[nt]);
            if constexpr (NTILE == 4) {
                // B fragments from Bl (rows 384+), reuse rb registers
#pragma unroll
                for (int np = 0; np < 4; np++) {
                    int row = 384 + wn * 64 + np * 16 + (seg >> 1) * 8 + i8;
                    int c = kstep * 2 + (seg & 1);
                    u32 r4[4];
                    ldm4(r4, sb + row * 64 + ((c ^ ((row >> 1) & 3)) << 4));
                    rb[np * 2][0] = r4[0]; rb[np * 2][1] = r4[1];
                    rb[np * 2 + 1][0] = r4[2]; rb[np * 2 + 1][1] = r4[3];
                }
#pragma unroll
                for (int mt = 0; mt < 2; mt++)
#pragma unroll
                    for (int nt = 0; nt < 8; nt++)
                        mma16816(acc[mt][nt], ra0[mt], rb[nt]);
            }
        }
        __syncthreads();
        buf ^= 1;
    }

    const int r0 = m0 + wm * 32 + (lane >> 2);
    const int cb = n0 + wn * 64 + (lane & 3) * 2;
#pragma unroll
    for (int mt = 0; mt < 2; mt++)
#pragma unroll
        for (int nt = 0; nt < 8; nt++) {
            int col = cb + nt * 8;
#pragma unroll
            for (int hh = 0; hh < 2; hh++) {
                int rr = r0 + mt * 16 + hh * 8;
                float f0 = acc[mt][nt][hh * 2], f1 = acc[mt][nt][hh * 2 + 1];
                size_t addr = (size_t)rr * 1024 + col;
                if constexpr (EPI == 0) {
                    *(float2*)(CF + addr) = make_float2(f0, f1);
                } else if constexpr (EPI == 1) {
                    u32 h, l;
                    split2(f0, f1, h, l);
                    *(u32*)(CH + addr) = h;
                    *(u32*)(CL + addr) = l;
                } else {
                    *(u32*)(CH + addr) = pack2(f0, f1);
                }
            }
        }
}

// ---------------- kernel: V transpose (s*8+b,1024) -> (bh*64+d, s) ----------
__global__ __launch_bounds__(256) void transpose_v_k() {
    __shared__ __half th[32][33];
    int z = blockIdx.z, b = z >> 4, h = z & 15;
    int s0 = blockIdx.x * 32, d0 = blockIdx.y * 32;
    int r = threadIdx.x >> 5, c = threadIdx.x & 31;
#pragma unroll
    for (int p = 0; p < 4; p++) {
        int rr = r + p * 8;
        th[rr][c] = g_vh[(size_t)((s0 + rr) * 8 + b) * 1024 + h * 64 + d0 + c];
    }
    __syncthreads();
#pragma unroll
    for (int p = 0; p < 4; p++) {
        int rr = r + p * 8;
        g_vt[(size_t)(z * 64 + d0 + rr) * 1024 + s0 + c] = th[c][rr];
    }
}

// ---------------- fused flash attention ----------------
// grid (T/128, B*H). 256 threads = 8 warps; warp owns 16 q rows.
// s-tiles of 64 keys, double-buffered: kh,kl,vt tiles (64x64 each).
// 3-term split S (qh.kh + ql.kh + qh.kl), online softmax, ctx += P.V.
__global__ __launch_bounds__(256) void attn_fused_k(const unsigned char* __restrict__ mask) {
    extern __shared__ char smem[];
    const u32 sbase = smem_u32(smem);
    const int tid = threadIdx.x, lane = tid & 31, w = tid >> 5;
    const int z = blockIdx.y, b = z >> 4, h = z & 15;
    const int t0 = blockIdx.x * 128;
    const int r = lane >> 2, cp = (lane & 3) * 2;
    constexpr int STAGE = 3 * 8192;

    u32 qa[2][4][4];
    {
        const int mrow = t0 + w * 16 + r;
#pragma unroll
        for (int c = 0; c < 4; c++)
#pragma unroll
            for (int i = 0; i < 4; i++) {
                int mm = mrow + (i & 1) * 8;
                int col = h * 64 + c * 16 + cp + (i >> 1) * 8;
                size_t ad = ((size_t)(mm * 8 + b)) * 1024 + col;
                qa[0][c][i] = *(const u32*)(g_qh + ad);
                qa[1][c][i] = *(const u32*)(g_ql + ad);
            }
    }

    float ctx[8][4];
#pragma unroll
    for (int j = 0; j < 8; j++)
#pragma unroll
        for (int c = 0; c < 4; c++) ctx[j][c] = 0.f;
    float m0 = -1e30f, m1 = -1e30f, l0 = 0.f, l1 = 0.f;

    auto load_stage = [&](int it) {
        const int st = it & 1;
        const int s0 = it * 64;
        const u32 sb = sbase + st * STAGE;
#pragma unroll
        for (int p = 0; p < 6; p++) {
            int L = p * 256 + tid;
            int tile = L >> 9, rr = (L >> 3) & 63, c = L & 7;
            const __half* g;
            if (tile == 0)
                g = g_kh + ((size_t)((s0 + rr) * 8 + b)) * 1024 + h * 64 + c * 8;
            else if (tile == 1)
                g = g_kl + ((size_t)((s0 + rr) * 8 + b)) * 1024 + h * 64 + c * 8;
            else
                g = g_vt + ((size_t)(z * 64 + rr)) * 1024 + s0 + c * 8;
            cpa16(sb + tile * 8192 + rr * 128 + ((c ^ (rr & 7)) << 4), g);
        }
        if (tid < 64)
            ((float*)(smem + 2 * STAGE + st * 256))[tid] =
                mask[b * 1024 + s0 + tid] ? -1e30f : 0.f;
    };

    load_stage(0);
    asm volatile("cp.async.commit_group;");
    int buf = 0;
    for (int it = 0; it < 16; it++) {
        if (it < 15) load_stage(it + 1);
        asm volatile("cp.async.commit_group;");
        asm volatile("cp.async.wait_group 1;");
        __syncthreads();
        const u32 sb = sbase + buf * STAGE;

        float sc[8][4];
#pragma unroll
        for (int j = 0; j < 8; j++)
#pragma unroll
            for (int c = 0; c < 4; c++) sc[j][c] = 0.f;

        const int i8 = lane & 7, seg = lane >> 3;
#pragma unroll
        for (int c = 0; c < 4; c++) {
            u32 bf[8][2];
#pragma unroll
            for (int np = 0; np < 4; np++) {
                int row = np * 16 + (seg >> 1) * 8 + i8;
                int cc = c * 2 + (seg & 1);
                u32 r4[4];
                ldm4(r4, sb + row * 128 + ((cc ^ (row & 7)) << 4));
                bf[np * 2][0] = r4[0]; bf[np * 2][1] = r4[1];
                bf[np * 2 + 1][0] = r4[2]; bf[np * 2 + 1][1] = r4[3];
            }
#pragma unroll
            for (int j = 0; j < 8; j++) mma16816(sc[j], qa[0][c], bf[j]);
#pragma unroll
            for (int j = 0; j < 8; j++) mma16816(sc[j], qa[1][c], bf[j]);
        }
#pragma unroll
        for (int c = 0; c < 4; c++) {
            u32 bf[8][2];
#pragma unroll
            for (int np = 0; np < 4; np++) {
                int row = np * 16 + (seg >> 1) * 8 + i8;
                int cc = c * 2 + (seg & 1);
                u32 r4[4];
                ldm4(r4, sb + 8192 + row * 128 + ((cc ^ (row & 7)) << 4));
                bf[np * 2][0] = r4[0]; bf[np * 2][1] = r4[1];
                bf[np * 2 + 1][0] = r4[2]; bf[np * 2 + 1][1] = r4[3];
            }
#pragma unroll
            for (int j = 0; j < 8; j++) mma16816(sc[j], qa[0][c], bf[j]);
        }

        const float* bias = (const float*)(smem + 2 * STAGE + buf * 256);
        float mx0 = -1e30f, mx1 = -1e30f;
#pragma unroll
        for (int j = 0; j < 8; j++) {
            int col = j * 8 + cp;
            float b0 = bias[col], b1 = bias[col + 1];
            sc[j][0] += b0; sc[j][1] += b1;
            sc[j][2] += b0; sc[j][3] += b1;
            mx0 = fmaxf(mx0, fmaxf(sc[j][0], sc[j][1]));
            mx1 = fmaxf(mx1, fmaxf(sc[j][2], sc[j][3]));
        }
        mx0 = fmaxf(mx0, __shfl_xor_sync(~0u, mx0, 1));
        mx0 = fmaxf(mx0, __shfl_xor_sync(~0u, mx0, 2));
        mx1 = fmaxf(mx1, __shfl_xor_sync(~0u, mx1, 1));
        mx1 = fmaxf(mx1, __shfl_xor_sync(~0u, mx1, 2));
        float nm0 = fmaxf(m0, mx0), nm1 = fmaxf(m1, mx1);
        float cr0 = __expf(m0 - nm0), cr1 = __expf(m1 - nm1);
        m0 = nm0; m1 = nm1;
        float sum0 = 0.f, sum1 = 0.f;
#pragma unroll
        for (int j = 0; j < 8; j++) {
            sc[j][0] = __expf(sc[j][0] - nm0);
            sc[j][1] = __expf(sc[j][1] - nm0);
            sc[j][2] = __expf(sc[j][2] - nm1);
            sc[j][3] = __expf(sc[j][3] - nm1);
            sum0 += sc[j][0] + sc[j][1];
            sum1 += sc[j][2] + sc[j][3];
        }
        sum0 += __shfl_xor_sync(~0u, sum0, 1);
        sum0 += __shfl_xor_sync(~0u, sum0, 2);
        sum1 += __shfl_xor_sync(~0u, sum1, 1);
        sum1 += __shfl_xor_sync(~0u, sum1, 2);
        l0 = l0 * cr0 + sum0;
        l1 = l1 * cr1 + sum1;
#pragma unroll
        for (int j = 0; j < 8; j++) {
            ctx[j][0] *= cr0; ctx[j][1] *= cr0;
            ctx[j][2] *= cr1; ctx[j][3] *= cr1;
        }

        u32 pa[4][4];
#pragma unroll
        for (int c = 0; c < 4; c++) {
            pa[c][0] = pack2(sc[2 * c][0], sc[2 * c][1]);
            pa[c][1] = pack2(sc[2 * c][2], sc[2 * c][3]);
            pa[c][2] = pack2(sc[2 * c + 1][0], sc[2 * c + 1][1]);
            pa[c][3] = pack2(sc[2 * c + 1][2], sc[2 * c + 1][3]);
        }

#pragma unroll
        for (int c = 0; c < 4; c++) {
            u32 bv[8][2];
#pragma unroll
            for (int np = 0; np < 4; np++) {
                int row = np * 16 + (seg >> 1) * 8 + i8;
                int cc = c * 2 + (seg & 1);
                u32 r4[4];
                ldm4(r4, sb + 16384 + row * 128 + ((cc ^ (row & 7)) << 4));
                bv[np * 2][0] = r4[0]; bv[np * 2][1] = r4[1];
                bv[np * 2 + 1][0] = r4[2]; bv[np * 2 + 1][1] = r4[3];
            }
#pragma unroll
            for (int j = 0; j < 8; j++) mma16816(ctx[j], pa[c], bv[j]);
        }
        __syncthreads();
        buf ^= 1;
    }

    const float inv0 = 1.f / l0, inv1 = 1.f / l1;
    const int mrow = t0 + w * 16 + r;
#pragma unroll
    for (int j = 0; j < 8; j++) {
        int col = h * 64 + j * 8 + cp;
        u32 hh, ll;
        split2(ctx[j][0] * inv0, ctx[j][1] * inv0, hh, ll);
        size_t a0 = ((size_t)(mrow * 8 + b)) * 1024 + col;
        *(u32*)(g_ch + a0) = hh;
        *(u32*)(g_cl + a0) = ll;
        split2(ctx[j][2] * inv1, ctx[j][3] * inv1, hh, ll);
        size_t a1 = ((size_t)((mrow + 8) * 8 + b)) * 1024 + col;
        *(u32*)(g_ch + a1) = hh;
        *(u32*)(g_cl + a1) = ll;
    }
}

// ---------------- launch ----------------
extern "C" void kernel_launch(void* const* d_in, const int* in_sizes, int n_in,
                              void* d_out, int out_size) {
    const float* query = (const float*)d_in[0];
    const float* key = (const float*)d_in[1];
    const float* tgt = (const float*)d_in[2];
    const float* src = (const float*)d_in[3];
    const float* wq_f = (const float*)d_in[4];
    const float* wkv_f = (const float*)d_in[5];
    const float* wo_f = (const float*)d_in[6];
    const unsigned char* mask = (const unsigned char*)d_in[7];
    float* out = (float*)d_out;

#define SYM(v, s) cudaGetSymbolAddress((void**)&v, s)
    __half *xqh, *xql, *xkh, *xkl, *wqh, *wql, *wkh, *wkl, *wvh, *woh;
    __half *qh, *ql, *kh, *kl, *vh, *ch, *cl;
    SYM(xqh, g_xqh); SYM(xql, g_xql); SYM(xkh, g_xkh); SYM(xkl, g_xkl);
    SYM(wqh, g_wqh); SYM(wql, g_wql); SYM(wkh, g_wkh); SYM(wkl, g_wkl);
    SYM(wvh, g_wvh); SYM(woh, g_woh);
    SYM(qh, g_qh); SYM(ql, g_ql); SYM(kh, g_kh); SYM(kl, g_kl);
    SYM(vh, g_vh); SYM(ch, g_ch); SYM(cl, g_cl);

    const int SM4 = 2 * 4 * 128 * 64;      // 64 KB (4-tile stages)
    const int SM3 = 2 * 3 * 128 * 64;      // 48 KB (3-tile stages)
    const int SMATT = 2 * 3 * 8192 + 512;  // 49.5 KB
    cudaFuncSetAttribute(attn_fused_k,
                         cudaFuncAttributeMaxDynamicSharedMemorySize, SMATT);
    cudaFuncSetAttribute(gemmf<4, 1>,
                         cudaFuncAttributeMaxDynamicSharedMemorySize, SM4);
    cudaFuncSetAttribute(gemmf<3, 2>,
                         cudaFuncAttributeMaxDynamicSharedMemorySize, SM3);
    cudaFuncSetAttribute(gemmf<3, 0>,
                         cudaFuncAttributeMaxDynamicSharedMemorySize, SM3);

    split_inputs_k<<<8192, 256>>>(query, key);
    build_weights_k<<<16384, 256>>>(wq_f, wkv_f, wo_f, tgt, src);

    // q/k projections: 3 fused terms (xh.wh + xl.wh + xh.wl), split fp16 out
    gemmf<4, 1><<<dim3(8, 64), 256, SM4>>>(xqh, xql, wqh, wql, nullptr, qh, ql);
    gemmf<4, 1><<<dim3(8, 64), 256, SM4>>>(xkh, xkl, wkh, wkl, nullptr, kh, kl);
    // v projection: 2 fused terms (xh.wv + xl.wv), plain fp16 out
    gemmf<3, 2><<<dim3(8, 64), 256, SM3>>>(xkh, xkl, wvh, nullptr, nullptr, vh, nullptr);

    transpose_v_k<<<dim3(32, 2, 128), 256>>>();

    // fused attention: scores(3-term) + mask + softmax + P@V
    attn_fused_k<<<dim3(8, 128), 256, SMATT>>>(mask);

    // out = ch@wo^T + cl@wo^T, fp32 out
    gemmf<3, 0><<<dim3(8, 64), 256, SM3>>>(ch, cl, woh, nullptr, out, nullptr, nullptr);
}

// round 8
// speedup vs baseline: 1.5204x; 1.0108x over previous
#include <cuda_runtime.h>
#include <cuda_fp16.h>
#include <cstdint>
#include <cstddef>

using u32 = uint32_t;
using u64 = uint64_t;
#define MTOT 8192

// ---------------- static scratch (no allocation) ----------------
__device__ __half g_xqh[MTOT * 1024], g_xql[MTOT * 1024];
__device__ __half g_xkh[MTOT * 1024], g_xkl[MTOT * 1024];
__device__ __half g_wqh[1024 * 1024], g_wql[1024 * 1024];
__device__ __half g_wkh[1024 * 1024], g_wkl[1024 * 1024];
__device__ __half g_wvh[1024 * 1024];
__device__ __half g_woh[1024 * 1024];
__device__ __half g_qh[MTOT * 1024], g_ql[MTOT * 1024];
__device__ __half g_kh[MTOT * 1024], g_kl[MTOT * 1024];
__device__ __half g_vh[MTOT * 1024];
__device__ __half g_vt[MTOT * 1024];
__device__ __half g_ch[MTOT * 1024], g_cl[MTOT * 1024];

// ---------------- helpers ----------------
__device__ __forceinline__ u32 smem_u32(const void* p) {
    u32 a;
    asm("{ .reg .u64 t; cvta.to.shared.u64 t, %1; cvt.u32.u64 %0, t; }"
        : "=r"(a) : "l"(p));
    return a;
}
__device__ __forceinline__ void split2(float f0, float f1, u32& h, u32& l) {
    __half a = __float2half_rn(f0), b = __float2half_rn(f1);
    h = (u32)__half_as_ushort(a) | ((u32)__half_as_ushort(b) << 16);
    __half c = __float2half_rn(f0 - __half2float(a));
    __half d = __float2half_rn(f1 - __half2float(b));
    l = (u32)__half_as_ushort(c) | ((u32)__half_as_ushort(d) << 16);
}
__device__ __forceinline__ u32 pack2(float f0, float f1) {
    __half2 hh = __floats2half2_rn(f0, f1);
    return *reinterpret_cast<u32*>(&hh);
}
__device__ __forceinline__ void cpa16(u32 s, const void* g) {
    asm volatile("cp.async.cg.shared.global [%0], [%1], 16;"
                 :: "r"(s), "l"((u64)__cvta_generic_to_global(g)));
}
__device__ __forceinline__ void ldm4(u32* r, u32 addr) {
    asm volatile("ldmatrix.sync.aligned.m8n8.x4.shared.b16 {%0,%1,%2,%3}, [%4];"
                 : "=r"(r[0]), "=r"(r[1]), "=r"(r[2]), "=r"(r[3]) : "r"(addr));
}
__device__ __forceinline__ void mma16816(float* d, const u32* a, const u32* b) {
    asm volatile(
        "mma.sync.aligned.m16n8k16.row.col.f32.f16.f16.f32 "
        "{%0,%1,%2,%3},{%4,%5,%6,%7},{%8,%9},{%0,%1,%2,%3};"
        : "+f"(d[0]), "+f"(d[1]), "+f"(d[2]), "+f"(d[3])
        : "r"(a[0]), "r"(a[1]), "r"(a[2]), "r"(a[3]), "r"(b[0]), "r"(b[1]));
}

// ---------------- kernel: split fp32 inputs to hi/lo fp16 ----------------
__global__ __launch_bounds__(256) void split_inputs_k(
    const float* __restrict__ q, const float* __restrict__ kk) {
    size_t idx = (size_t)blockIdx.x * 256 + threadIdx.x;  // 0..2M-1
    size_t i = idx & ((1u << 20) - 1);
    const float* src = (idx < (1u << 20)) ? q : kk;
    __half* dh = (idx < (1u << 20)) ? g_xqh : g_xkh;
    __half* dl = (idx < (1u << 20)) ? g_xql : g_xkl;
    size_t e = i * 8;
    float4 a = ((const float4*)(src + e))[0];
    float4 b = ((const float4*)(src + e))[1];
    float f[8] = {a.x, a.y, a.z, a.w, b.x, b.y, b.z, b.w};
    u32 ph[4], pl[4];
#pragma unroll
    for (int j = 0; j < 4; j++) split2(f[2 * j], f[2 * j + 1], ph[j], pl[j]);
    *(uint4*)(dh + e) = make_uint4(ph[0], ph[1], ph[2], ph[3]);
    *(uint4*)(dl + e) = make_uint4(pl[0], pl[1], pl[2], pl[3]);
}

// ---------------- kernel: factorized weights -> fp16 (split where needed) ---
__global__ __launch_bounds__(256) void build_weights_k(
    const float* __restrict__ wq_f, const float* __restrict__ wkv_f,
    const float* __restrict__ wo_f, const float* __restrict__ tgt,
    const float* __restrict__ src) {
    u32 n = blockIdx.x * 256 + threadIdx.x;  // 0..4M-1
    u32 seg = n >> 20, m = n & 1048575;
    const float* w;
    const float* f;
    __half *dh, *dl = nullptr;
    float scale = 1.f;
    if (seg == 0) { w = wq_f + (size_t)m * 8; f = tgt; dh = g_wqh; dl = g_wql; scale = 0.125f; }
    else if (seg == 1) { w = wkv_f + (size_t)m * 8; f = src; dh = g_wkh; dl = g_wkl; }
    else if (seg == 2) { w = wkv_f + ((size_t)1048576 + m) * 8; f = src; dh = g_wvh; }
    else { w = wo_f + (size_t)m * 8; f = tgt; dh = g_woh; }
    float acc = 0.f;
#pragma unroll
    for (int r = 0; r < 8; r++) acc += w[r] * f[r];
    acc *= scale;
    __half h = __float2half_rn(acc);
    dh[m] = h;
    if (dl) dl[m] = __float2half_rn(acc - __half2float(h));
}

// ---------------- fused-term mma.sync GEMM --------------------------------
// C = Ah@Bh^T + Al@Bh^T (+ Ah@Bl^T if NTILE==4). M=8192, N=1024, K=1024.
// BM=128, BN=128, BK=32. Stage holds {Ah, Al, Bh[, Bl]} tiles. Ring of 3
// stages, prefetch depth 2, ONE barrier per k-chunk.
// EPI 0: fp32 -> CF. EPI 1: split fp16 -> CH/CL. EPI 2: plain fp16 -> CH.
template <int NTILE, int EPI>
__global__ __launch_bounds__(256, 2) void gemmf(
    const __half* __restrict__ Ah, const __half* __restrict__ Al,
    const __half* __restrict__ Bh, const __half* __restrict__ Bl,
    float* CF, __half* CH, __half* CL) {
    constexpr int STAGE = NTILE * 128 * 64;
    constexpr int NPASS = NTILE * 2;
    extern __shared__ char smem[];
    const u32 sbase = smem_u32(smem);

    const int tid = threadIdx.x, lane = tid & 31, wid = tid >> 5;
    const int m0 = blockIdx.y * 128, n0 = blockIdx.x * 128;
    const __half* tiles[4];
    tiles[0] = Ah + (size_t)m0 * 1024;
    tiles[1] = Al + (size_t)m0 * 1024;
    tiles[2] = Bh + (size_t)n0 * 1024;
    tiles[3] = (NTILE == 4) ? Bl + (size_t)n0 * 1024 : Bh;

    float acc[2][8][4];
#pragma unroll
    for (int a = 0; a < 2; a++)
#pragma unroll
        for (int b = 0; b < 8; b++)
#pragma unroll
            for (int c = 0; c < 4; c++) acc[a][b][c] = 0.f;

    auto load_stage = [&](int kc, int bufi) {
        const u32 sb = sbase + bufi * STAGE;
#pragma unroll
        for (int p = 0; p < NPASS; p++) {
            const int L = p * 256 + tid;
            const int row = L >> 2, c = L & 3;
            const __half* g = tiles[row >> 7] + (size_t)(row & 127) * 1024 +
                              kc * 32 + c * 8;
            cpa16(sb + row * 64 + ((c ^ ((row >> 1) & 3)) << 4), g);
        }
    };

    load_stage(0, 0);
    asm volatile("cp.async.commit_group;");
    load_stage(1, 1);
    asm volatile("cp.async.commit_group;");
    int s_cur = 0, s_pre = 2;
    const int wm = wid >> 1, wn = wid & 1;
    for (int kc = 0; kc < 32; kc++) {
        asm volatile("cp.async.wait_group 1;");
        __syncthreads();
        if (kc + 2 < 32) load_stage(kc + 2, s_pre);
        asm volatile("cp.async.commit_group;");
        const u32 sb = sbase + s_cur * STAGE;
        const int i8 = lane & 7, seg = lane >> 3;
#pragma unroll
        for (int kstep = 0; kstep < 2; kstep++) {
            // A fragments: Ah rows [0,128), Al rows [128,256)
            u32 ra0[2][4], ra1[2][4];
#pragma unroll
            for (int mt = 0; mt < 2; mt++) {
                int row = wm * 32 + mt * 16 + (lane & 15);
                int c = kstep * 2 + (lane >> 4);
                u32 sw = (u32)((c ^ ((row >> 1) & 3)) << 4);
                ldm4(ra0[mt], sb + row * 64 + sw);
                ldm4(ra1[mt], sb + (row + 128) * 64 + sw);
            }
            // B fragments from Bh (rows 256+)
            u32 rb[8][2];
#pragma unroll
            for (int np = 0; np < 4; np++) {
                int row = 256 + wn * 64 + np * 16 + (seg >> 1) * 8 + i8;
                int c = kstep * 2 + (seg & 1);
                u32 r4[4];
                ldm4(r4, sb + row * 64 + ((c ^ ((row >> 1) & 3)) << 4));
                rb[np * 2][0] = r4[0]; rb[np * 2][1] = r4[1];
                rb[np * 2 + 1][0] = r4[2]; rb[np * 2 + 1][1] = r4[3];
            }
#pragma unroll
            for (int mt = 0; mt < 2; mt++)
#pragma unroll
                for (int nt = 0; nt < 8; nt++)
                    mma16816(acc[mt][nt], ra0[mt], rb[nt]);
#pragma unroll
            for (int mt = 0; mt < 2; mt++)
#pragma unroll
                for (int nt = 0; nt < 8; nt++)
                    mma16816(acc[mt][nt], ra1[mt], rb[nt]);
            if constexpr (NTILE == 4) {
                // B fragments from Bl (rows 384+), reuse rb registers
#pragma unroll
                for (int np = 0; np < 4; np++) {
                    int row = 384 + wn * 64 + np * 16 + (seg >> 1) * 8 + i8;
                    int c = kstep * 2 + (seg & 1);
                    u32 r4[4];
                    ldm4(r4, sb + row * 64 + ((c ^ ((row >> 1) & 3)) << 4));
                    rb[np * 2][0] = r4[0]; rb[np * 2][1] = r4[1];
                    rb[np * 2 + 1][0] = r4[2]; rb[np * 2 + 1][1] = r4[3];
                }
#pragma unroll
                for (int mt = 0; mt < 2; mt++)
#pragma unroll
                    for (int nt = 0; nt < 8; nt++)
                        mma16816(acc[mt][nt], ra0[mt], rb[nt]);
            }
        }
        s_cur = (s_cur == 2) ? 0 : s_cur + 1;
        s_pre = (s_pre == 2) ? 0 : s_pre + 1;
    }

    const int r0 = m0 + wm * 32 + (lane >> 2);
    const int cb = n0 + wn * 64 + (lane & 3) * 2;
#pragma unroll
    for (int mt = 0; mt < 2; mt++)
#pragma unroll
        for (int nt = 0; nt < 8; nt++) {
            int col = cb + nt * 8;
#pragma unroll
            for (int hh = 0; hh < 2; hh++) {
                int rr = r0 + mt * 16 + hh * 8;
                float f0 = acc[mt][nt][hh * 2], f1 = acc[mt][nt][hh * 2 + 1];
                size_t addr = (size_t)rr * 1024 + col;
                if constexpr (EPI == 0) {
                    *(float2*)(CF + addr) = make_float2(f0, f1);
                } else if constexpr (EPI == 1) {
                    u32 h, l;
                    split2(f0, f1, h, l);
                    *(u32*)(CH + addr) = h;
                    *(u32*)(CL + addr) = l;
                } else {
                    *(u32*)(CH + addr) = pack2(f0, f1);
                }
            }
        }
}

// ---------------- kernel: V transpose (s*8+b,1024) -> (bh*64+d, s) ----------
__global__ __launch_bounds__(256) void transpose_v_k() {
    __shared__ __half th[32][33];
    int z = blockIdx.z, b = z >> 4, h = z & 15;
    int s0 = blockIdx.x * 32, d0 = blockIdx.y * 32;
    int r = threadIdx.x >> 5, c = threadIdx.x & 31;
#pragma unroll
    for (int p = 0; p < 4; p++) {
        int rr = r + p * 8;
        th[rr][c] = g_vh[(size_t)((s0 + rr) * 8 + b) * 1024 + h * 64 + d0 + c];
    }
    __syncthreads();
#pragma unroll
    for (int p = 0; p < 4; p++) {
        int rr = r + p * 8;
        g_vt[(size_t)(z * 64 + d0 + rr) * 1024 + s0 + c] = th[c][rr];
    }
}

// ---------------- fused flash attention ----------------
// grid (T/128, B*H). 256 threads = 8 warps; warp owns 16 q rows.
// s-tiles of 64 keys: kh,kl,vt (64x64 each, 24KB/stage), ring of 3 stages,
// prefetch depth 2, one barrier per iteration.
// 3-term split S (qh.kh + ql.kh + qh.kl), online softmax, ctx += P.V.
__global__ __launch_bounds__(256) void attn_fused_k(const unsigned char* __restrict__ mask) {
    extern __shared__ char smem[];
    const u32 sbase = smem_u32(smem);
    const int tid = threadIdx.x, lane = tid & 31, w = tid >> 5;
    const int z = blockIdx.y, b = z >> 4, h = z & 15;
    const int t0 = blockIdx.x * 128;
    const int r = lane >> 2, cp = (lane & 3) * 2;
    constexpr int STAGE = 3 * 8192;   // kh + kl + vt

    u32 qa[2][4][4];
    {
        const int mrow = t0 + w * 16 + r;
#pragma unroll
        for (int c = 0; c < 4; c++)
#pragma unroll
            for (int i = 0; i < 4; i++) {
                int mm = mrow + (i & 1) * 8;
                int col = h * 64 + c * 16 + cp + (i >> 1) * 8;
                size_t ad = ((size_t)(mm * 8 + b)) * 1024 + col;
                qa[0][c][i] = *(const u32*)(g_qh + ad);
                qa[1][c][i] = *(const u32*)(g_ql + ad);
            }
    }

    float ctx[8][4];
#pragma unroll
    for (int j = 0; j < 8; j++)
#pragma unroll
        for (int c = 0; c < 4; c++) ctx[j][c] = 0.f;
    float m0 = -1e30f, m1 = -1e30f, l0 = 0.f, l1 = 0.f;

    auto load_stage = [&](int it, int st) {
        const int s0 = it * 64;
        const u32 sb = sbase + st * STAGE;
#pragma unroll
        for (int p = 0; p < 6; p++) {
            int L = p * 256 + tid;
            int tile = L >> 9, rr = (L >> 3) & 63, c = L & 7;
            const __half* g;
            if (tile == 0)
                g = g_kh + ((size_t)((s0 + rr) * 8 + b)) * 1024 + h * 64 + c * 8;
            else if (tile == 1)
                g = g_kl + ((size_t)((s0 + rr) * 8 + b)) * 1024 + h * 64 + c * 8;
            else
                g = g_vt + ((size_t)(z * 64 + rr)) * 1024 + s0 + c * 8;
            cpa16(sb + tile * 8192 + rr * 128 + ((c ^ (rr & 7)) << 4), g);
        }
        if (tid < 64)
            ((float*)(smem + 3 * STAGE + st * 256))[tid] =
                mask[b * 1024 + s0 + tid] ? -1e30f : 0.f;
    };

    load_stage(0, 0);
    asm volatile("cp.async.commit_group;");
    load_stage(1, 1);
    asm volatile("cp.async.commit_group;");
    int s_cur = 0, s_pre = 2;
    for (int it = 0; it < 16; it++) {
        asm volatile("cp.async.wait_group 1;");
        __syncthreads();
        if (it + 2 < 16) load_stage(it + 2, s_pre);
        asm volatile("cp.async.commit_group;");
        const u32 sb = sbase + s_cur * STAGE;

        float sc[8][4];
#pragma unroll
        for (int j = 0; j < 8; j++)
#pragma unroll
            for (int c = 0; c < 4; c++) sc[j][c] = 0.f;

        const int i8 = lane & 7, seg = lane >> 3;
#pragma unroll
        for (int c = 0; c < 4; c++) {
            u32 bf[8][2];
#pragma unroll
            for (int np = 0; np < 4; np++) {
                int row = np * 16 + (seg >> 1) * 8 + i8;
                int cc = c * 2 + (seg & 1);
                u32 r4[4];
                ldm4(r4, sb + row * 128 + ((cc ^ (row & 7)) << 4));
                bf[np * 2][0] = r4[0]; bf[np * 2][1] = r4[1];
                bf[np * 2 + 1][0] = r4[2]; bf[np * 2 + 1][1] = r4[3];
            }
#pragma unroll
            for (int j = 0; j < 8; j++) mma16816(sc[j], qa[0][c], bf[j]);
#pragma unroll
            for (int j = 0; j < 8; j++) mma16816(sc[j], qa[1][c], bf[j]);
        }
#pragma unroll
        for (int c = 0; c < 4; c++) {
            u32 bf[8][2];
#pragma unroll
            for (int np = 0; np < 4; np++) {
                int row = np * 16 + (seg >> 1) * 8 + i8;
                int cc = c * 2 + (seg & 1);
                u32 r4[4];
                ldm4(r4, sb + 8192 + row * 128 + ((cc ^ (row & 7)) << 4));
                bf[np * 2][0] = r4[0]; bf[np * 2][1] = r4[1];
                bf[np * 2 + 1][0] = r4[2]; bf[np * 2 + 1][1] = r4[3];
            }
#pragma unroll
            for (int j = 0; j < 8; j++) mma16816(sc[j], qa[0][c], bf[j]);
        }

        const float* bias = (const float*)(smem + 3 * STAGE + s_cur * 256);
        float mx0 = -1e30f, mx1 = -1e30f;
#pragma unroll
        for (int j = 0; j < 8; j++) {
            int col = j * 8 + cp;
            float b0 = bias[col], b1 = bias[col + 1];
            sc[j][0] += b0; sc[j][1] += b1;
            sc[j][2] += b0; sc[j][3] += b1;
            mx0 = fmaxf(mx0, fmaxf(sc[j][0], sc[j][1]));
            mx1 = fmaxf(mx1, fmaxf(sc[j][2], sc[j][3]));
        }
        mx0 = fmaxf(mx0, __shfl_xor_sync(~0u, mx0, 1));
        mx0 = fmaxf(mx0, __shfl_xor_sync(~0u, mx0, 2));
        mx1 = fmaxf(mx1, __shfl_xor_sync(~0u, mx1, 1));
        mx1 = fmaxf(mx1, __shfl_xor_sync(~0u, mx1, 2));
        float nm0 = fmaxf(m0, mx0), nm1 = fmaxf(m1, mx1);
        float cr0 = __expf(m0 - nm0), cr1 = __expf(m1 - nm1);
        m0 = nm0; m1 = nm1;
        float sum0 = 0.f, sum1 = 0.f;
#pragma unroll
        for (int j = 0; j < 8; j++) {
            sc[j][0] = __expf(sc[j][0] - nm0);
            sc[j][1] = __expf(sc[j][1] - nm0);
            sc[j][2] = __expf(sc[j][2] - nm1);
            sc[j][3] = __expf(sc[j][3] - nm1);
            sum0 += sc[j][0] + sc[j][1];
            sum1 += sc[j][2] + sc[j][3];
        }
        sum0 += __shfl_xor_sync(~0u, sum0, 1);
        sum0 += __shfl_xor_sync(~0u, sum0, 2);
        sum1 += __shfl_xor_sync(~0u, sum1, 1);
        sum1 += __shfl_xor_sync(~0u, sum1, 2);
        l0 = l0 * cr0 + sum0;
        l1 = l1 * cr1 + sum1;
#pragma unroll
        for (int j = 0; j < 8; j++) {
            ctx[j][0] *= cr0; ctx[j][1] *= cr0;
            ctx[j][2] *= cr1; ctx[j][3] *= cr1;
        }

        u32 pa[4][4];
#pragma unroll
        for (int c = 0; c < 4; c++) {
            pa[c][0] = pack2(sc[2 * c][0], sc[2 * c][1]);
            pa[c][1] = pack2(sc[2 * c][2], sc[2 * c][3]);
            pa[c][2] = pack2(sc[2 * c + 1][0], sc[2 * c + 1][1]);
            pa[c][3] = pack2(sc[2 * c + 1][2], sc[2 * c + 1][3]);
        }

#pragma unroll
        for (int c = 0; c < 4; c++) {
            u32 bv[8][2];
#pragma unroll
            for (int np = 0; np < 4; np++) {
                int row = np * 16 + (seg >> 1) * 8 + i8;
                int cc = c * 2 + (seg & 1);
                u32 r4[4];
                ldm4(r4, sb + 16384 + row * 128 + ((cc ^ (row & 7)) << 4));
                bv[np * 2][0] = r4[0]; bv[np * 2][1] = r4[1];
                bv[np * 2 + 1][0] = r4[2]; bv[np * 2 + 1][1] = r4[3];
            }
#pragma unroll
            for (int j = 0; j < 8; j++) mma16816(ctx[j], pa[c], bv[j]);
        }
        s_cur = (s_cur == 2) ? 0 : s_cur + 1;
        s_pre = (s_pre == 2) ? 0 : s_pre + 1;
    }

    const float inv0 = 1.f / l0, inv1 = 1.f / l1;
    const int mrow = t0 + w * 16 + r;
#pragma unroll
    for (int j = 0; j < 8; j++) {
        int col = h * 64 + j * 8 + cp;
        u32 hh, ll;
        split2(ctx[j][0] * inv0, ctx[j][1] * inv0, hh, ll);
        size_t a0 = ((size_t)(mrow * 8 + b)) * 1024 + col;
        *(u32*)(g_ch + a0) = hh;
        *(u32*)(g_cl + a0) = ll;
        split2(ctx[j][2] * inv1, ctx[j][3] * inv1, hh, ll);
        size_t a1 = ((size_t)((mrow + 8) * 8 + b)) * 1024 + col;
        *(u32*)(g_ch + a1) = hh;
        *(u32*)(g_cl + a1) = ll;
    }
}

// ---------------- launch ----------------
extern "C" void kernel_launch(void* const* d_in, const int* in_sizes, int n_in,
                              void* d_out, int out_size) {
    const float* query = (const float*)d_in[0];
    const float* key = (const float*)d_in[1];
    const float* tgt = (const float*)d_in[2];
    const float* src = (const float*)d_in[3];
    const float* wq_f = (const float*)d_in[4];
    const float* wkv_f = (const float*)d_in[5];
    const float* wo_f = (const float*)d_in[6];
    const unsigned char* mask = (const unsigned char*)d_in[7];
    float* out = (float*)d_out;

#define SYM(v, s) cudaGetSymbolAddress((void**)&v, s)
    __half *xqh, *xql, *xkh, *xkl, *wqh, *wql, *wkh, *wkl, *wvh, *woh;
    __half *qh, *ql, *kh, *kl, *vh, *ch, *cl;
    SYM(xqh, g_xqh); SYM(xql, g_xql); SYM(xkh, g_xkh); SYM(xkl, g_xkl);
    SYM(wqh, g_wqh); SYM(wql, g_wql); SYM(wkh, g_wkh); SYM(wkl, g_wkl);
    SYM(wvh, g_wvh); SYM(woh, g_woh);
    SYM(qh, g_qh); SYM(ql, g_ql); SYM(kh, g_kh); SYM(kl, g_kl);
    SYM(vh, g_vh); SYM(ch, g_ch); SYM(cl, g_cl);

    const int SM4 = 3 * 4 * 128 * 64;          // 96 KB (4-tile, ring-3)
    const int SM3 = 3 * 3 * 128 * 64;          // 72 KB (3-tile, ring-3)
    const int SMATT = 3 * 3 * 8192 + 768;      // 74.25 KB (ring-3 + bias)
    cudaFuncSetAttribute(attn_fused_k,
                         cudaFuncAttributeMaxDynamicSharedMemorySize, SMATT);
    cudaFuncSetAttribute(gemmf<4, 1>,
                         cudaFuncAttributeMaxDynamicSharedMemorySize, SM4);
    cudaFuncSetAttribute(gemmf<3, 2>,
                         cudaFuncAttributeMaxDynamicSharedMemorySize, SM3);
    cudaFuncSetAttribute(gemmf<3, 0>,
                         cudaFuncAttributeMaxDynamicSharedMemorySize, SM3);

    split_inputs_k<<<8192, 256>>>(query, key);
    build_weights_k<<<16384, 256>>>(wq_f, wkv_f, wo_f, tgt, src);

    // q/k projections: 3 fused terms (xh.wh + xl.wh + xh.wl), split fp16 out
    gemmf<4, 1><<<dim3(8, 64), 256, SM4>>>(xqh, xql, wqh, wql, nullptr, qh, ql);
    gemmf<4, 1><<<dim3(8, 64), 256, SM4>>>(xkh, xkl, wkh, wkl, nullptr, kh, kl);
    // v projection: 2 fused terms (xh.wv + xl.wv), plain fp16 out
    gemmf<3, 2><<<dim3(8, 64), 256, SM3>>>(xkh, xkl, wvh, nullptr, nullptr, vh, nullptr);

    transpose_v_k<<<dim3(32, 2, 128), 256>>>();

    // fused attention: scores(3-term) + mask + softmax + P@V
    attn_fused_k<<<dim3(8, 128), 256, SMATT>>>(mask);

    // out = ch@wo^T + cl@wo^T, fp32 out
    gemmf<3, 0><<<dim3(8, 64), 256, SM3>>>(ch, cl, woh, nullptr, out, nullptr, nullptr);
}

// round 9
// speedup vs baseline: 1.6387x; 1.0778x over previous
#include <cuda_runtime.h>
#include <cuda_fp16.h>
#include <cstdint>
#include <cstddef>

using u32 = uint32_t;
using u64 = uint64_t;
#define MTOT 8192

// ---------------- static scratch (no allocation) ----------------
__device__ __half g_xqh[MTOT * 1024], g_xql[MTOT * 1024];
__device__ __half g_xkh[MTOT * 1024], g_xkl[MTOT * 1024];
__device__ __half g_wqh[1024 * 1024], g_wql[1024 * 1024];
__device__ __half g_wkh[1024 * 1024], g_wkl[1024 * 1024];
__device__ __half g_wvh[1024 * 1024];
__device__ __half g_woh[1024 * 1024];
__device__ __half g_qh[MTOT * 1024], g_ql[MTOT * 1024];
__device__ __half g_kh[MTOT * 1024], g_kl[MTOT * 1024];
__device__ __half g_vh[MTOT * 1024];
__device__ __half g_ch[MTOT * 1024], g_cl[MTOT * 1024];

// ---------------- helpers ----------------
__device__ __forceinline__ u32 smem_u32(const void* p) {
    u32 a;
    asm("{ .reg .u64 t; cvta.to.shared.u64 t, %1; cvt.u32.u64 %0, t; }"
        : "=r"(a) : "l"(p));
    return a;
}
__device__ __forceinline__ void split2(float f0, float f1, u32& h, u32& l) {
    __half a = __float2half_rn(f0), b = __float2half_rn(f1);
    h = (u32)__half_as_ushort(a) | ((u32)__half_as_ushort(b) << 16);
    __half c = __float2half_rn(f0 - __half2float(a));
    __half d = __float2half_rn(f1 - __half2float(b));
    l = (u32)__half_as_ushort(c) | ((u32)__half_as_ushort(d) << 16);
}
__device__ __forceinline__ u32 pack2(float f0, float f1) {
    __half2 hh = __floats2half2_rn(f0, f1);
    return *reinterpret_cast<u32*>(&hh);
}
__device__ __forceinline__ void cpa16(u32 s, const void* g) {
    asm volatile("cp.async.cg.shared.global [%0], [%1], 16;"
                 :: "r"(s), "l"((u64)__cvta_generic_to_global(g)));
}
__device__ __forceinline__ void ldm4(u32* r, u32 addr) {
    asm volatile("ldmatrix.sync.aligned.m8n8.x4.shared.b16 {%0,%1,%2,%3}, [%4];"
                 : "=r"(r[0]), "=r"(r[1]), "=r"(r[2]), "=r"(r[3]) : "r"(addr));
}
__device__ __forceinline__ void ldm4t(u32* r, u32 addr) {
    asm volatile("ldmatrix.sync.aligned.m8n8.x4.trans.shared.b16 {%0,%1,%2,%3}, [%4];"
                 : "=r"(r[0]), "=r"(r[1]), "=r"(r[2]), "=r"(r[3]) : "r"(addr));
}
__device__ __forceinline__ void mma16816(float* d, const u32* a, const u32* b) {
    asm volatile(
        "mma.sync.aligned.m16n8k16.row.col.f32.f16.f16.f32 "
        "{%0,%1,%2,%3},{%4,%5,%6,%7},{%8,%9},{%0,%1,%2,%3};"
        : "+f"(d[0]), "+f"(d[1]), "+f"(d[2]), "+f"(d[3])
        : "r"(a[0]), "r"(a[1]), "r"(a[2]), "r"(a[3]), "r"(b[0]), "r"(b[1]));
}

// ---------------- merged prep: input split + weight build -------------------
// blocks [0,8192): split query/key fp32 -> hi/lo fp16 (8 elems/thread)
// blocks [8192,24576): factorized weights -> fp16 (split where needed)
__global__ __launch_bounds__(256) void prep_k(
    const float* __restrict__ q, const float* __restrict__ kk,
    const float* __restrict__ wq_f, const float* __restrict__ wkv_f,
    const float* __restrict__ wo_f, const float* __restrict__ tgt,
    const float* __restrict__ src) {
    const u32 bid = blockIdx.x;
    if (bid < 8192) {
        size_t idx = (size_t)bid * 256 + threadIdx.x;  // 0..2M-1
        size_t i = idx & ((1u << 20) - 1);
        const float* sp = (idx < (1u << 20)) ? q : kk;
        __half* dh = (idx < (1u << 20)) ? g_xqh : g_xkh;
        __half* dl = (idx < (1u << 20)) ? g_xql : g_xkl;
        size_t e = i * 8;
        float4 a = ((const float4*)(sp + e))[0];
        float4 b = ((const float4*)(sp + e))[1];
        float f[8] = {a.x, a.y, a.z, a.w, b.x, b.y, b.z, b.w};
        u32 ph[4], pl[4];
#pragma unroll
        for (int j = 0; j < 4; j++) split2(f[2 * j], f[2 * j + 1], ph[j], pl[j]);
        *(uint4*)(dh + e) = make_uint4(ph[0], ph[1], ph[2], ph[3]);
        *(uint4*)(dl + e) = make_uint4(pl[0], pl[1], pl[2], pl[3]);
    } else {
        u32 n = (bid - 8192) * 256 + threadIdx.x;  // 0..4M-1
        u32 seg = n >> 20, m = n & 1048575;
        const float* w;
        const float* f;
        __half *dh, *dl = nullptr;
        float scale = 1.f;
        if (seg == 0) { w = wq_f + (size_t)m * 8; f = tgt; dh = g_wqh; dl = g_wql; scale = 0.125f; }
        else if (seg == 1) { w = wkv_f + (size_t)m * 8; f = src; dh = g_wkh; dl = g_wkl; }
        else if (seg == 2) { w = wkv_f + ((size_t)1048576 + m) * 8; f = src; dh = g_wvh; }
        else { w = wo_f + (size_t)m * 8; f = tgt; dh = g_woh; }
        float acc = 0.f;
#pragma unroll
        for (int r = 0; r < 8; r++) acc += w[r] * f[r];
        acc *= scale;
        __half h = __float2half_rn(acc);
        dh[m] = h;
        if (dl) dl[m] = __float2half_rn(acc - __half2float(h));
    }
}

// ---------------- fused-term mma.sync GEMM --------------------------------
// C = Ah@Bh^T + Al@Bh^T (+ Ah@Bl^T if NTILE==4). Per z: independent problem
// (pointer set 0 or 1) -> lets two projections share one launch (tail backfill).
// BM=128, BN=128, BK=32. Ring-3 stages, prefetch depth 2, one barrier/chunk.
// EPI 0: fp32 -> CF. EPI 1: split fp16 -> CH/CL. EPI 2: plain fp16 -> CH.
template <int NTILE, int EPI>
__global__ __launch_bounds__(256, 2) void gemmf(
    const __half* __restrict__ Ah0, const __half* __restrict__ Al0,
    const __half* __restrict__ Bh0, const __half* __restrict__ Bl0,
    __half* CH0, __half* CL0,
    const __half* __restrict__ Ah1, const __half* __restrict__ Al1,
    const __half* __restrict__ Bh1, const __half* __restrict__ Bl1,
    __half* CH1, __half* CL1,
    float* CF) {
    constexpr int STAGE = NTILE * 128 * 64;
    constexpr int NPASS = NTILE * 2;
    extern __shared__ char smem[];
    const u32 sbase = smem_u32(smem);

    const int tid = threadIdx.x, lane = tid & 31, wid = tid >> 5;
    const int m0 = blockIdx.y * 128, n0 = blockIdx.x * 128;
    const int z = blockIdx.z;
    const __half* Ah = z ? Ah1 : Ah0;
    const __half* Al = z ? Al1 : Al0;
    const __half* Bh = z ? Bh1 : Bh0;
    const __half* Bl = z ? Bl1 : Bl0;
    __half* CH = z ? CH1 : CH0;
    __half* CL = z ? CL1 : CL0;
    const __half* tiles[4];
    tiles[0] = Ah + (size_t)m0 * 1024;
    tiles[1] = Al + (size_t)m0 * 1024;
    tiles[2] = Bh + (size_t)n0 * 1024;
    tiles[3] = (NTILE == 4) ? Bl + (size_t)n0 * 1024 : Bh;

    float acc[2][8][4];
#pragma unroll
    for (int a = 0; a < 2; a++)
#pragma unroll
        for (int b = 0; b < 8; b++)
#pragma unroll
            for (int c = 0; c < 4; c++) acc[a][b][c] = 0.f;

    auto load_stage = [&](int kc, int bufi) {
        const u32 sb = sbase + bufi * STAGE;
#pragma unroll
        for (int p = 0; p < NPASS; p++) {
            const int L = p * 256 + tid;
            const int row = L >> 2, c = L & 3;
            const __half* g = tiles[row >> 7] + (size_t)(row & 127) * 1024 +
                              kc * 32 + c * 8;
            cpa16(sb + row * 64 + ((c ^ ((row >> 1) & 3)) << 4), g);
        }
    };

    load_stage(0, 0);
    asm volatile("cp.async.commit_group;");
    load_stage(1, 1);
    asm volatile("cp.async.commit_group;");
    int s_cur = 0, s_pre = 2;
    const int wm = wid >> 1, wn = wid & 1;
    for (int kc = 0; kc < 32; kc++) {
        asm volatile("cp.async.wait_group 1;");
        __syncthreads();
        if (kc + 2 < 32) load_stage(kc + 2, s_pre);
        asm volatile("cp.async.commit_group;");
        const u32 sb = sbase + s_cur * STAGE;
        const int i8 = lane & 7, seg = lane >> 3;
#pragma unroll
        for (int kstep = 0; kstep < 2; kstep++) {
            u32 ra0[2][4], ra1[2][4];
#pragma unroll
            for (int mt = 0; mt < 2; mt++) {
                int row = wm * 32 + mt * 16 + (lane & 15);
                int c = kstep * 2 + (lane >> 4);
                u32 sw = (u32)((c ^ ((row >> 1) & 3)) << 4);
                ldm4(ra0[mt], sb + row * 64 + sw);
                ldm4(ra1[mt], sb + (row + 128) * 64 + sw);
            }
            u32 rb[8][2];
#pragma unroll
            for (int np = 0; np < 4; np++) {
                int row = 256 + wn * 64 + np * 16 + (seg >> 1) * 8 + i8;
                int c = kstep * 2 + (seg & 1);
                u32 r4[4];
                ldm4(r4, sb + row * 64 + ((c ^ ((row >> 1) & 3)) << 4));
                rb[np * 2][0] = r4[0]; rb[np * 2][1] = r4[1];
                rb[np * 2 + 1][0] = r4[2]; rb[np * 2 + 1][1] = r4[3];
            }
#pragma unroll
            for (int mt = 0; mt < 2; mt++)
#pragma unroll
                for (int nt = 0; nt < 8; nt++)
                    mma16816(acc[mt][nt], ra0[mt], rb[nt]);
#pragma unroll
            for (int mt = 0; mt < 2; mt++)
#pragma unroll
                for (int nt = 0; nt < 8; nt++)
                    mma16816(acc[mt][nt], ra1[mt], rb[nt]);
            if constexpr (NTILE == 4) {
#pragma unroll
                for (int np = 0; np < 4; np++) {
                    int row = 384 + wn * 64 + np * 16 + (seg >> 1) * 8 + i8;
                    int c = kstep * 2 + (seg & 1);
                    u32 r4[4];
                    ldm4(r4, sb + row * 64 + ((c ^ ((row >> 1) & 3)) << 4));
                    rb[np * 2][0] = r4[0]; rb[np * 2][1] = r4[1];
                    rb[np * 2 + 1][0] = r4[2]; rb[np * 2 + 1][1] = r4[3];
                }
#pragma unroll
                for (int mt = 0; mt < 2; mt++)
#pragma unroll
                    for (int nt = 0; nt < 8; nt++)
                        mma16816(acc[mt][nt], ra0[mt], rb[nt]);
            }
        }
        s_cur = (s_cur == 2) ? 0 : s_cur + 1;
        s_pre = (s_pre == 2) ? 0 : s_pre + 1;
    }

    const int r0 = m0 + wm * 32 + (lane >> 2);
    const int cb = n0 + wn * 64 + (lane & 3) * 2;
#pragma unroll
    for (int mt = 0; mt < 2; mt++)
#pragma unroll
        for (int nt = 0; nt < 8; nt++) {
            int col = cb + nt * 8;
#pragma unroll
            for (int hh = 0; hh < 2; hh++) {
                int rr = r0 + mt * 16 + hh * 8;
                float f0 = acc[mt][nt][hh * 2], f1 = acc[mt][nt][hh * 2 + 1];
                size_t addr = (size_t)rr * 1024 + col;
                if constexpr (EPI == 0) {
                    *(float2*)(CF + addr) = make_float2(f0, f1);
                } else if constexpr (EPI == 1) {
                    u32 h, l;
                    split2(f0, f1, h, l);
                    *(u32*)(CH + addr) = h;
                    *(u32*)(CL + addr) = l;
                } else {
                    *(u32*)(CH + addr) = pack2(f0, f1);
                }
            }
        }
}

// ---------------- fused flash attention ----------------
// grid (T/128, B*H). 256 threads = 8 warps; warp owns 16 q rows.
// s-tiles of 64 keys: kh,kl,v (64x64 each, 24KB/stage), ring-3 stages,
// prefetch depth 2, one barrier per iteration. V fragments via ldmatrix.trans
// (no pre-transposed V needed). 3-term split S, online softmax, ctx += P.V.
__global__ __launch_bounds__(256) void attn_fused_k(const unsigned char* __restrict__ mask) {
    extern __shared__ char smem[];
    const u32 sbase = smem_u32(smem);
    const int tid = threadIdx.x, lane = tid & 31, w = tid >> 5;
    const int z = blockIdx.y, b = z >> 4, h = z & 15;
    const int t0 = blockIdx.x * 128;
    const int r = lane >> 2, cp = (lane & 3) * 2;
    constexpr int STAGE = 3 * 8192;   // kh + kl + v

    u32 qa[2][4][4];
    {
        const int mrow = t0 + w * 16 + r;
#pragma unroll
        for (int c = 0; c < 4; c++)
#pragma unroll
            for (int i = 0; i < 4; i++) {
                int mm = mrow + (i & 1) * 8;
                int col = h * 64 + c * 16 + cp + (i >> 1) * 8;
                size_t ad = ((size_t)(mm * 8 + b)) * 1024 + col;
                qa[0][c][i] = *(const u32*)(g_qh + ad);
                qa[1][c][i] = *(const u32*)(g_ql + ad);
            }
    }

    float ctx[8][4];
#pragma unroll
    for (int j = 0; j < 8; j++)
#pragma unroll
        for (int c = 0; c < 4; c++) ctx[j][c] = 0.f;
    float m0 = -1e30f, m1 = -1e30f, l0 = 0.f, l1 = 0.f;

    auto load_stage = [&](int it, int st) {
        const int s0 = it * 64;
        const u32 sb = sbase + st * STAGE;
#pragma unroll
        for (int p = 0; p < 6; p++) {
            int L = p * 256 + tid;
            int tile = L >> 9, rr = (L >> 3) & 63, c = L & 7;
            const __half* g;
            if (tile == 0)
                g = g_kh + ((size_t)((s0 + rr) * 8 + b)) * 1024 + h * 64 + c * 8;
            else if (tile == 1)
                g = g_kl + ((size_t)((s0 + rr) * 8 + b)) * 1024 + h * 64 + c * 8;
            else
                g = g_vh + ((size_t)((s0 + rr) * 8 + b)) * 1024 + h * 64 + c * 8;
            cpa16(sb + tile * 8192 + rr * 128 + ((c ^ (rr & 7)) << 4), g);
        }
        if (tid < 64)
            ((float*)(smem + 3 * STAGE + st * 256))[tid] =
                mask[b * 1024 + s0 + tid] ? -1e30f : 0.f;
    };

    load_stage(0, 0);
    asm volatile("cp.async.commit_group;");
    load_stage(1, 1);
    asm volatile("cp.async.commit_group;");
    int s_cur = 0, s_pre = 2;
    for (int it = 0; it < 16; it++) {
        asm volatile("cp.async.wait_group 1;");
        __syncthreads();
        if (it + 2 < 16) load_stage(it + 2, s_pre);
        asm volatile("cp.async.commit_group;");
        const u32 sb = sbase + s_cur * STAGE;

        float sc[8][4];
#pragma unroll
        for (int j = 0; j < 8; j++)
#pragma unroll
            for (int c = 0; c < 4; c++) sc[j][c] = 0.f;

        const int i8 = lane & 7, seg = lane >> 3;
#pragma unroll
        for (int c = 0; c < 4; c++) {
            u32 bf[8][2];
#pragma unroll
            for (int np = 0; np < 4; np++) {
                int row = np * 16 + (seg >> 1) * 8 + i8;
                int cc = c * 2 + (seg & 1);
                u32 r4[4];
                ldm4(r4, sb + row * 128 + ((cc ^ (row & 7)) << 4));
                bf[np * 2][0] = r4[0]; bf[np * 2][1] = r4[1];
                bf[np * 2 + 1][0] = r4[2]; bf[np * 2 + 1][1] = r4[3];
            }
#pragma unroll
            for (int j = 0; j < 8; j++) mma16816(sc[j], qa[0][c], bf[j]);
#pragma unroll
            for (int j = 0; j < 8; j++) mma16816(sc[j], qa[1][c], bf[j]);
        }
#pragma unroll
        for (int c = 0; c < 4; c++) {
            u32 bf[8][2];
#pragma unroll
            for (int np = 0; np < 4; np++) {
                int row = np * 16 + (seg >> 1) * 8 + i8;
                int cc = c * 2 + (seg & 1);
                u32 r4[4];
                ldm4(r4, sb + 8192 + row * 128 + ((cc ^ (row & 7)) << 4));
                bf[np * 2][0] = r4[0]; bf[np * 2][1] = r4[1];
                bf[np * 2 + 1][0] = r4[2]; bf[np * 2 + 1][1] = r4[3];
            }
#pragma unroll
            for (int j = 0; j < 8; j++) mma16816(sc[j], qa[0][c], bf[j]);
        }

        const float* bias = (const float*)(smem + 3 * STAGE + s_cur * 256);
        float mx0 = -1e30f, mx1 = -1e30f;
#pragma unroll
        for (int j = 0; j < 8; j++) {
            int col = j * 8 + cp;
            float b0 = bias[col], b1 = bias[col + 1];
            sc[j][0] += b0; sc[j][1] += b1;
            sc[j][2] += b0; sc[j][3] += b1;
            mx0 = fmaxf(mx0, fmaxf(sc[j][0], sc[j][1]));
            mx1 = fmaxf(mx1, fmaxf(sc[j][2], sc[j][3]));
        }
        mx0 = fmaxf(mx0, __shfl_xor_sync(~0u, mx0, 1));
        mx0 = fmaxf(mx0, __shfl_xor_sync(~0u, mx0, 2));
        mx1 = fmaxf(mx1, __shfl_xor_sync(~0u, mx1, 1));
        mx1 = fmaxf(mx1, __shfl_xor_sync(~0u, mx1, 2));
        float nm0 = fmaxf(m0, mx0), nm1 = fmaxf(m1, mx1);
        float cr0 = __expf(m0 - nm0), cr1 = __expf(m1 - nm1);
        m0 = nm0; m1 = nm1;
        float sum0 = 0.f, sum1 = 0.f;
#pragma unroll
        for (int j = 0; j < 8; j++) {
            sc[j][0] = __expf(sc[j][0] - nm0);
            sc[j][1] = __expf(sc[j][1] - nm0);
            sc[j][2] = __expf(sc[j][2] - nm1);
            sc[j][3] = __expf(sc[j][3] - nm1);
            sum0 += sc[j][0] + sc[j][1];
            sum1 += sc[j][2] + sc[j][3];
        }
        sum0 += __shfl_xor_sync(~0u, sum0, 1);
        sum0 += __shfl_xor_sync(~0u, sum0, 2);
        sum1 += __shfl_xor_sync(~0u, sum1, 1);
        sum1 += __shfl_xor_sync(~0u, sum1, 2);
        l0 = l0 * cr0 + sum0;
        l1 = l1 * cr1 + sum1;
#pragma unroll
        for (int j = 0; j < 8; j++) {
            ctx[j][0] *= cr0; ctx[j][1] *= cr0;
            ctx[j][2] *= cr1; ctx[j][3] *= cr1;
        }

        u32 pa[4][4];
#pragma unroll
        for (int c = 0; c < 4; c++) {
            pa[c][0] = pack2(sc[2 * c][0], sc[2 * c][1]);
            pa[c][1] = pack2(sc[2 * c][2], sc[2 * c][3]);
            pa[c][2] = pack2(sc[2 * c + 1][0], sc[2 * c + 1][1]);
            pa[c][3] = pack2(sc[2 * c + 1][2], sc[2 * c + 1][3]);
        }

        // ctx += P @ V ; V tile stored (row=s, col=d); B-frags via ldmatrix.trans
#pragma unroll
        for (int c = 0; c < 4; c++) {
            u32 bv[8][2];
#pragma unroll
            for (int jp = 0; jp < 4; jp++) {
                int srow = c * 16 + (seg & 1) * 8 + i8;
                int cseg = jp * 2 + (seg >> 1);
                u32 r4[4];
                ldm4t(r4, sb + 16384 + srow * 128 + ((cseg ^ (srow & 7)) << 4));
                bv[2 * jp][0] = r4[0]; bv[2 * jp][1] = r4[1];
                bv[2 * jp + 1][0] = r4[2]; bv[2 * jp + 1][1] = r4[3];
            }
#pragma unroll
            for (int j = 0; j < 8; j++) mma16816(ctx[j], pa[c], bv[j]);
        }
        s_cur = (s_cur == 2) ? 0 : s_cur + 1;
        s_pre = (s_pre == 2) ? 0 : s_pre + 1;
    }

    const float inv0 = 1.f / l0, inv1 = 1.f / l1;
    const int mrow = t0 + w * 16 + r;
#pragma unroll
    for (int j = 0; j < 8; j++) {
        int col = h * 64 + j * 8 + cp;
        u32 hh, ll;
        split2(ctx[j][0] * inv0, ctx[j][1] * inv0, hh, ll);
        size_t a0 = ((size_t)(mrow * 8 + b)) * 1024 + col;
        *(u32*)(g_ch + a0) = hh;
        *(u32*)(g_cl + a0) = ll;
        split2(ctx[j][2] * inv1, ctx[j][3] * inv1, hh, ll);
        size_t a1 = ((size_t)((mrow + 8) * 8 + b)) * 1024 + col;
        *(u32*)(g_ch + a1) = hh;
        *(u32*)(g_cl + a1) = ll;
    }
}

// ---------------- launch ----------------
extern "C" void kernel_launch(void* const* d_in, const int* in_sizes, int n_in,
                              void* d_out, int out_size) {
    const float* query = (const float*)d_in[0];
    const float* key = (const float*)d_in[1];
    const float* tgt = (const float*)d_in[2];
    const float* src = (const float*)d_in[3];
    const float* wq_f = (const float*)d_in[4];
    const float* wkv_f = (const float*)d_in[5];
    const float* wo_f = (const float*)d_in[6];
    const unsigned char* mask = (const unsigned char*)d_in[7];
    float* out = (float*)d_out;

#define SYM(v, s) cudaGetSymbolAddress((void**)&v, s)
    __half *xqh, *xql, *xkh, *xkl, *wqh, *wql, *wkh, *wkl, *wvh, *woh;
    __half *qh, *ql, *kh, *kl, *vh, *ch, *cl;
    SYM(xqh, g_xqh); SYM(xql, g_xql); SYM(xkh, g_xkh); SYM(xkl, g_xkl);
    SYM(wqh, g_wqh); SYM(wql, g_wql); SYM(wkh, g_wkh); SYM(wkl, g_wkl);
    SYM(wvh, g_wvh); SYM(woh, g_woh);
    SYM(qh, g_qh); SYM(ql, g_ql); SYM(kh, g_kh); SYM(kl, g_kl);
    SYM(vh, g_vh); SYM(ch, g_ch); SYM(cl, g_cl);

    const int SM4 = 3 * 4 * 128 * 64;          // 96 KB (4-tile, ring-3)
    const int SM3 = 3 * 3 * 128 * 64;          // 72 KB (3-tile, ring-3)
    const int SMATT = 3 * 3 * 8192 + 768;      // 74.25 KB (ring-3 + bias)
    cudaFuncSetAttribute(attn_fused_k,
                         cudaFuncAttributeMaxDynamicSharedMemorySize, SMATT);
    cudaFuncSetAttribute(gemmf<4, 1>,
                         cudaFuncAttributeMaxDynamicSharedMemorySize, SM4);
    cudaFuncSetAttribute(gemmf<3, 2>,
                         cudaFuncAttributeMaxDynamicSharedMemorySize, SM3);
    cudaFuncSetAttribute(gemmf<3, 0>,
                         cudaFuncAttributeMaxDynamicSharedMemorySize, SM3);

    // merged input-split + weight-build
    prep_k<<<24576, 256>>>(query, key, wq_f, wkv_f, wo_f, tgt, src);

    // q-proj (z=0) and k-proj (z=1) in ONE launch: 3 fused terms, split out
    gemmf<4, 1><<<dim3(8, 64, 2), 256, SM4>>>(
        xqh, xql, wqh, wql, qh, ql,
        xkh, xkl, wkh, wkl, kh, kl, nullptr);

    // v projection: 2 fused terms (xh.wv + xl.wv), plain fp16 out
    gemmf<3, 2><<<dim3(8, 64, 1), 256, SM3>>>(
        xkh, xkl, wvh, nullptr, vh, nullptr,
        xkh, xkl, wvh, nullptr, vh, nullptr, nullptr);

    // fused attention: scores(3-term) + mask + softmax + P@V (trans-ldmatrix V)
    attn_fused_k<<<dim3(8, 128), 256, SMATT>>>(mask);

    // out = ch@wo^T + cl@wo^T, fp32 out
    gemmf<3, 0><<<dim3(8, 64, 1), 256, SM3>>>(
        ch, cl, woh, nullptr, nullptr, nullptr,
        ch, cl, woh, nullptr, nullptr, nullptr, out);
}

// round 10
// speedup vs baseline: 1.6996x; 1.0372x over previous
#include <cuda_runtime.h>
#include <cuda_fp16.h>
#include <cstdint>
#include <cstddef>

using u32 = uint32_t;
using u64 = uint64_t;
#define MTOT 8192

// ---------------- static scratch (no allocation) ----------------
__device__ __half g_xqh[MTOT * 1024], g_xql[MTOT * 1024];
__device__ __half g_xkh[MTOT * 1024], g_xkl[MTOT * 1024];
__device__ __half g_wqh[1024 * 1024], g_wql[1024 * 1024];
__device__ __half g_wkh[1024 * 1024], g_wkl[1024 * 1024];
__device__ __half g_wvh[1024 * 1024];
__device__ __half g_woh[1024 * 1024];
__device__ __half g_qh[MTOT * 1024], g_ql[MTOT * 1024];
__device__ __half g_kh[MTOT * 1024], g_kl[MTOT * 1024];
__device__ __half g_vh[MTOT * 1024];
__device__ __half g_ch[MTOT * 1024], g_cl[MTOT * 1024];

// ---------------- helpers ----------------
__device__ __forceinline__ u32 smem_u32(const void* p) {
    u32 a;
    asm("{ .reg .u64 t; cvta.to.shared.u64 t, %1; cvt.u32.u64 %0, t; }"
        : "=r"(a) : "l"(p));
    return a;
}
__device__ __forceinline__ void split2(float f0, float f1, u32& h, u32& l) {
    __half a = __float2half_rn(f0), b = __float2half_rn(f1);
    h = (u32)__half_as_ushort(a) | ((u32)__half_as_ushort(b) << 16);
    __half c = __float2half_rn(f0 - __half2float(a));
    __half d = __float2half_rn(f1 - __half2float(b));
    l = (u32)__half_as_ushort(c) | ((u32)__half_as_ushort(d) << 16);
}
__device__ __forceinline__ u32 pack2(float f0, float f1) {
    __half2 hh = __floats2half2_rn(f0, f1);
    return *reinterpret_cast<u32*>(&hh);
}
__device__ __forceinline__ void cpa16(u32 s, const void* g) {
    asm volatile("cp.async.cg.shared.global [%0], [%1], 16;"
                 :: "r"(s), "l"((u64)__cvta_generic_to_global(g)));
}
__device__ __forceinline__ void ldm4(u32* r, u32 addr) {
    asm volatile("ldmatrix.sync.aligned.m8n8.x4.shared.b16 {%0,%1,%2,%3}, [%4];"
                 : "=r"(r[0]), "=r"(r[1]), "=r"(r[2]), "=r"(r[3]) : "r"(addr));
}
__device__ __forceinline__ void ldm4t(u32* r, u32 addr) {
    asm volatile("ldmatrix.sync.aligned.m8n8.x4.trans.shared.b16 {%0,%1,%2,%3}, [%4];"
                 : "=r"(r[0]), "=r"(r[1]), "=r"(r[2]), "=r"(r[3]) : "r"(addr));
}
__device__ __forceinline__ void mma16816(float* d, const u32* a, const u32* b) {
    asm volatile(
        "mma.sync.aligned.m16n8k16.row.col.f32.f16.f16.f32 "
        "{%0,%1,%2,%3},{%4,%5,%6,%7},{%8,%9},{%0,%1,%2,%3};"
        : "+f"(d[0]), "+f"(d[1]), "+f"(d[2]), "+f"(d[3])
        : "r"(a[0]), "r"(a[1]), "r"(a[2]), "r"(a[3]), "r"(b[0]), "r"(b[1]));
}

// ---------------- merged prep: input split + weight build -------------------
__global__ __launch_bounds__(256) void prep_k(
    const float* __restrict__ q, const float* __restrict__ kk,
    const float* __restrict__ wq_f, const float* __restrict__ wkv_f,
    const float* __restrict__ wo_f, const float* __restrict__ tgt,
    const float* __restrict__ src) {
    const u32 bid = blockIdx.x;
    if (bid < 8192) {
        size_t idx = (size_t)bid * 256 + threadIdx.x;  // 0..2M-1
        size_t i = idx & ((1u << 20) - 1);
        const float* sp = (idx < (1u << 20)) ? q : kk;
        __half* dh = (idx < (1u << 20)) ? g_xqh : g_xkh;
        __half* dl = (idx < (1u << 20)) ? g_xql : g_xkl;
        size_t e = i * 8;
        float4 a = ((const float4*)(sp + e))[0];
        float4 b = ((const float4*)(sp + e))[1];
        float f[8] = {a.x, a.y, a.z, a.w, b.x, b.y, b.z, b.w};
        u32 ph[4], pl[4];
#pragma unroll
        for (int j = 0; j < 4; j++) split2(f[2 * j], f[2 * j + 1], ph[j], pl[j]);
        *(uint4*)(dh + e) = make_uint4(ph[0], ph[1], ph[2], ph[3]);
        *(uint4*)(dl + e) = make_uint4(pl[0], pl[1], pl[2], pl[3]);
    } else {
        u32 n = (bid - 8192) * 256 + threadIdx.x;  // 0..4M-1
        u32 seg = n >> 20, m = n & 1048575;
        const float* w;
        const float* f;
        __half *dh, *dl = nullptr;
        float scale = 1.f;
        if (seg == 0) { w = wq_f + (size_t)m * 8; f = tgt; dh = g_wqh; dl = g_wql; scale = 0.125f; }
        else if (seg == 1) { w = wkv_f + (size_t)m * 8; f = src; dh = g_wkh; dl = g_wkl; }
        else if (seg == 2) { w = wkv_f + ((size_t)1048576 + m) * 8; f = src; dh = g_wvh; }
        else { w = wo_f + (size_t)m * 8; f = tgt; dh = g_woh; }
        float acc = 0.f;
#pragma unroll
        for (int r = 0; r < 8; r++) acc += w[r] * f[r];
        acc *= scale;
        __half h = __float2half_rn(acc);
        dh[m] = h;
        if (dl) dl[m] = __float2half_rn(acc - __half2float(h));
    }
}

// ---------------- fused-term mma.sync GEMM --------------------------------
// C = Ah@Bh^T + Al@Bh^T (+ Ah@Bl^T if NTILE==4). Per z: independent problem.
// BM=128, BN=128, BK=32. Ring-3 stages, prefetch depth 2, one barrier/chunk.
// EPI 0: fp32 -> CF. EPI 1: split fp16 -> CH/CL. EPI 2: plain fp16 -> CH.
template <int NTILE, int EPI>
__global__ __launch_bounds__(256, 2) void gemmf(
    const __half* __restrict__ Ah0, const __half* __restrict__ Al0,
    const __half* __restrict__ Bh0, const __half* __restrict__ Bl0,
    __half* CH0, __half* CL0,
    const __half* __restrict__ Ah1, const __half* __restrict__ Al1,
    const __half* __restrict__ Bh1, const __half* __restrict__ Bl1,
    __half* CH1, __half* CL1,
    float* CF) {
    constexpr int STAGE = NTILE * 128 * 64;
    constexpr int NPASS = NTILE * 2;
    extern __shared__ char smem[];
    const u32 sbase = smem_u32(smem);

    const int tid = threadIdx.x, lane = tid & 31, wid = tid >> 5;
    const int m0 = blockIdx.y * 128, n0 = blockIdx.x * 128;
    const int z = blockIdx.z;
    const __half* Ah = z ? Ah1 : Ah0;
    const __half* Al = z ? Al1 : Al0;
    const __half* Bh = z ? Bh1 : Bh0;
    const __half* Bl = z ? Bl1 : Bl0;
    __half* CH = z ? CH1 : CH0;
    __half* CL = z ? CL1 : CL0;
    const __half* tiles[4];
    tiles[0] = Ah + (size_t)m0 * 1024;
    tiles[1] = Al + (size_t)m0 * 1024;
    tiles[2] = Bh + (size_t)n0 * 1024;
    tiles[3] = (NTILE == 4) ? Bl + (size_t)n0 * 1024 : Bh;

    float acc[2][8][4];
#pragma unroll
    for (int a = 0; a < 2; a++)
#pragma unroll
        for (int b = 0; b < 8; b++)
#pragma unroll
            for (int c = 0; c < 4; c++) acc[a][b][c] = 0.f;

    auto load_stage = [&](int kc, int bufi) {
        const u32 sb = sbase + bufi * STAGE;
#pragma unroll
        for (int p = 0; p < NPASS; p++) {
            const int L = p * 256 + tid;
            const int row = L >> 2, c = L & 3;
            const __half* g = tiles[row >> 7] + (size_t)(row & 127) * 1024 +
                              kc * 32 + c * 8;
            cpa16(sb + row * 64 + ((c ^ ((row >> 1) & 3)) << 4), g);
        }
    };

    load_stage(0, 0);
    asm volatile("cp.async.commit_group;");
    load_stage(1, 1);
    asm volatile("cp.async.commit_group;");
    int s_cur = 0, s_pre = 2;
    const int wm = wid >> 1, wn = wid & 1;
    for (int kc = 0; kc < 32; kc++) {
        asm volatile("cp.async.wait_group 1;");
        __syncthreads();
        if (kc + 2 < 32) load_stage(kc + 2, s_pre);
        asm volatile("cp.async.commit_group;");
        const u32 sb = sbase + s_cur * STAGE;
        const int i8 = lane & 7, seg = lane >> 3;
#pragma unroll
        for (int kstep = 0; kstep < 2; kstep++) {
            u32 ra0[2][4], ra1[2][4];
#pragma unroll
            for (int mt = 0; mt < 2; mt++) {
                int row = wm * 32 + mt * 16 + (lane & 15);
                int c = kstep * 2 + (lane >> 4);
                u32 sw = (u32)((c ^ ((row >> 1) & 3)) << 4);
                ldm4(ra0[mt], sb + row * 64 + sw);
                ldm4(ra1[mt], sb + (row + 128) * 64 + sw);
            }
            u32 rb[8][2];
#pragma unroll
            for (int np = 0; np < 4; np++) {
                int row = 256 + wn * 64 + np * 16 + (seg >> 1) * 8 + i8;
                int c = kstep * 2 + (seg & 1);
                u32 r4[4];
                ldm4(r4, sb + row * 64 + ((c ^ ((row >> 1) & 3)) << 4));
                rb[np * 2][0] = r4[0]; rb[np * 2][1] = r4[1];
                rb[np * 2 + 1][0] = r4[2]; rb[np * 2 + 1][1] = r4[3];
            }
#pragma unroll
            for (int mt = 0; mt < 2; mt++)
#pragma unroll
                for (int nt = 0; nt < 8; nt++)
                    mma16816(acc[mt][nt], ra0[mt], rb[nt]);
#pragma unroll
            for (int mt = 0; mt < 2; mt++)
#pragma unroll
                for (int nt = 0; nt < 8; nt++)
                    mma16816(acc[mt][nt], ra1[mt], rb[nt]);
            if constexpr (NTILE == 4) {
#pragma unroll
                for (int np = 0; np < 4; np++) {
                    int row = 384 + wn * 64 + np * 16 + (seg >> 1) * 8 + i8;
                    int c = kstep * 2 + (seg & 1);
                    u32 r4[4];
                    ldm4(r4, sb + row * 64 + ((c ^ ((row >> 1) & 3)) << 4));
                    rb[np * 2][0] = r4[0]; rb[np * 2][1] = r4[1];
                    rb[np * 2 + 1][0] = r4[2]; rb[np * 2 + 1][1] = r4[3];
                }
#pragma unroll
                for (int mt = 0; mt < 2; mt++)
#pragma unroll
                    for (int nt = 0; nt < 8; nt++)
                        mma16816(acc[mt][nt], ra0[mt], rb[nt]);
            }
        }
        s_cur = (s_cur == 2) ? 0 : s_cur + 1;
        s_pre = (s_pre == 2) ? 0 : s_pre + 1;
    }

    const int r0 = m0 + wm * 32 + (lane >> 2);
    const int cb = n0 + wn * 64 + (lane & 3) * 2;
#pragma unroll
    for (int mt = 0; mt < 2; mt++)
#pragma unroll
        for (int nt = 0; nt < 8; nt++) {
            int col = cb + nt * 8;
#pragma unroll
            for (int hh = 0; hh < 2; hh++) {
                int rr = r0 + mt * 16 + hh * 8;
                float f0 = acc[mt][nt][hh * 2], f1 = acc[mt][nt][hh * 2 + 1];
                size_t addr = (size_t)rr * 1024 + col;
                if constexpr (EPI == 0) {
                    *(float2*)(CF + addr) = make_float2(f0, f1);
                } else if constexpr (EPI == 1) {
                    u32 h, l;
                    split2(f0, f1, h, l);
                    *(u32*)(CH + addr) = h;
                    *(u32*)(CL + addr) = l;
                } else {
                    *(u32*)(CH + addr) = pack2(f0, f1);
                }
            }
        }
}

// ---------------- fused flash attention ----------------
// grid (T/128, B*H). 256 threads = 8 warps; warp owns 16 q rows.
// s-tiles of 64 keys: kh,kl,v (64x64 each, 24KB/stage), ring-3 stages,
// prefetch depth 2, one barrier per iteration. V fragments via ldmatrix.trans.
// 3-term split S, online softmax, ctx += P.V. 2 CTAs/SM (reg cap 128).
__global__ __launch_bounds__(256, 2) void attn_fused_k(const unsigned char* __restrict__ mask) {
    extern __shared__ char smem[];
    const u32 sbase = smem_u32(smem);
    const int tid = threadIdx.x, lane = tid & 31, w = tid >> 5;
    const int z = blockIdx.y, b = z >> 4, h = z & 15;
    const int t0 = blockIdx.x * 128;
    const int r = lane >> 2, cp = (lane & 3) * 2;
    constexpr int STAGE = 3 * 8192;   // kh + kl + v

    u32 qa[2][4][4];
    {
        const int mrow = t0 + w * 16 + r;
#pragma unroll
        for (int c = 0; c < 4; c++)
#pragma unroll
            for (int i = 0; i < 4; i++) {
                int mm = mrow + (i & 1) * 8;
                int col = h * 64 + c * 16 + cp + (i >> 1) * 8;
                size_t ad = ((size_t)(mm * 8 + b)) * 1024 + col;
                qa[0][c][i] = *(const u32*)(g_qh + ad);
                qa[1][c][i] = *(const u32*)(g_ql + ad);
            }
    }

    float ctx[8][4];
#pragma unroll
    for (int j = 0; j < 8; j++)
#pragma unroll
        for (int c = 0; c < 4; c++) ctx[j][c] = 0.f;
    float m0 = -1e30f, m1 = -1e30f, l0 = 0.f, l1 = 0.f;

    auto load_stage = [&](int it, int st) {
        const int s0 = it * 64;
        const u32 sb = sbase + st * STAGE;
#pragma unroll
        for (int p = 0; p < 6; p++) {
            int L = p * 256 + tid;
            int tile = L >> 9, rr = (L >> 3) & 63, c = L & 7;
            const __half* g;
            if (tile == 0)
                g = g_kh + ((size_t)((s0 + rr) * 8 + b)) * 1024 + h * 64 + c * 8;
            else if (tile == 1)
                g = g_kl + ((size_t)((s0 + rr) * 8 + b)) * 1024 + h * 64 + c * 8;
            else
                g = g_vh + ((size_t)((s0 + rr) * 8 + b)) * 1024 + h * 64 + c * 8;
            cpa16(sb + tile * 8192 + rr * 128 + ((c ^ (rr & 7)) << 4), g);
        }
        if (tid < 64)
            ((float*)(smem + 3 * STAGE + st * 256))[tid] =
                mask[b * 1024 + s0 + tid] ? -1e30f : 0.f;
    };

    load_stage(0, 0);
    asm volatile("cp.async.commit_group;");
    load_stage(1, 1);
    asm volatile("cp.async.commit_group;");
    int s_cur = 0, s_pre = 2;
    for (int it = 0; it < 16; it++) {
        asm volatile("cp.async.wait_group 1;");
        __syncthreads();
        if (it + 2 < 16) load_stage(it + 2, s_pre);
        asm volatile("cp.async.commit_group;");
        const u32 sb = sbase + s_cur * STAGE;

        float sc[8][4];
#pragma unroll
        for (int j = 0; j < 8; j++)
#pragma unroll
            for (int c = 0; c < 4; c++) sc[j][c] = 0.f;

        const int i8 = lane & 7, seg = lane >> 3;
#pragma unroll
        for (int c = 0; c < 4; c++) {
            u32 bf[8][2];
#pragma unroll
            for (int np = 0; np < 4; np++) {
                int row = np * 16 + (seg >> 1) * 8 + i8;
                int cc = c * 2 + (seg & 1);
                u32 r4[4];
                ldm4(r4, sb + row * 128 + ((cc ^ (row & 7)) << 4));
                bf[np * 2][0] = r4[0]; bf[np * 2][1] = r4[1];
                bf[np * 2 + 1][0] = r4[2]; bf[np * 2 + 1][1] = r4[3];
            }
#pragma unroll
            for (int j = 0; j < 8; j++) mma16816(sc[j], qa[0][c], bf[j]);
#pragma unroll
            for (int j = 0; j < 8; j++) mma16816(sc[j], qa[1][c], bf[j]);
        }
#pragma unroll
        for (int c = 0; c < 4; c++) {
            u32 bf[8][2];
#pragma unroll
            for (int np = 0; np < 4; np++) {
                int row = np * 16 + (seg >> 1) * 8 + i8;
                int cc = c * 2 + (seg & 1);
                u32 r4[4];
                ldm4(r4, sb + 8192 + row * 128 + ((cc ^ (row & 7)) << 4));
                bf[np * 2][0] = r4[0]; bf[np * 2][1] = r4[1];
                bf[np * 2 + 1][0] = r4[2]; bf[np * 2 + 1][1] = r4[3];
            }
#pragma unroll
            for (int j = 0; j < 8; j++) mma16816(sc[j], qa[0][c], bf[j]);
        }

        const float* bias = (const float*)(smem + 3 * STAGE + s_cur * 256);
        float mx0 = -1e30f, mx1 = -1e30f;
#pragma unroll
        for (int j = 0; j < 8; j++) {
            int col = j * 8 + cp;
            float b0 = bias[col], b1 = bias[col + 1];
            sc[j][0] += b0; sc[j][1] += b1;
            sc[j][2] += b0; sc[j][3] += b1;
            mx0 = fmaxf(mx0, fmaxf(sc[j][0], sc[j][1]));
            mx1 = fmaxf(mx1, fmaxf(sc[j][2], sc[j][3]));
        }
        mx0 = fmaxf(mx0, __shfl_xor_sync(~0u, mx0, 1));
        mx0 = fmaxf(mx0, __shfl_xor_sync(~0u, mx0, 2));
        mx1 = fmaxf(mx1, __shfl_xor_sync(~0u, mx1, 1));
        mx1 = fmaxf(mx1, __shfl_xor_sync(~0u, mx1, 2));
        float nm0 = fmaxf(m0, mx0), nm1 = fmaxf(m1, mx1);
        float cr0 = __expf(m0 - nm0), cr1 = __expf(m1 - nm1);
        m0 = nm0; m1 = nm1;
        float sum0 = 0.f, sum1 = 0.f;
#pragma unroll
        for (int j = 0; j < 8; j++) {
            sc[j][0] = __expf(sc[j][0] - nm0);
            sc[j][1] = __expf(sc[j][1] - nm0);
            sc[j][2] = __expf(sc[j][2] - nm1);
            sc[j][3] = __expf(sc[j][3] - nm1);
            sum0 += sc[j][0] + sc[j][1];
            sum1 += sc[j][2] + sc[j][3];
        }
        sum0 += __shfl_xor_sync(~0u, sum0, 1);
        sum0 += __shfl_xor_sync(~0u, sum0, 2);
        sum1 += __shfl_xor_sync(~0u, sum1, 1);
        sum1 += __shfl_xor_sync(~0u, sum1, 2);
        l0 = l0 * cr0 + sum0;
        l1 = l1 * cr1 + sum1;
#pragma unroll
        for (int j = 0; j < 8; j++) {
            ctx[j][0] *= cr0; ctx[j][1] *= cr0;
            ctx[j][2] *= cr1; ctx[j][3] *= cr1;
        }

        u32 pa[4][4];
#pragma unroll
        for (int c = 0; c < 4; c++) {
            pa[c][0] = pack2(sc[2 * c][0], sc[2 * c][1]);
            pa[c][1] = pack2(sc[2 * c][2], sc[2 * c][3]);
            pa[c][2] = pack2(sc[2 * c + 1][0], sc[2 * c + 1][1]);
            pa[c][3] = pack2(sc[2 * c + 1][2], sc[2 * c + 1][3]);
        }

        // ctx += P @ V ; V tile stored (row=s, col=d); B-frags via ldmatrix.trans
#pragma unroll
        for (int c = 0; c < 4; c++) {
            u32 bv[8][2];
#pragma unroll
            for (int jp = 0; jp < 4; jp++) {
                int srow = c * 16 + (seg & 1) * 8 + i8;
                int cseg = jp * 2 + (seg >> 1);
                u32 r4[4];
                ldm4t(r4, sb + 16384 + srow * 128 + ((cseg ^ (srow & 7)) << 4));
                bv[2 * jp][0] = r4[0]; bv[2 * jp][1] = r4[1];
                bv[2 * jp + 1][0] = r4[2]; bv[2 * jp + 1][1] = r4[3];
            }
#pragma unroll
            for (int j = 0; j < 8; j++) mma16816(ctx[j], pa[c], bv[j]);
        }
        s_cur = (s_cur == 2) ? 0 : s_cur + 1;
        s_pre = (s_pre == 2) ? 0 : s_pre + 1;
    }

    const float inv0 = 1.f / l0, inv1 = 1.f / l1;
    const int mrow = t0 + w * 16 + r;
#pragma unroll
    for (int j = 0; j < 8; j++) {
        int col = h * 64 + j * 8 + cp;
        u32 hh, ll;
        split2(ctx[j][0] * inv0, ctx[j][1] * inv0, hh, ll);
        size_t a0 = ((size_t)(mrow * 8 + b)) * 1024 + col;
        *(u32*)(g_ch + a0) = hh;
        *(u32*)(g_cl + a0) = ll;
        split2(ctx[j][2] * inv1, ctx[j][3] * inv1, hh, ll);
        size_t a1 = ((size_t)((mrow + 8) * 8 + b)) * 1024 + col;
        *(u32*)(g_ch + a1) = hh;
        *(u32*)(g_cl + a1) = ll;
    }
}

// ---------------- launch ----------------
extern "C" void kernel_launch(void* const* d_in, const int* in_sizes, int n_in,
                              void* d_out, int out_size) {
    const float* query = (const float*)d_in[0];
    const float* key = (const float*)d_in[1];
    const float* tgt = (const float*)d_in[2];
    const float* src = (const float*)d_in[3];
    const float* wq_f = (const float*)d_in[4];
    const float* wkv_f = (const float*)d_in[5];
    const float* wo_f = (const float*)d_in[6];
    const unsigned char* mask = (const unsigned char*)d_in[7];
    float* out = (float*)d_out;

#define SYM(v, s) cudaGetSymbolAddress((void**)&v, s)
    __half *xqh, *xql, *xkh, *xkl, *wqh, *wql, *wkh, *wkl, *wvh, *woh;
    __half *qh, *ql, *kh, *kl, *vh, *ch, *cl;
    SYM(xqh, g_xqh); SYM(xql, g_xql); SYM(xkh, g_xkh); SYM(xkl, g_xkl);
    SYM(wqh, g_wqh); SYM(wql, g_wql); SYM(wkh, g_wkh); SYM(wkl, g_wkl);
    SYM(wvh, g_wvh); SYM(woh, g_woh);
    SYM(qh, g_qh); SYM(ql, g_ql); SYM(kh, g_kh); SYM(kl, g_kl);
    SYM(vh, g_vh); SYM(ch, g_ch); SYM(cl, g_cl);

    const int SM4 = 3 * 4 * 128 * 64;          // 96 KB (4-tile, ring-3)
    const int SM3 = 3 * 3 * 128 * 64;          // 72 KB (3-tile, ring-3)
    const int SMATT = 3 * 3 * 8192 + 768;      // 74.25 KB (ring-3 + bias)
    cudaFuncSetAttribute(attn_fused_k,
                         cudaFuncAttributeMaxDynamicSharedMemorySize, SMATT);
    cudaFuncSetAttribute(gemmf<4, 1>,
                         cudaFuncAttributeMaxDynamicSharedMemorySize, SM4);
    cudaFuncSetAttribute(gemmf<3, 2>,
                         cudaFuncAttributeMaxDynamicSharedMemorySize, SM3);
    cudaFuncSetAttribute(gemmf<3, 0>,
                         cudaFuncAttributeMaxDynamicSharedMemorySize, SM3);

    // merged input-split + weight-build
    prep_k<<<24576, 256>>>(query, key, wq_f, wkv_f, wo_f, tgt, src);

    // q-proj (z=0) and k-proj (z=1) in ONE launch: 3 fused terms, split out
    gemmf<4, 1><<<dim3(8, 64, 2), 256, SM4>>>(
        xqh, xql, wqh, wql, qh, ql,
        xkh, xkl, wkh, wkl, kh, kl, nullptr);

    // v projection: 2 fused terms (xh.wv + xl.wv), plain fp16 out
    gemmf<3, 2><<<dim3(8, 64, 1), 256, SM3>>>(
        xkh, xkl, wvh, nullptr, vh, nullptr,
        xkh, xkl, wvh, nullptr, vh, nullptr, nullptr);

    // fused attention: scores(3-term) + mask + softmax + P@V (trans-ldmatrix V)
    attn_fused_k<<<dim3(8, 128), 256, SMATT>>>(mask);

    // out = ch@wo^T + cl@wo^T, fp32 out
    gemmf<3, 0><<<dim3(8, 64, 1), 256, SM3>>>(
        ch, cl, woh, nullptr, nullptr, nullptr,
        ch, cl, woh, nullptr, nullptr, nullptr, out);
}

// round 11
// speedup vs baseline: 1.8613x; 1.0951x over previous
#include <cuda_runtime.h>
#include <cuda_fp16.h>
#include <cstdint>
#include <cstddef>

using u32 = uint32_t;
using u64 = uint64_t;
#define MTOT 8192

// ---------------- static scratch (no allocation) ----------------
__device__ __half g_xqh[MTOT * 1024], g_xql[MTOT * 1024];
__device__ __half g_xkh[MTOT * 1024], g_xkl[MTOT * 1024];
__device__ __half g_wqh[1024 * 1024], g_wql[1024 * 1024];
__device__ __half g_wkh[1024 * 1024], g_wkl[1024 * 1024];
__device__ __half g_wvh[1024 * 1024];
__device__ __half g_woh[1024 * 1024];
__device__ __half g_qh[MTOT * 1024], g_ql[MTOT * 1024];
__device__ __half g_kh[MTOT * 1024], g_kl[MTOT * 1024];
__device__ __half g_vh[MTOT * 1024];
__device__ __half g_ch[MTOT * 1024];

// ---------------- helpers ----------------
__device__ __forceinline__ u32 smem_u32(const void* p) {
    u32 a;
    asm("{ .reg .u64 t; cvta.to.shared.u64 t, %1; cvt.u32.u64 %0, t; }"
        : "=r"(a) : "l"(p));
    return a;
}
__device__ __forceinline__ void split2(float f0, float f1, u32& h, u32& l) {
    __half a = __float2half_rn(f0), b = __float2half_rn(f1);
    h = (u32)__half_as_ushort(a) | ((u32)__half_as_ushort(b) << 16);
    __half c = __float2half_rn(f0 - __half2float(a));
    __half d = __float2half_rn(f1 - __half2float(b));
    l = (u32)__half_as_ushort(c) | ((u32)__half_as_ushort(d) << 16);
}
__device__ __forceinline__ u32 pack2(float f0, float f1) {
    __half2 hh = __floats2half2_rn(f0, f1);
    return *reinterpret_cast<u32*>(&hh);
}
__device__ __forceinline__ void cpa16(u32 s, const void* g) {
    asm volatile("cp.async.cg.shared.global [%0], [%1], 16;"
                 :: "r"(s), "l"((u64)__cvta_generic_to_global(g)));
}
__device__ __forceinline__ void ldm4(u32* r, u32 addr) {
    asm volatile("ldmatrix.sync.aligned.m8n8.x4.shared.b16 {%0,%1,%2,%3}, [%4];"
                 : "=r"(r[0]), "=r"(r[1]), "=r"(r[2]), "=r"(r[3]) : "r"(addr));
}
__device__ __forceinline__ void ldm4t(u32* r, u32 addr) {
    asm volatile("ldmatrix.sync.aligned.m8n8.x4.trans.shared.b16 {%0,%1,%2,%3}, [%4];"
                 : "=r"(r[0]), "=r"(r[1]), "=r"(r[2]), "=r"(r[3]) : "r"(addr));
}
__device__ __forceinline__ void mma16816(float* d, const u32* a, const u32* b) {
    asm volatile(
        "mma.sync.aligned.m16n8k16.row.col.f32.f16.f16.f32 "
        "{%0,%1,%2,%3},{%4,%5,%6,%7},{%8,%9},{%0,%1,%2,%3};"
        : "+f"(d[0]), "+f"(d[1]), "+f"(d[2]), "+f"(d[3])
        : "r"(a[0]), "r"(a[1]), "r"(a[2]), "r"(a[3]), "r"(b[0]), "r"(b[1]));
}

// ---------------- merged prep: input split + weight build -------------------
__global__ __launch_bounds__(256) void prep_k(
    const float* __restrict__ q, const float* __restrict__ kk,
    const float* __restrict__ wq_f, const float* __restrict__ wkv_f,
    const float* __restrict__ wo_f, const float* __restrict__ tgt,
    const float* __restrict__ src) {
    const u32 bid = blockIdx.x;
    if (bid < 8192) {
        size_t idx = (size_t)bid * 256 + threadIdx.x;  // 0..2M-1
        size_t i = idx & ((1u << 20) - 1);
        const float* sp = (idx < (1u << 20)) ? q : kk;
        __half* dh = (idx < (1u << 20)) ? g_xqh : g_xkh;
        __half* dl = (idx < (1u << 20)) ? g_xql : g_xkl;
        size_t e = i * 8;
        float4 a = ((const float4*)(sp + e))[0];
        float4 b = ((const float4*)(sp + e))[1];
        float f[8] = {a.x, a.y, a.z, a.w, b.x, b.y, b.z, b.w};
        u32 ph[4], pl[4];
#pragma unroll
        for (int j = 0; j < 4; j++) split2(f[2 * j], f[2 * j + 1], ph[j], pl[j]);
        *(uint4*)(dh + e) = make_uint4(ph[0], ph[1], ph[2], ph[3]);
        *(uint4*)(dl + e) = make_uint4(pl[0], pl[1], pl[2], pl[3]);
    } else {
        u32 n = (bid - 8192) * 256 + threadIdx.x;  // 0..4M-1
        u32 seg = n >> 20, m = n & 1048575;
        const float* w;
        const float* f;
        __half *dh, *dl = nullptr;
        float scale = 1.f;
        if (seg == 0) { w = wq_f + (size_t)m * 8; f = tgt; dh = g_wqh; dl = g_wql; scale = 0.125f; }
        else if (seg == 1) { w = wkv_f + (size_t)m * 8; f = src; dh = g_wkh; dl = g_wkl; }
        else if (seg == 2) { w = wkv_f + ((size_t)1048576 + m) * 8; f = src; dh = g_wvh; }
        else { w = wo_f + (size_t)m * 8; f = tgt; dh = g_woh; }
        float acc = 0.f;
#pragma unroll
        for (int r = 0; r < 8; r++) acc += w[r] * f[r];
        acc *= scale;
        __half h = __float2half_rn(acc);
        dh[m] = h;
        if (dl) dl[m] = __float2half_rn(acc - __half2float(h));
    }
}

// ---------------- merged q/k/v projection (one launch) ----------------------
// z=0: q = xqh.wqh + xql.wqh + xqh.wql -> split qh/ql
// z=1: k = xkh.wkh + xkl.wkh + xkh.wkl -> split kh/kl
// z=2: v = xkh.wvh + xkl.wvh           -> plain vh (skips Bl tile + 3rd pass)
// BM=128, BN=128, BK=32. Stage: {Ah,Al,Bh,Bl} 32KB. Ring-3, depth-2 prefetch.
__global__ __launch_bounds__(256, 2) void qkv_proj_k() {
    constexpr int STAGE = 4 * 128 * 64;
    extern __shared__ char smem[];
    const u32 sbase = smem_u32(smem);

    const int tid = threadIdx.x, lane = tid & 31, wid = tid >> 5;
    const int m0 = blockIdx.y * 128, n0 = blockIdx.x * 128;
    const int z = blockIdx.z;
    const __half *Ah, *Al, *Bh, *Bl;
    __half *CH, *CL;
    if (z == 0) { Ah = g_xqh; Al = g_xql; Bh = g_wqh; Bl = g_wql; CH = g_qh; CL = g_ql; }
    else if (z == 1) { Ah = g_xkh; Al = g_xkl; Bh = g_wkh; Bl = g_wkl; CH = g_kh; CL = g_kl; }
    else { Ah = g_xkh; Al = g_xkl; Bh = g_wvh; Bl = g_wvh; CH = g_vh; CL = nullptr; }
    const bool full = (z < 2);
    const __half* tiles[4];
    tiles[0] = Ah + (size_t)m0 * 1024;
    tiles[1] = Al + (size_t)m0 * 1024;
    tiles[2] = Bh + (size_t)n0 * 1024;
    tiles[3] = Bl + (size_t)n0 * 1024;

    float acc[2][8][4];
#pragma unroll
    for (int a = 0; a < 2; a++)
#pragma unroll
        for (int b = 0; b < 8; b++)
#pragma unroll
            for (int c = 0; c < 4; c++) acc[a][b][c] = 0.f;

    auto load_stage = [&](int kc, int bufi) {
        const u32 sb = sbase + bufi * STAGE;
#pragma unroll
        for (int p = 0; p < 8; p++) {
            if (p >= 6 && !full) break;   // rows 384+ are Bl: skip for v
            const int L = p * 256 + tid;
            const int row = L >> 2, c = L & 3;
            const __half* g = tiles[row >> 7] + (size_t)(row & 127) * 1024 +
                              kc * 32 + c * 8;
            cpa16(sb + row * 64 + ((c ^ ((row >> 1) & 3)) << 4), g);
        }
    };

    load_stage(0, 0);
    asm volatile("cp.async.commit_group;");
    load_stage(1, 1);
    asm volatile("cp.async.commit_group;");
    int s_cur = 0, s_pre = 2;
    const int wm = wid >> 1, wn = wid & 1;
    for (int kc = 0; kc < 32; kc++) {
        asm volatile("cp.async.wait_group 1;");
        __syncthreads();
        if (kc + 2 < 32) load_stage(kc + 2, s_pre);
        asm volatile("cp.async.commit_group;");
        const u32 sb = sbase + s_cur * STAGE;
        const int i8 = lane & 7, seg = lane >> 3;
#pragma unroll
        for (int kstep = 0; kstep < 2; kstep++) {
            u32 ra0[2][4], ra1[2][4];
#pragma unroll
            for (int mt = 0; mt < 2; mt++) {
                int row = wm * 32 + mt * 16 + (lane & 15);
                int c = kstep * 2 + (lane >> 4);
                u32 sw = (u32)((c ^ ((row >> 1) & 3)) << 4);
                ldm4(ra0[mt], sb + row * 64 + sw);
                ldm4(ra1[mt], sb + (row + 128) * 64 + sw);
            }
            u32 rb[8][2];
#pragma unroll
            for (int np = 0; np < 4; np++) {
                int row = 256 + wn * 64 + np * 16 + (seg >> 1) * 8 + i8;
                int c = kstep * 2 + (seg & 1);
                u32 r4[4];
                ldm4(r4, sb + row * 64 + ((c ^ ((row >> 1) & 3)) << 4));
                rb[np * 2][0] = r4[0]; rb[np * 2][1] = r4[1];
                rb[np * 2 + 1][0] = r4[2]; rb[np * 2 + 1][1] = r4[3];
            }
#pragma unroll
            for (int mt = 0; mt < 2; mt++)
#pragma unroll
                for (int nt = 0; nt < 8; nt++)
                    mma16816(acc[mt][nt], ra0[mt], rb[nt]);
#pragma unroll
            for (int mt = 0; mt < 2; mt++)
#pragma unroll
                for (int nt = 0; nt < 8; nt++)
                    mma16816(acc[mt][nt], ra1[mt], rb[nt]);
            if (full) {
#pragma unroll
                for (int np = 0; np < 4; np++) {
                    int row = 384 + wn * 64 + np * 16 + (seg >> 1) * 8 + i8;
                    int c = kstep * 2 + (seg & 1);
                    u32 r4[4];
                    ldm4(r4, sb + row * 64 + ((c ^ ((row >> 1) & 3)) << 4));
                    rb[np * 2][0] = r4[0]; rb[np * 2][1] = r4[1];
                    rb[np * 2 + 1][0] = r4[2]; rb[np * 2 + 1][1] = r4[3];
                }
#pragma unroll
                for (int mt = 0; mt < 2; mt++)
#pragma unroll
                    for (int nt = 0; nt < 8; nt++)
                        mma16816(acc[mt][nt], ra0[mt], rb[nt]);
            }
        }
        s_cur = (s_cur == 2) ? 0 : s_cur + 1;
        s_pre = (s_pre == 2) ? 0 : s_pre + 1;
    }

    const int r0 = m0 + wm * 32 + (lane >> 2);
    const int cb = n0 + wn * 64 + (lane & 3) * 2;
#pragma unroll
    for (int mt = 0; mt < 2; mt++)
#pragma unroll
        for (int nt = 0; nt < 8; nt++) {
            int col = cb + nt * 8;
#pragma unroll
            for (int hh = 0; hh < 2; hh++) {
                int rr = r0 + mt * 16 + hh * 8;
                float f0 = acc[mt][nt][hh * 2], f1 = acc[mt][nt][hh * 2 + 1];
                size_t addr = (size_t)rr * 1024 + col;
                if (CL) {
                    u32 h, l;
                    split2(f0, f1, h, l);
                    *(u32*)(CH + addr) = h;
                    *(u32*)(CL + addr) = l;
                } else {
                    *(u32*)(CH + addr) = pack2(f0, f1);
                }
            }
        }
}

// ---------------- out-projection: out = ch @ woh^T (single term, fp32 out) --
// BM=128, BN=128, BK=32. Stage: {A,B} 16KB. Ring-3, depth-2 prefetch.
__global__ __launch_bounds__(256, 2) void gemmo_k(float* __restrict__ CF) {
    constexpr int STAGE = 2 * 128 * 64;
    extern __shared__ char smem[];
    const u32 sbase = smem_u32(smem);

    const int tid = threadIdx.x, lane = tid & 31, wid = tid >> 5;
    const int m0 = blockIdx.y * 128, n0 = blockIdx.x * 128;
    const __half* tiles[2];
    tiles[0] = g_ch + (size_t)m0 * 1024;
    tiles[1] = g_woh + (size_t)n0 * 1024;

    float acc[2][8][4];
#pragma unroll
    for (int a = 0; a < 2; a++)
#pragma unroll
        for (int b = 0; b < 8; b++)
#pragma unroll
            for (int c = 0; c < 4; c++) acc[a][b][c] = 0.f;

    auto load_stage = [&](int kc, int bufi) {
        const u32 sb = sbase + bufi * STAGE;
#pragma unroll
        for (int p = 0; p < 4; p++) {
            const int L = p * 256 + tid;
            const int row = L >> 2, c = L & 3;
            const __half* g = tiles[row >> 7] + (size_t)(row & 127) * 1024 +
                              kc * 32 + c * 8;
            cpa16(sb + row * 64 + ((c ^ ((row >> 1) & 3)) << 4), g);
        }
    };

    load_stage(0, 0);
    asm volatile("cp.async.commit_group;");
    load_stage(1, 1);
    asm volatile("cp.async.commit_group;");
    int s_cur = 0, s_pre = 2;
    const int wm = wid >> 1, wn = wid & 1;
    for (int kc = 0; kc < 32; kc++) {
        asm volatile("cp.async.wait_group 1;");
        __syncthreads();
        if (kc + 2 < 32) load_stage(kc + 2, s_pre);
        asm volatile("cp.async.commit_group;");
        const u32 sb = sbase + s_cur * STAGE;
        const int i8 = lane & 7, seg = lane >> 3;
#pragma unroll
        for (int kstep = 0; kstep < 2; kstep++) {
            u32 ra0[2][4];
#pragma unroll
            for (int mt = 0; mt < 2; mt++) {
                int row = wm * 32 + mt * 16 + (lane & 15);
                int c = kstep * 2 + (lane >> 4);
                ldm4(ra0[mt], sb + row * 64 + ((c ^ ((row >> 1) & 3)) << 4));
            }
            u32 rb[8][2];
#pragma unroll
            for (int np = 0; np < 4; np++) {
                int row = 128 + wn * 64 + np * 16 + (seg >> 1) * 8 + i8;
                int c = kstep * 2 + (seg & 1);
                u32 r4[4];
                ldm4(r4, sb + row * 64 + ((c ^ ((row >> 1) & 3)) << 4));
                rb[np * 2][0] = r4[0]; rb[np * 2][1] = r4[1];
                rb[np * 2 + 1][0] = r4[2]; rb[np * 2 + 1][1] = r4[3];
            }
#pragma unroll
            for (int mt = 0; mt < 2; mt++)
#pragma unroll
                for (int nt = 0; nt < 8; nt++)
                    mma16816(acc[mt][nt], ra0[mt], rb[nt]);
        }
        s_cur = (s_cur == 2) ? 0 : s_cur + 1;
        s_pre = (s_pre == 2) ? 0 : s_pre + 1;
    }

    const int r0 = m0 + wm * 32 + (lane >> 2);
    const int cb = n0 + wn * 64 + (lane & 3) * 2;
#pragma unroll
    for (int mt = 0; mt < 2; mt++)
#pragma unroll
        for (int nt = 0; nt < 8; nt++) {
            int col = cb + nt * 8;
#pragma unroll
            for (int hh = 0; hh < 2; hh++) {
                int rr = r0 + mt * 16 + hh * 8;
                *(float2*)(CF + (size_t)rr * 1024 + col) =
                    make_float2(acc[mt][nt][hh * 2], acc[mt][nt][hh * 2 + 1]);
            }
        }
}

// ---------------- fused flash attention ----------------
// grid (T/128, B*H). 256 threads = 8 warps; warp owns 16 q rows.
// s-tiles of 64 keys: kh,kl,v (64x64 each, 24KB/stage), ring-3 stages,
// prefetch depth 2, one barrier per iteration. V fragments via ldmatrix.trans.
// 3-term split S, online softmax, ctx += P.V. 2 CTAs/SM (reg cap 128).
__global__ __launch_bounds__(256, 2) void attn_fused_k(const unsigned char* __restrict__ mask) {
    extern __shared__ char smem[];
    const u32 sbase = smem_u32(smem);
    const int tid = threadIdx.x, lane = tid & 31, w = tid >> 5;
    const int z = blockIdx.y, b = z >> 4, h = z & 15;
    const int t0 = blockIdx.x * 128;
    const int r = lane >> 2, cp = (lane & 3) * 2;
    constexpr int STAGE = 3 * 8192;   // kh + kl + v

    u32 qa[2][4][4];
    {
        const int mrow = t0 + w * 16 + r;
#pragma unroll
        for (int c = 0; c < 4; c++)
#pragma unroll
            for (int i = 0; i < 4; i++) {
                int mm = mrow + (i & 1) * 8;
                int col = h * 64 + c * 16 + cp + (i >> 1) * 8;
                size_t ad = ((size_t)(mm * 8 + b)) * 1024 + col;
                qa[0][c][i] = *(const u32*)(g_qh + ad);
                qa[1][c][i] = *(const u32*)(g_ql + ad);
            }
    }

    float ctx[8][4];
#pragma unroll
    for (int j = 0; j < 8; j++)
#pragma unroll
        for (int c = 0; c < 4; c++) ctx[j][c] = 0.f;
    float m0 = -1e30f, m1 = -1e30f, l0 = 0.f, l1 = 0.f;

    auto load_stage = [&](int it, int st) {
        const int s0 = it * 64;
        const u32 sb = sbase + st * STAGE;
#pragma unroll
        for (int p = 0; p < 6; p++) {
            int L = p * 256 + tid;
            int tile = L >> 9, rr = (L >> 3) & 63, c = L & 7;
            const __half* g;
            if (tile == 0)
                g = g_kh + ((size_t)((s0 + rr) * 8 + b)) * 1024 + h * 64 + c * 8;
            else if (tile == 1)
                g = g_kl + ((size_t)((s0 + rr) * 8 + b)) * 1024 + h * 64 + c * 8;
            else
                g = g_vh + ((size_t)((s0 + rr) * 8 + b)) * 1024 + h * 64 + c * 8;
            cpa16(sb + tile * 8192 + rr * 128 + ((c ^ (rr & 7)) << 4), g);
        }
        if (tid < 64)
            ((float*)(smem + 3 * STAGE + st * 256))[tid] =
                mask[b * 1024 + s0 + tid] ? -1e30f : 0.f;
    };

    load_stage(0, 0);
    asm volatile("cp.async.commit_group;");
    load_stage(1, 1);
    asm volatile("cp.async.commit_group;");
    int s_cur = 0, s_pre = 2;
    for (int it = 0; it < 16; it++) {
        asm volatile("cp.async.wait_group 1;");
        __syncthreads();
        if (it + 2 < 16) load_stage(it + 2, s_pre);
        asm volatile("cp.async.commit_group;");
        const u32 sb = sbase + s_cur * STAGE;

        float sc[8][4];
#pragma unroll
        for (int j = 0; j < 8; j++)
#pragma unroll
            for (int c = 0; c < 4; c++) sc[j][c] = 0.f;

        const int i8 = lane & 7, seg = lane >> 3;
#pragma unroll
        for (int c = 0; c < 4; c++) {
            u32 bf[8][2];
#pragma unroll
            for (int np = 0; np < 4; np++) {
                int row = np * 16 + (seg >> 1) * 8 + i8;
                int cc = c * 2 + (seg & 1);
                u32 r4[4];
                ldm4(r4, sb + row * 128 + ((cc ^ (row & 7)) << 4));
                bf[np * 2][0] = r4[0]; bf[np * 2][1] = r4[1];
                bf[np * 2 + 1][0] = r4[2]; bf[np * 2 + 1][1] = r4[3];
            }
#pragma unroll
            for (int j = 0; j < 8; j++) mma16816(sc[j], qa[0][c], bf[j]);
#pragma unroll
            for (int j = 0; j < 8; j++) mma16816(sc[j], qa[1][c], bf[j]);
        }
#pragma unroll
        for (int c = 0; c < 4; c++) {
            u32 bf[8][2];
#pragma unroll
            for (int np = 0; np < 4; np++) {
                int row = np * 16 + (seg >> 1) * 8 + i8;
                int cc = c * 2 + (seg & 1);
                u32 r4[4];
                ldm4(r4, sb + 8192 + row * 128 + ((cc ^ (row & 7)) << 4));
                bf[np * 2][0] = r4[0]; bf[np * 2][1] = r4[1];
                bf[np * 2 + 1][0] = r4[2]; bf[np * 2 + 1][1] = r4[3];
            }
#pragma unroll
            for (int j = 0; j < 8; j++) mma16816(sc[j], qa[0][c], bf[j]);
        }

        const float* bias = (const float*)(smem + 3 * STAGE + s_cur * 256);
        float mx0 = -1e30f, mx1 = -1e30f;
#pragma unroll
        for (int j = 0; j < 8; j++) {
            int col = j * 8 + cp;
            float b0 = bias[col], b1 = bias[col + 1];
            sc[j][0] += b0; sc[j][1] += b1;
            sc[j][2] += b0; sc[j][3] += b1;
            mx0 = fmaxf(mx0, fmaxf(sc[j][0], sc[j][1]));
            mx1 = fmaxf(mx1, fmaxf(sc[j][2], sc[j][3]));
        }
        mx0 = fmaxf(mx0, __shfl_xor_sync(~0u, mx0, 1));
        mx0 = fmaxf(mx0, __shfl_xor_sync(~0u, mx0, 2));
        mx1 = fmaxf(mx1, __shfl_xor_sync(~0u, mx1, 1));
        mx1 = fmaxf(mx1, __shfl_xor_sync(~0u, mx1, 2));
        float nm0 = fmaxf(m0, mx0), nm1 = fmaxf(m1, mx1);
        float cr0 = __expf(m0 - nm0), cr1 = __expf(m1 - nm1);
        m0 = nm0; m1 = nm1;
        float sum0 = 0.f, sum1 = 0.f;
#pragma unroll
        for (int j = 0; j < 8; j++) {
            sc[j][0] = __expf(sc[j][0] - nm0);
            sc[j][1] = __expf(sc[j][1] - nm0);
            sc[j][2] = __expf(sc[j][2] - nm1);
            sc[j][3] = __expf(sc[j][3] - nm1);
            sum0 += sc[j][0] + sc[j][1];
            sum1 += sc[j][2] + sc[j][3];
        }
        sum0 += __shfl_xor_sync(~0u, sum0, 1);
        sum0 += __shfl_xor_sync(~0u, sum0, 2);
        sum1 += __shfl_xor_sync(~0u, sum1, 1);
        sum1 += __shfl_xor_sync(~0u, sum1, 2);
        l0 = l0 * cr0 + sum0;
        l1 = l1 * cr1 + sum1;
#pragma unroll
        for (int j = 0; j < 8; j++) {
            ctx[j][0] *= cr0; ctx[j][1] *= cr0;
            ctx[j][2] *= cr1; ctx[j][3] *= cr1;
        }

        u32 pa[4][4];
#pragma unroll
        for (int c = 0; c < 4; c++) {
            pa[c][0] = pack2(sc[2 * c][0], sc[2 * c][1]);
            pa[c][1] = pack2(sc[2 * c][2], sc[2 * c][3]);
            pa[c][2] = pack2(sc[2 * c + 1][0], sc[2 * c + 1][1]);
            pa[c][3] = pack2(sc[2 * c + 1][2], sc[2 * c + 1][3]);
        }

        // ctx += P @ V ; V tile stored (row=s, col=d); B-frags via ldmatrix.trans
#pragma unroll
        for (int c = 0; c < 4; c++) {
            u32 bv[8][2];
#pragma unroll
            for (int jp = 0; jp < 4; jp++) {
                int srow = c * 16 + (seg & 1) * 8 + i8;
                int cseg = jp * 2 + (seg >> 1);
                u32 r4[4];
                ldm4t(r4, sb + 16384 + srow * 128 + ((cseg ^ (srow & 7)) << 4));
                bv[2 * jp][0] = r4[0]; bv[2 * jp][1] = r4[1];
                bv[2 * jp + 1][0] = r4[2]; bv[2 * jp + 1][1] = r4[3];
            }
#pragma unroll
            for (int j = 0; j < 8; j++) mma16816(ctx[j], pa[c], bv[j]);
        }
        s_cur = (s_cur == 2) ? 0 : s_cur + 1;
        s_pre = (s_pre == 2) ? 0 : s_pre + 1;
    }

    const float inv0 = 1.f / l0, inv1 = 1.f / l1;
    const int mrow = t0 + w * 16 + r;
#pragma unroll
    for (int j = 0; j < 8; j++) {
        int col = h * 64 + j * 8 + cp;
        size_t a0 = ((size_t)(mrow * 8 + b)) * 1024 + col;
        *(u32*)(g_ch + a0) = pack2(ctx[j][0] * inv0, ctx[j][1] * inv0);
        size_t a1 = ((size_t)((mrow + 8) * 8 + b)) * 1024 + col;
        *(u32*)(g_ch + a1) = pack2(ctx[j][2] * inv1, ctx[j][3] * inv1);
    }
}

// ---------------- launch ----------------
extern "C" void kernel_launch(void* const* d_in, const int* in_sizes, int n_in,
                              void* d_out, int out_size) {
    const float* query = (const float*)d_in[0];
    const float* key = (const float*)d_in[1];
    const float* tgt = (const float*)d_in[2];
    const float* src = (const float*)d_in[3];
    const float* wq_f = (const float*)d_in[4];
    const float* wkv_f = (const float*)d_in[5];
    const float* wo_f = (const float*)d_in[6];
    const unsigned char* mask = (const unsigned char*)d_in[7];
    float* out = (float*)d_out;

    const int SM4 = 3 * 4 * 128 * 64;          // 96 KB (4-tile, ring-3)
    const int SM2 = 3 * 2 * 128 * 64;          // 48 KB (2-tile, ring-3)
    const int SMATT = 3 * 3 * 8192 + 768;      // 74.25 KB (ring-3 + bias)
    cudaFuncSetAttribute(attn_fused_k,
                         cudaFuncAttributeMaxDynamicSharedMemorySize, SMATT);
    cudaFuncSetAttribute(qkv_proj_k,
                         cudaFuncAttributeMaxDynamicSharedMemorySize, SM4);
    cudaFuncSetAttribute(gemmo_k,
                         cudaFuncAttributeMaxDynamicSharedMemorySize, SM2);

    // merged input-split + weight-build
    prep_k<<<24576, 256>>>(query, key, wq_f, wkv_f, wo_f, tgt, src);

    // q-proj (z=0), k-proj (z=1), v-proj (z=2) in ONE launch
    qkv_proj_k<<<dim3(8, 64, 3), 256, SM4>>>();

    // fused attention: scores(3-term) + mask + softmax + P@V -> ch (fp16)
    attn_fused_k<<<dim3(8, 128), 256, SMATT>>>(mask);

    // out = ch @ wo^T (single term), fp32 out
    gemmo_k<<<dim3(8, 64), 256, SM2>>>(out);
}

// round 12
// speedup vs baseline: 2.0021x; 1.0756x over previous
#include <cuda_runtime.h>
#include <cuda_fp16.h>
#include <cstdint>
#include <cstddef>

using u32 = uint32_t;
using u64 = uint64_t;
#define MTOT 8192

// ---------------- static scratch (no allocation) ----------------
__device__ __half g_xqh[MTOT * 1024], g_xql[MTOT * 1024];
__device__ __half g_xkh[MTOT * 1024], g_xkl[MTOT * 1024];
__device__ __half g_wqh[1024 * 1024], g_wql[1024 * 1024];
__device__ __half g_wkh[1024 * 1024], g_wkl[1024 * 1024];
__device__ __half g_wvh[1024 * 1024];
__device__ __half g_woh[1024 * 1024];
__device__ __half g_qh[MTOT * 1024], g_ql[MTOT * 1024];
__device__ __half g_kh[MTOT * 1024], g_kl[MTOT * 1024];
__device__ __half g_vh[MTOT * 1024];
__device__ __half g_ch[MTOT * 1024];

// ---------------- helpers ----------------
__device__ __forceinline__ u32 smem_u32(const void* p) {
    u32 a;
    asm("{ .reg .u64 t; cvta.to.shared.u64 t, %1; cvt.u32.u64 %0, t; }"
        : "=r"(a) : "l"(p));
    return a;
}
__device__ __forceinline__ void split2(float f0, float f1, u32& h, u32& l) {
    __half a = __float2half_rn(f0), b = __float2half_rn(f1);
    h = (u32)__half_as_ushort(a) | ((u32)__half_as_ushort(b) << 16);
    __half c = __float2half_rn(f0 - __half2float(a));
    __half d = __float2half_rn(f1 - __half2float(b));
    l = (u32)__half_as_ushort(c) | ((u32)__half_as_ushort(d) << 16);
}
__device__ __forceinline__ u32 pack2(float f0, float f1) {
    __half2 hh = __floats2half2_rn(f0, f1);
    return *reinterpret_cast<u32*>(&hh);
}
__device__ __forceinline__ void cpa16(u32 s, const void* g) {
    asm volatile("cp.async.cg.shared.global [%0], [%1], 16;"
                 :: "r"(s), "l"((u64)__cvta_generic_to_global(g)));
}
__device__ __forceinline__ void ldm4(u32* r, u32 addr) {
    asm volatile("ldmatrix.sync.aligned.m8n8.x4.shared.b16 {%0,%1,%2,%3}, [%4];"
                 : "=r"(r[0]), "=r"(r[1]), "=r"(r[2]), "=r"(r[3]) : "r"(addr));
}
__device__ __forceinline__ void ldm4t(u32* r, u32 addr) {
    asm volatile("ldmatrix.sync.aligned.m8n8.x4.trans.shared.b16 {%0,%1,%2,%3}, [%4];"
                 : "=r"(r[0]), "=r"(r[1]), "=r"(r[2]), "=r"(r[3]) : "r"(addr));
}
__device__ __forceinline__ void mma16816(float* d, const u32* a, const u32* b) {
    asm volatile(
        "mma.sync.aligned.m16n8k16.row.col.f32.f16.f16.f32 "
        "{%0,%1,%2,%3},{%4,%5,%6,%7},{%8,%9},{%0,%1,%2,%3};"
        : "+f"(d[0]), "+f"(d[1]), "+f"(d[2]), "+f"(d[3])
        : "r"(a[0]), "r"(a[1]), "r"(a[2]), "r"(a[3]), "r"(b[0]), "r"(b[1]));
}

// ---------------- merged prep: input split + weight build -------------------
__global__ __launch_bounds__(256) void prep_k(
    const float* __restrict__ q, const float* __restrict__ kk,
    const float* __restrict__ wq_f, const float* __restrict__ wkv_f,
    const float* __restrict__ wo_f, const float* __restrict__ tgt,
    const float* __restrict__ src) {
    const u32 bid = blockIdx.x;
    if (bid < 8192) {
        size_t idx = (size_t)bid * 256 + threadIdx.x;  // 0..2M-1
        size_t i = idx & ((1u << 20) - 1);
        const float* sp = (idx < (1u << 20)) ? q : kk;
        __half* dh = (idx < (1u << 20)) ? g_xqh : g_xkh;
        __half* dl = (idx < (1u << 20)) ? g_xql : g_xkl;
        size_t e = i * 8;
        float4 a = ((const float4*)(sp + e))[0];
        float4 b = ((const float4*)(sp + e))[1];
        float f[8] = {a.x, a.y, a.z, a.w, b.x, b.y, b.z, b.w};
        u32 ph[4], pl[4];
#pragma unroll
        for (int j = 0; j < 4; j++) split2(f[2 * j], f[2 * j + 1], ph[j], pl[j]);
        *(uint4*)(dh + e) = make_uint4(ph[0], ph[1], ph[2], ph[3]);
        *(uint4*)(dl + e) = make_uint4(pl[0], pl[1], pl[2], pl[3]);
    } else {
        u32 n = (bid - 8192) * 256 + threadIdx.x;  // 0..4M-1
        u32 seg = n >> 20, m = n & 1048575;
        const float* w;
        const float* f;
        __half *dh, *dl = nullptr;
        float scale = 1.f;
        if (seg == 0) { w = wq_f + (size_t)m * 8; f = tgt; dh = g_wqh; dl = g_wql; scale = 0.125f; }
        else if (seg == 1) { w = wkv_f + (size_t)m * 8; f = src; dh = g_wkh; dl = g_wkl; }
        else if (seg == 2) { w = wkv_f + ((size_t)1048576 + m) * 8; f = src; dh = g_wvh; }
        else { w = wo_f + (size_t)m * 8; f = tgt; dh = g_woh; }
        float acc = 0.f;
#pragma unroll
        for (int r = 0; r < 8; r++) acc += w[r] * f[r];
        acc *= scale;
        __half h = __float2half_rn(acc);
        dh[m] = h;
        if (dl) dl[m] = __float2half_rn(acc - __half2float(h));
    }
}

// ---------------- merged q/k/v projection (one launch) ----------------------
// z=0: q = xqh.wqh + xql.wqh + xqh.wql -> split qh/ql
// z=1: k = xkh.wkh + xkl.wkh + xkh.wkl -> split kh/kl
// z=2: v = xkh.wvh (single term)       -> plain vh (skips Al/Bl tiles + passes)
// BM=128, BN=128, BK=32. Stage: {Ah,Al,Bh,Bl} 32KB. Ring-3, depth-2 prefetch.
__global__ __launch_bounds__(256, 2) void qkv_proj_k() {
    constexpr int STAGE = 4 * 128 * 64;
    extern __shared__ char smem[];
    const u32 sbase = smem_u32(smem);

    const int tid = threadIdx.x, lane = tid & 31, wid = tid >> 5;
    const int m0 = blockIdx.y * 128, n0 = blockIdx.x * 128;
    const int z = blockIdx.z;
    const __half *Ah, *Al, *Bh, *Bl;
    __half *CH, *CL;
    if (z == 0) { Ah = g_xqh; Al = g_xql; Bh = g_wqh; Bl = g_wql; CH = g_qh; CL = g_ql; }
    else if (z == 1) { Ah = g_xkh; Al = g_xkl; Bh = g_wkh; Bl = g_wkl; CH = g_kh; CL = g_kl; }
    else { Ah = g_xkh; Al = g_xkh; Bh = g_wvh; Bl = g_wvh; CH = g_vh; CL = nullptr; }
    const bool full = (z < 2);
    const __half* tiles[4];
    tiles[0] = Ah + (size_t)m0 * 1024;
    tiles[1] = Al + (size_t)m0 * 1024;
    tiles[2] = Bh + (size_t)n0 * 1024;
    tiles[3] = Bl + (size_t)n0 * 1024;

    float acc[2][8][4];
#pragma unroll
    for (int a = 0; a < 2; a++)
#pragma unroll
        for (int b = 0; b < 8; b++)
#pragma unroll
            for (int c = 0; c < 4; c++) acc[a][b][c] = 0.f;

    auto load_stage = [&](int kc, int bufi) {
        const u32 sb = sbase + bufi * STAGE;
#pragma unroll
        for (int p = 0; p < 8; p++) {
            // passes 2,3 load Al (rows 128-255); passes 6,7 load Bl (rows 384+)
            if (!full && ((p >> 1) == 1 || (p >> 1) == 3)) continue;
            const int L = p * 256 + tid;
            const int row = L >> 2, c = L & 3;
            const __half* g = tiles[row >> 7] + (size_t)(row & 127) * 1024 +
                              kc * 32 + c * 8;
            cpa16(sb + row * 64 + ((c ^ ((row >> 1) & 3)) << 4), g);
        }
    };

    load_stage(0, 0);
    asm volatile("cp.async.commit_group;");
    load_stage(1, 1);
    asm volatile("cp.async.commit_group;");
    int s_cur = 0, s_pre = 2;
    const int wm = wid >> 1, wn = wid & 1;
    for (int kc = 0; kc < 32; kc++) {
        asm volatile("cp.async.wait_group 1;");
        __syncthreads();
        if (kc + 2 < 32) load_stage(kc + 2, s_pre);
        asm volatile("cp.async.commit_group;");
        const u32 sb = sbase + s_cur * STAGE;
        const int i8 = lane & 7, seg = lane >> 3;
#pragma unroll
        for (int kstep = 0; kstep < 2; kstep++) {
            u32 ra0[2][4], ra1[2][4];
#pragma unroll
            for (int mt = 0; mt < 2; mt++) {
                int row = wm * 32 + mt * 16 + (lane & 15);
                int c = kstep * 2 + (lane >> 4);
                u32 sw = (u32)((c ^ ((row >> 1) & 3)) << 4);
                ldm4(ra0[mt], sb + row * 64 + sw);
                if (full) ldm4(ra1[mt], sb + (row + 128) * 64 + sw);
            }
            u32 rb[8][2];
#pragma unroll
            for (int np = 0; np < 4; np++) {
                int row = 256 + wn * 64 + np * 16 + (seg >> 1) * 8 + i8;
                int c = kstep * 2 + (seg & 1);
                u32 r4[4];
                ldm4(r4, sb + row * 64 + ((c ^ ((row >> 1) & 3)) << 4));
                rb[np * 2][0] = r4[0]; rb[np * 2][1] = r4[1];
                rb[np * 2 + 1][0] = r4[2]; rb[np * 2 + 1][1] = r4[3];
            }
#pragma unroll
            for (int mt = 0; mt < 2; mt++)
#pragma unroll
                for (int nt = 0; nt < 8; nt++)
                    mma16816(acc[mt][nt], ra0[mt], rb[nt]);
            if (full) {
#pragma unroll
                for (int mt = 0; mt < 2; mt++)
#pragma unroll
                    for (int nt = 0; nt < 8; nt++)
                        mma16816(acc[mt][nt], ra1[mt], rb[nt]);
#pragma unroll
                for (int np = 0; np < 4; np++) {
                    int row = 384 + wn * 64 + np * 16 + (seg >> 1) * 8 + i8;
                    int c = kstep * 2 + (seg & 1);
                    u32 r4[4];
                    ldm4(r4, sb + row * 64 + ((c ^ ((row >> 1) & 3)) << 4));
                    rb[np * 2][0] = r4[0]; rb[np * 2][1] = r4[1];
                    rb[np * 2 + 1][0] = r4[2]; rb[np * 2 + 1][1] = r4[3];
                }
#pragma unroll
                for (int mt = 0; mt < 2; mt++)
#pragma unroll
                    for (int nt = 0; nt < 8; nt++)
                        mma16816(acc[mt][nt], ra0[mt], rb[nt]);
            }
        }
        s_cur = (s_cur == 2) ? 0 : s_cur + 1;
        s_pre = (s_pre == 2) ? 0 : s_pre + 1;
    }

    const int r0 = m0 + wm * 32 + (lane >> 2);
    const int cb = n0 + wn * 64 + (lane & 3) * 2;
#pragma unroll
    for (int mt = 0; mt < 2; mt++)
#pragma unroll
        for (int nt = 0; nt < 8; nt++) {
            int col = cb + nt * 8;
#pragma unroll
            for (int hh = 0; hh < 2; hh++) {
                int rr = r0 + mt * 16 + hh * 8;
                float f0 = acc[mt][nt][hh * 2], f1 = acc[mt][nt][hh * 2 + 1];
                size_t addr = (size_t)rr * 1024 + col;
                if (CL) {
                    u32 h, l;
                    split2(f0, f1, h, l);
                    *(u32*)(CH + addr) = h;
                    *(u32*)(CL + addr) = l;
                } else {
                    *(u32*)(CH + addr) = pack2(f0, f1);
                }
            }
        }
}

// ---------------- out-projection: out = ch @ woh^T (single term, fp32 out) --
__global__ __launch_bounds__(256, 2) void gemmo_k(float* __restrict__ CF) {
    constexpr int STAGE = 2 * 128 * 64;
    extern __shared__ char smem[];
    const u32 sbase = smem_u32(smem);

    const int tid = threadIdx.x, lane = tid & 31, wid = tid >> 5;
    const int m0 = blockIdx.y * 128, n0 = blockIdx.x * 128;
    const __half* tiles[2];
    tiles[0] = g_ch + (size_t)m0 * 1024;
    tiles[1] = g_woh + (size_t)n0 * 1024;

    float acc[2][8][4];
#pragma unroll
    for (int a = 0; a < 2; a++)
#pragma unroll
        for (int b = 0; b < 8; b++)
#pragma unroll
            for (int c = 0; c < 4; c++) acc[a][b][c] = 0.f;

    auto load_stage = [&](int kc, int bufi) {
        const u32 sb = sbase + bufi * STAGE;
#pragma unroll
        for (int p = 0; p < 4; p++) {
            const int L = p * 256 + tid;
            const int row = L >> 2, c = L & 3;
            const __half* g = tiles[row >> 7] + (size_t)(row & 127) * 1024 +
                              kc * 32 + c * 8;
            cpa16(sb + row * 64 + ((c ^ ((row >> 1) & 3)) << 4), g);
        }
    };

    load_stage(0, 0);
    asm volatile("cp.async.commit_group;");
    load_stage(1, 1);
    asm volatile("cp.async.commit_group;");
    int s_cur = 0, s_pre = 2;
    const int wm = wid >> 1, wn = wid & 1;
    for (int kc = 0; kc < 32; kc++) {
        asm volatile("cp.async.wait_group 1;");
        __syncthreads();
        if (kc + 2 < 32) load_stage(kc + 2, s_pre);
        asm volatile("cp.async.commit_group;");
        const u32 sb = sbase + s_cur * STAGE;
        const int i8 = lane & 7, seg = lane >> 3;
#pragma unroll
        for (int kstep = 0; kstep < 2; kstep++) {
            u32 ra0[2][4];
#pragma unroll
            for (int mt = 0; mt < 2; mt++) {
                int row = wm * 32 + mt * 16 + (lane & 15);
                int c = kstep * 2 + (lane >> 4);
                ldm4(ra0[mt], sb + row * 64 + ((c ^ ((row >> 1) & 3)) << 4));
            }
            u32 rb[8][2];
#pragma unroll
            for (int np = 0; np < 4; np++) {
                int row = 128 + wn * 64 + np * 16 + (seg >> 1) * 8 + i8;
                int c = kstep * 2 + (seg & 1);
                u32 r4[4];
                ldm4(r4, sb + row * 64 + ((c ^ ((row >> 1) & 3)) << 4));
                rb[np * 2][0] = r4[0]; rb[np * 2][1] = r4[1];
                rb[np * 2 + 1][0] = r4[2]; rb[np * 2 + 1][1] = r4[3];
            }
#pragma unroll
            for (int mt = 0; mt < 2; mt++)
#pragma unroll
                for (int nt = 0; nt < 8; nt++)
                    mma16816(acc[mt][nt], ra0[mt], rb[nt]);
        }
        s_cur = (s_cur == 2) ? 0 : s_cur + 1;
        s_pre = (s_pre == 2) ? 0 : s_pre + 1;
    }

    const int r0 = m0 + wm * 32 + (lane >> 2);
    const int cb = n0 + wn * 64 + (lane & 3) * 2;
#pragma unroll
    for (int mt = 0; mt < 2; mt++)
#pragma unroll
        for (int nt = 0; nt < 8; nt++) {
            int col = cb + nt * 8;
#pragma unroll
            for (int hh = 0; hh < 2; hh++) {
                int rr = r0 + mt * 16 + hh * 8;
                *(float2*)(CF + (size_t)rr * 1024 + col) =
                    make_float2(acc[mt][nt][hh * 2], acc[mt][nt][hh * 2 + 1]);
            }
        }
}

// ---------------- fused flash attention ----------------
// grid (T/128, B*H). 256 threads = 8 warps; warp owns 16 q rows.
// s-tiles of 64 keys: kh,kl,v (64x64 each, 24KB/stage), ring-3 stages,
// prefetch depth 2, one barrier per iteration. V fragments via ldmatrix.trans.
// 3-term split S, online softmax, ctx += P.V. 2 CTAs/SM (reg cap 128).
__global__ __launch_bounds__(256, 2) void attn_fused_k(const unsigned char* __restrict__ mask) {
    extern __shared__ char smem[];
    const u32 sbase = smem_u32(smem);
    const int tid = threadIdx.x, lane = tid & 31, w = tid >> 5;
    const int z = blockIdx.y, b = z >> 4, h = z & 15;
    const int t0 = blockIdx.x * 128;
    const int r = lane >> 2, cp = (lane & 3) * 2;
    constexpr int STAGE = 3 * 8192;   // kh + kl + v

    u32 qa[2][4][4];
    {
        const int mrow = t0 + w * 16 + r;
#pragma unroll
        for (int c = 0; c < 4; c++)
#pragma unroll
            for (int i = 0; i < 4; i++) {
                int mm = mrow + (i & 1) * 8;
                int col = h * 64 + c * 16 + cp + (i >> 1) * 8;
                size_t ad = ((size_t)(mm * 8 + b)) * 1024 + col;
                qa[0][c][i] = *(const u32*)(g_qh + ad);
                qa[1][c][i] = *(const u32*)(g_ql + ad);
            }
    }

    float ctx[8][4];
#pragma unroll
    for (int j = 0; j < 8; j++)
#pragma unroll
        for (int c = 0; c < 4; c++) ctx[j][c] = 0.f;
    float m0 = -1e30f, m1 = -1e30f, l0 = 0.f, l1 = 0.f;

    auto load_stage = [&](int it, int st) {
        const int s0 = it * 64;
        const u32 sb = sbase + st * STAGE;
#pragma unroll
        for (int p = 0; p < 6; p++) {
            int L = p * 256 + tid;
            int tile = L >> 9, rr = (L >> 3) & 63, c = L & 7;
            const __half* g;
            if (tile == 0)
                g = g_kh + ((size_t)((s0 + rr) * 8 + b)) * 1024 + h * 64 + c * 8;
            else if (tile == 1)
                g = g_kl + ((size_t)((s0 + rr) * 8 + b)) * 1024 + h * 64 + c * 8;
            else
                g = g_vh + ((size_t)((s0 + rr) * 8 + b)) * 1024 + h * 64 + c * 8;
            cpa16(sb + tile * 8192 + rr * 128 + ((c ^ (rr & 7)) << 4), g);
        }
        if (tid < 64)
            ((float*)(smem + 3 * STAGE + st * 256))[tid] =
                mask[b * 1024 + s0 + tid] ? -1e30f : 0.f;
    };

    load_stage(0, 0);
    asm volatile("cp.async.commit_group;");
    load_stage(1, 1);
    asm volatile("cp.async.commit_group;");
    int s_cur = 0, s_pre = 2;
    for (int it = 0; it < 16; it++) {
        asm volatile("cp.async.wait_group 1;");
        __syncthreads();
        if (it + 2 < 16) load_stage(it + 2, s_pre);
        asm volatile("cp.async.commit_group;");
        const u32 sb = sbase + s_cur * STAGE;

        float sc[8][4];
#pragma unroll
        for (int j = 0; j < 8; j++)
#pragma unroll
            for (int c = 0; c < 4; c++) sc[j][c] = 0.f;

        const int i8 = lane & 7, seg = lane >> 3;
#pragma unroll
        for (int c = 0; c < 4; c++) {
            u32 bf[8][2];
#pragma unroll
            for (int np = 0; np < 4; np++) {
                int row = np * 16 + (seg >> 1) * 8 + i8;
                int cc = c * 2 + (seg & 1);
                u32 r4[4];
                ldm4(r4, sb + row * 128 + ((cc ^ (row & 7)) << 4));
                bf[np * 2][0] = r4[0]; bf[np * 2][1] = r4[1];
                bf[np * 2 + 1][0] = r4[2]; bf[np * 2 + 1][1] = r4[3];
            }
#pragma unroll
            for (int j = 0; j < 8; j++) mma16816(sc[j], qa[0][c], bf[j]);
#pragma unroll
            for (int j = 0; j < 8; j++) mma16816(sc[j], qa[1][c], bf[j]);
        }
#pragma unroll
        for (int c = 0; c < 4; c++) {
            u32 bf[8][2];
#pragma unroll
            for (int np = 0; np < 4; np++) {
                int row = np * 16 + (seg >> 1) * 8 + i8;
                int cc = c * 2 + (seg & 1);
                u32 r4[4];
                ldm4(r4, sb + 8192 + row * 128 + ((cc ^ (row & 7)) << 4));
                bf[np * 2][0] = r4[0]; bf[np * 2][1] = r4[1];
                bf[np * 2 + 1][0] = r4[2]; bf[np * 2 + 1][1] = r4[3];
            }
#pragma unroll
            for (int j = 0; j < 8; j++) mma16816(sc[j], qa[0][c], bf[j]);
        }

        const float* bias = (const float*)(smem + 3 * STAGE + s_cur * 256);
        float mx0 = -1e30f, mx1 = -1e30f;
#pragma unroll
        for (int j = 0; j < 8; j++) {
            int col = j * 8 + cp;
            float b0 = bias[col], b1 = bias[col + 1];
            sc[j][0] += b0; sc[j][1] += b1;
            sc[j][2] += b0; sc[j][3] += b1;
            mx0 = fmaxf(mx0, fmaxf(sc[j][0], sc[j][1]));
            mx1 = fmaxf(mx1, fmaxf(sc[j][2], sc[j][3]));
        }
        mx0 = fmaxf(mx0, __shfl_xor_sync(~0u, mx0, 1));
        mx0 = fmaxf(mx0, __shfl_xor_sync(~0u, mx0, 2));
        mx1 = fmaxf(mx1, __shfl_xor_sync(~0u, mx1, 1));
        mx1 = fmaxf(mx1, __shfl_xor_sync(~0u, mx1, 2));
        float nm0 = fmaxf(m0, mx0), nm1 = fmaxf(m1, mx1);
        float cr0 = __expf(m0 - nm0), cr1 = __expf(m1 - nm1);
        m0 = nm0; m1 = nm1;
        float sum0 = 0.f, sum1 = 0.f;
#pragma unroll
        for (int j = 0; j < 8; j++) {
            sc[j][0] = __expf(sc[j][0] - nm0);
            sc[j][1] = __expf(sc[j][1] - nm0);
            sc[j][2] = __expf(sc[j][2] - nm1);
            sc[j][3] = __expf(sc[j][3] - nm1);
            sum0 += sc[j][0] + sc[j][1];
            sum1 += sc[j][2] + sc[j][3];
        }
        sum0 += __shfl_xor_sync(~0u, sum0, 1);
        sum0 += __shfl_xor_sync(~0u, sum0, 2);
        sum1 += __shfl_xor_sync(~0u, sum1, 1);
        sum1 += __shfl_xor_sync(~0u, sum1, 2);
        l0 = l0 * cr0 + sum0;
        l1 = l1 * cr1 + sum1;
#pragma unroll
        for (int j = 0; j < 8; j++) {
            ctx[j][0] *= cr0; ctx[j][1] *= cr0;
            ctx[j][2] *= cr1; ctx[j][3] *= cr1;
        }

        u32 pa[4][4];
#pragma unroll
        for (int c = 0; c < 4; c++) {
            pa[c][0] = pack2(sc[2 * c][0], sc[2 * c][1]);
            pa[c][1] = pack2(sc[2 * c][2], sc[2 * c][3]);
            pa[c][2] = pack2(sc[2 * c + 1][0], sc[2 * c + 1][1]);
            pa[c][3] = pack2(sc[2 * c + 1][2], sc[2 * c + 1][3]);
        }

        // ctx += P @ V ; V tile stored (row=s, col=d); B-frags via ldmatrix.trans
#pragma unroll
        for (int c = 0; c < 4; c++) {
            u32 bv[8][2];
#pragma unroll
            for (int jp = 0; jp < 4; jp++) {
                int srow = c * 16 + (seg & 1) * 8 + i8;
                int cseg = jp * 2 + (seg >> 1);
                u32 r4[4];
                ldm4t(r4, sb + 16384 + srow * 128 + ((cseg ^ (srow & 7)) << 4));
                bv[2 * jp][0] = r4[0]; bv[2 * jp][1] = r4[1];
                bv[2 * jp + 1][0] = r4[2]; bv[2 * jp + 1][1] = r4[3];
            }
#pragma unroll
            for (int j = 0; j < 8; j++) mma16816(ctx[j], pa[c], bv[j]);
        }
        s_cur = (s_cur == 2) ? 0 : s_cur + 1;
        s_pre = (s_pre == 2) ? 0 : s_pre + 1;
    }

    const float inv0 = 1.f / l0, inv1 = 1.f / l1;
    const int mrow = t0 + w * 16 + r;
#pragma unroll
    for (int j = 0; j < 8; j++) {
        int col = h * 64 + j * 8 + cp;
        size_t a0 = ((size_t)(mrow * 8 + b)) * 1024 + col;
        *(u32*)(g_ch + a0) = pack2(ctx[j][0] * inv0, ctx[j][1] * inv0);
        size_t a1 = ((size_t)((mrow + 8) * 8 + b)) * 1024 + col;
        *(u32*)(g_ch + a1) = pack2(ctx[j][2] * inv1, ctx[j][3] * inv1);
    }
}

// ---------------- launch ----------------
extern "C" void kernel_launch(void* const* d_in, const int* in_sizes, int n_in,
                              void* d_out, int out_size) {
    const float* query = (const float*)d_in[0];
    const float* key = (const float*)d_in[1];
    const float* tgt = (const float*)d_in[2];
    const float* src = (const float*)d_in[3];
    const float* wq_f = (const float*)d_in[4];
    const float* wkv_f = (const float*)d_in[5];
    const float* wo_f = (const float*)d_in[6];
    const unsigned char* mask = (const unsigned char*)d_in[7];
    float* out = (float*)d_out;

    const int SM4 = 3 * 4 * 128 * 64;          // 96 KB (4-tile, ring-3)
    const int SM2 = 3 * 2 * 128 * 64;          // 48 KB (2-tile, ring-3)
    const int SMATT = 3 * 3 * 8192 + 768;      // 74.25 KB (ring-3 + bias)
    cudaFuncSetAttribute(attn_fused_k,
                         cudaFuncAttributeMaxDynamicSharedMemorySize, SMATT);
    cudaFuncSetAttribute(qkv_proj_k,
                         cudaFuncAttributeMaxDynamicSharedMemorySize, SM4);
    cudaFuncSetAttribute(gemmo_k,
                         cudaFuncAttributeMaxDynamicSharedMemorySize, SM2);

    // merged input-split + weight-build
    prep_k<<<24576, 256>>>(query, key, wq_f, wkv_f, wo_f, tgt, src);

    // q-proj (z=0), k-proj (z=1), v-proj (z=2, single-term) in ONE launch
    qkv_proj_k<<<dim3(8, 64, 3), 256, SM4>>>();

    // fused attention: scores(3-term) + mask + softmax + P@V -> ch (fp16)
    attn_fused_k<<<dim3(8, 128), 256, SMATT>>>(mask);

    // out = ch @ wo^T (single term), fp32 out
    gemmo_k<<<dim3(8, 64), 256, SM2>>>(out);
}

// round 13
// speedup vs baseline: 2.0719x; 1.0349x over previous
#include <cuda_runtime.h>
#include <cuda_fp16.h>
#include <cstdint>
#include <cstddef>

using u32 = uint32_t;
using u64 = uint64_t;
#define MTOT 8192

// ---------------- static scratch (no allocation) ----------------
__device__ __half g_xqh[MTOT * 1024], g_xql[MTOT * 1024];
__device__ __half g_xkh[MTOT * 1024], g_xkl[MTOT * 1024];
__device__ __half g_wqh[1024 * 1024], g_wql[1024 * 1024];
__device__ __half g_wkh[1024 * 1024], g_wkl[1024 * 1024];
__device__ __half g_wvh[1024 * 1024];
__device__ __half g_woh[1024 * 1024];
__device__ __half g_qh[MTOT * 1024], g_qs[MTOT * 1024];
__device__ __half g_kh[MTOT * 1024], g_ks[MTOT * 1024];
__device__ __half g_vh[MTOT * 1024];
__device__ __half g_ch[MTOT * 1024];

// ---------------- helpers ----------------
__device__ __forceinline__ u32 smem_u32(const void* p) {
    u32 a;
    asm("{ .reg .u64 t; cvta.to.shared.u64 t, %1; cvt.u32.u64 %0, t; }"
        : "=r"(a) : "l"(p));
    return a;
}
// exact hi/lo split (inputs & weights)
__device__ __forceinline__ void split2(float f0, float f1, u32& h, u32& l) {
    __half a = __float2half_rn(f0), b = __float2half_rn(f1);
    h = (u32)__half_as_ushort(a) | ((u32)__half_as_ushort(b) << 16);
    __half c = __float2half_rn(f0 - __half2float(a));
    __half d = __float2half_rn(f1 - __half2float(b));
    l = (u32)__half_as_ushort(c) | ((u32)__half_as_ushort(d) << 16);
}
// alpha-combined split for q/k: s = fp16(f - (1-alpha)*hi), alpha = 1/32
__device__ __forceinline__ void splitA(float f0, float f1, u32& h, u32& s) {
    __half a = __float2half_rn(f0), b = __float2half_rn(f1);
    h = (u32)__half_as_ushort(a) | ((u32)__half_as_ushort(b) << 16);
    __half c = __float2half_rn(f0 - 0.96875f * __half2float(a));
    __half d = __float2half_rn(f1 - 0.96875f * __half2float(b));
    s = (u32)__half_as_ushort(c) | ((u32)__half_as_ushort(d) << 16);
}
__device__ __forceinline__ u32 pack2(float f0, float f1) {
    __half2 hh = __floats2half2_rn(f0, f1);
    return *reinterpret_cast<u32*>(&hh);
}
__device__ __forceinline__ void cpa16(u32 s, const void* g) {
    asm volatile("cp.async.cg.shared.global [%0], [%1], 16;"
                 :: "r"(s), "l"((u64)__cvta_generic_to_global(g)));
}
__device__ __forceinline__ void ldm4(u32* r, u32 addr) {
    asm volatile("ldmatrix.sync.aligned.m8n8.x4.shared.b16 {%0,%1,%2,%3}, [%4];"
                 : "=r"(r[0]), "=r"(r[1]), "=r"(r[2]), "=r"(r[3]) : "r"(addr));
}
__device__ __forceinline__ void ldm4t(u32* r, u32 addr) {
    asm volatile("ldmatrix.sync.aligned.m8n8.x4.trans.shared.b16 {%0,%1,%2,%3}, [%4];"
                 : "=r"(r[0]), "=r"(r[1]), "=r"(r[2]), "=r"(r[3]) : "r"(addr));
}
__device__ __forceinline__ void mma16816(float* d, const u32* a, const u32* b) {
    asm volatile(
        "mma.sync.aligned.m16n8k16.row.col.f32.f16.f16.f32 "
        "{%0,%1,%2,%3},{%4,%5,%6,%7},{%8,%9},{%0,%1,%2,%3};"
        : "+f"(d[0]), "+f"(d[1]), "+f"(d[2]), "+f"(d[3])
        : "r"(a[0]), "r"(a[1]), "r"(a[2]), "r"(a[3]), "r"(b[0]), "r"(b[1]));
}

// ---------------- merged prep: input split + weight build -------------------
__global__ __launch_bounds__(256) void prep_k(
    const float* __restrict__ q, const float* __restrict__ kk,
    const float* __restrict__ wq_f, const float* __restrict__ wkv_f,
    const float* __restrict__ wo_f, const float* __restrict__ tgt,
    const float* __restrict__ src) {
    const u32 bid = blockIdx.x;
    if (bid < 8192) {
        size_t idx = (size_t)bid * 256 + threadIdx.x;  // 0..2M-1
        size_t i = idx & ((1u << 20) - 1);
        const float* sp = (idx < (1u << 20)) ? q : kk;
        __half* dh = (idx < (1u << 20)) ? g_xqh : g_xkh;
        __half* dl = (idx < (1u << 20)) ? g_xql : g_xkl;
        size_t e = i * 8;
        float4 a = ((const float4*)(sp + e))[0];
        float4 b = ((const float4*)(sp + e))[1];
        float f[8] = {a.x, a.y, a.z, a.w, b.x, b.y, b.z, b.w};
        u32 ph[4], pl[4];
#pragma unroll
        for (int j = 0; j < 4; j++) split2(f[2 * j], f[2 * j + 1], ph[j], pl[j]);
        *(uint4*)(dh + e) = make_uint4(ph[0], ph[1], ph[2], ph[3]);
        *(uint4*)(dl + e) = make_uint4(pl[0], pl[1], pl[2], pl[3]);
    } else {
        u32 n = (bid - 8192) * 256 + threadIdx.x;  // 0..4M-1
        u32 seg = n >> 20, m = n & 1048575;
        const float* w;
        const float* f;
        __half *dh, *dl = nullptr;
        float scale = 1.f;
        if (seg == 0) {
            w = wq_f + (size_t)m * 8; f = tgt; dh = g_wqh; dl = g_wql;
            scale = 0.125f * 1.44269504088896f;   // fold log2(e): exp2 softmax
        }
        else if (seg == 1) { w = wkv_f + (size_t)m * 8; f = src; dh = g_wkh; dl = g_wkl; }
        else if (seg == 2) { w = wkv_f + ((size_t)1048576 + m) * 8; f = src; dh = g_wvh; }
        else { w = wo_f + (size_t)m * 8; f = tgt; dh = g_woh; }
        float acc = 0.f;
#pragma unroll
        for (int r = 0; r < 8; r++) acc += w[r] * f[r];
        acc *= scale;
        __half h = __float2half_rn(acc);
        dh[m] = h;
        if (dl) dl[m] = __float2half_rn(acc - __half2float(h));
    }
}

// ---------------- merged q/k/v projection (one launch) ----------------------
// z=0: q (3-term) -> qh + qs (alpha-combined split)
// z=1: k (3-term) -> kh + ks
// z=2: v = xkh.wvh (single term) -> plain vh
__global__ __launch_bounds__(256, 2) void qkv_proj_k() {
    constexpr int STAGE = 4 * 128 * 64;
    extern __shared__ char smem[];
    const u32 sbase = smem_u32(smem);

    const int tid = threadIdx.x, lane = tid & 31, wid = tid >> 5;
    const int m0 = blockIdx.y * 128, n0 = blockIdx.x * 128;
    const int z = blockIdx.z;
    const __half *Ah, *Al, *Bh, *Bl;
    __half *CH, *CL;
    if (z == 0) { Ah = g_xqh; Al = g_xql; Bh = g_wqh; Bl = g_wql; CH = g_qh; CL = g_qs; }
    else if (z == 1) { Ah = g_xkh; Al = g_xkl; Bh = g_wkh; Bl = g_wkl; CH = g_kh; CL = g_ks; }
    else { Ah = g_xkh; Al = g_xkh; Bh = g_wvh; Bl = g_wvh; CH = g_vh; CL = nullptr; }
    const bool full = (z < 2);
    const __half* tiles[4];
    tiles[0] = Ah + (size_t)m0 * 1024;
    tiles[1] = Al + (size_t)m0 * 1024;
    tiles[2] = Bh + (size_t)n0 * 1024;
    tiles[3] = Bl + (size_t)n0 * 1024;

    float acc[2][8][4];
#pragma unroll
    for (int a = 0; a < 2; a++)
#pragma unroll
        for (int b = 0; b < 8; b++)
#pragma unroll
            for (int c = 0; c < 4; c++) acc[a][b][c] = 0.f;

    auto load_stage = [&](int kc, int bufi) {
        const u32 sb = sbase + bufi * STAGE;
#pragma unroll
        for (int p = 0; p < 8; p++) {
            if (!full && ((p >> 1) == 1 || (p >> 1) == 3)) continue;
            const int L = p * 256 + tid;
            const int row = L >> 2, c = L & 3;
            const __half* g = tiles[row >> 7] + (size_t)(row & 127) * 1024 +
                              kc * 32 + c * 8;
            cpa16(sb + row * 64 + ((c ^ ((row >> 1) & 3)) << 4), g);
        }
    };

    load_stage(0, 0);
    asm volatile("cp.async.commit_group;");
    load_stage(1, 1);
    asm volatile("cp.async.commit_group;");
    int s_cur = 0, s_pre = 2;
    const int wm = wid >> 1, wn = wid & 1;
    for (int kc = 0; kc < 32; kc++) {
        asm volatile("cp.async.wait_group 1;");
        __syncthreads();
        if (kc + 2 < 32) load_stage(kc + 2, s_pre);
        asm volatile("cp.async.commit_group;");
        const u32 sb = sbase + s_cur * STAGE;
        const int i8 = lane & 7, seg = lane >> 3;
#pragma unroll
        for (int kstep = 0; kstep < 2; kstep++) {
            u32 ra0[2][4], ra1[2][4];
#pragma unroll
            for (int mt = 0; mt < 2; mt++) {
                int row = wm * 32 + mt * 16 + (lane & 15);
                int c = kstep * 2 + (lane >> 4);
                u32 sw = (u32)((c ^ ((row >> 1) & 3)) << 4);
                ldm4(ra0[mt], sb + row * 64 + sw);
                if (full) ldm4(ra1[mt], sb + (row + 128) * 64 + sw);
            }
            u32 rb[8][2];
#pragma unroll
            for (int np = 0; np < 4; np++) {
                int row = 256 + wn * 64 + np * 16 + (seg >> 1) * 8 + i8;
                int c = kstep * 2 + (seg & 1);
                u32 r4[4];
                ldm4(r4, sb + row * 64 + ((c ^ ((row >> 1) & 3)) << 4));
                rb[np * 2][0] = r4[0]; rb[np * 2][1] = r4[1];
                rb[np * 2 + 1][0] = r4[2]; rb[np * 2 + 1][1] = r4[3];
            }
#pragma unroll
            for (int mt = 0; mt < 2; mt++)
#pragma unroll
                for (int nt = 0; nt < 8; nt++)
                    mma16816(acc[mt][nt], ra0[mt], rb[nt]);
            if (full) {
#pragma unroll
                for (int mt = 0; mt < 2; mt++)
#pragma unroll
                    for (int nt = 0; nt < 8; nt++)
                        mma16816(acc[mt][nt], ra1[mt], rb[nt]);
#pragma unroll
                for (int np = 0; np < 4; np++) {
                    int row = 384 + wn * 64 + np * 16 + (seg >> 1) * 8 + i8;
                    int c = kstep * 2 + (seg & 1);
                    u32 r4[4];
                    ldm4(r4, sb + row * 64 + ((c ^ ((row >> 1) & 3)) << 4));
                    rb[np * 2][0] = r4[0]; rb[np * 2][1] = r4[1];
                    rb[np * 2 + 1][0] = r4[2]; rb[np * 2 + 1][1] = r4[3];
                }
#pragma unroll
                for (int mt = 0; mt < 2; mt++)
#pragma unroll
                    for (int nt = 0; nt < 8; nt++)
                        mma16816(acc[mt][nt], ra0[mt], rb[nt]);
            }
        }
        s_cur = (s_cur == 2) ? 0 : s_cur + 1;
        s_pre = (s_pre == 2) ? 0 : s_pre + 1;
    }

    const int r0 = m0 + wm * 32 + (lane >> 2);
    const int cb = n0 + wn * 64 + (lane & 3) * 2;
#pragma unroll
    for (int mt = 0; mt < 2; mt++)
#pragma unroll
        for (int nt = 0; nt < 8; nt++) {
            int col = cb + nt * 8;
#pragma unroll
            for (int hh = 0; hh < 2; hh++) {
                int rr = r0 + mt * 16 + hh * 8;
                float f0 = acc[mt][nt][hh * 2], f1 = acc[mt][nt][hh * 2 + 1];
                size_t addr = (size_t)rr * 1024 + col;
                if (CL) {
                    u32 h, s;
                    splitA(f0, f1, h, s);
                    *(u32*)(CH + addr) = h;
                    *(u32*)(CL + addr) = s;
                } else {
                    *(u32*)(CH + addr) = pack2(f0, f1);
                }
            }
        }
}

// ---------------- out-projection: out = ch @ woh^T (single term, fp32 out) --
__global__ __launch_bounds__(256, 2) void gemmo_k(float* __restrict__ CF) {
    constexpr int STAGE = 2 * 128 * 64;
    extern __shared__ char smem[];
    const u32 sbase = smem_u32(smem);

    const int tid = threadIdx.x, lane = tid & 31, wid = tid >> 5;
    const int m0 = blockIdx.y * 128, n0 = blockIdx.x * 128;
    const __half* tiles[2];
    tiles[0] = g_ch + (size_t)m0 * 1024;
    tiles[1] = g_woh + (size_t)n0 * 1024;

    float acc[2][8][4];
#pragma unroll
    for (int a = 0; a < 2; a++)
#pragma unroll
        for (int b = 0; b < 8; b++)
#pragma unroll
            for (int c = 0; c < 4; c++) acc[a][b][c] = 0.f;

    auto load_stage = [&](int kc, int bufi) {
        const u32 sb = sbase + bufi * STAGE;
#pragma unroll
        for (int p = 0; p < 4; p++) {
            const int L = p * 256 + tid;
            const int row = L >> 2, c = L & 3;
            const __half* g = tiles[row >> 7] + (size_t)(row & 127) * 1024 +
                              kc * 32 + c * 8;
            cpa16(sb + row * 64 + ((c ^ ((row >> 1) & 3)) << 4), g);
        }
    };

    load_stage(0, 0);
    asm volatile("cp.async.commit_group;");
    load_stage(1, 1);
    asm volatile("cp.async.commit_group;");
    int s_cur = 0, s_pre = 2;
    const int wm = wid >> 1, wn = wid & 1;
    for (int kc = 0; kc < 32; kc++) {
        asm volatile("cp.async.wait_group 1;");
        __syncthreads();
        if (kc + 2 < 32) load_stage(kc + 2, s_pre);
        asm volatile("cp.async.commit_group;");
        const u32 sb = sbase + s_cur * STAGE;
        const int i8 = lane & 7, seg = lane >> 3;
#pragma unroll
        for (int kstep = 0; kstep < 2; kstep++) {
            u32 ra0[2][4];
#pragma unroll
            for (int mt = 0; mt < 2; mt++) {
                int row = wm * 32 + mt * 16 + (lane & 15);
                int c = kstep * 2 + (lane >> 4);
                ldm4(ra0[mt], sb + row * 64 + ((c ^ ((row >> 1) & 3)) << 4));
            }
            u32 rb[8][2];
#pragma unroll
            for (int np = 0; np < 4; np++) {
                int row = 128 + wn * 64 + np * 16 + (seg >> 1) * 8 + i8;
                int c = kstep * 2 + (seg & 1);
                u32 r4[4];
                ldm4(r4, sb + row * 64 + ((c ^ ((row >> 1) & 3)) << 4));
                rb[np * 2][0] = r4[0]; rb[np * 2][1] = r4[1];
                rb[np * 2 + 1][0] = r4[2]; rb[np * 2 + 1][1] = r4[3];
            }
#pragma unroll
            for (int mt = 0; mt < 2; mt++)
#pragma unroll
                for (int nt = 0; nt < 8; nt++)
                    mma16816(acc[mt][nt], ra0[mt], rb[nt]);
        }
        s_cur = (s_cur == 2) ? 0 : s_cur + 1;
        s_pre = (s_pre == 2) ? 0 : s_pre + 1;
    }

    const int r0 = m0 + wm * 32 + (lane >> 2);
    const int cb = n0 + wn * 64 + (lane & 3) * 2;
#pragma unroll
    for (int mt = 0; mt < 2; mt++)
#pragma unroll
        for (int nt = 0; nt < 8; nt++) {
            int col = cb + nt * 8;
#pragma unroll
            for (int hh = 0; hh < 2; hh++) {
                int rr = r0 + mt * 16 + hh * 8;
                *(float2*)(CF + (size_t)rr * 1024 + col) =
                    make_float2(acc[mt][nt][hh * 2], acc[mt][nt][hh * 2 + 1]);
            }
        }
}

// ---------------- fused flash attention ----------------
// S via alpha-combined split: sc = 0.96875*(qh.kh) + 32*(qs.ks)  (2 mma terms)
// Tiles: kh, ks, v (64x64 each). Ring-3, depth-2 prefetch, one barrier/iter.
// exp2-domain softmax (log2e folded into wq). ctx += P.V (trans-ldmatrix V).
__global__ __launch_bounds__(256, 2) void attn_fused_k(const unsigned char* __restrict__ mask) {
    extern __shared__ char smem[];
    const u32 sbase = smem_u32(smem);
    const int tid = threadIdx.x, lane = tid & 31, w = tid >> 5;
    const int z = blockIdx.y, b = z >> 4, h = z & 15;
    const int t0 = blockIdx.x * 128;
    const int r = lane >> 2, cp = (lane & 3) * 2;
    constexpr int STAGE = 3 * 8192;   // kh + ks + v

    u32 qa[2][4][4];
    {
        const int mrow = t0 + w * 16 + r;
#pragma unroll
        for (int c = 0; c < 4; c++)
#pragma unroll
            for (int i = 0; i < 4; i++) {
                int mm = mrow + (i & 1) * 8;
                int col = h * 64 + c * 16 + cp + (i >> 1) * 8;
                size_t ad = ((size_t)(mm * 8 + b)) * 1024 + col;
                qa[0][c][i] = *(const u32*)(g_qh + ad);
                qa[1][c][i] = *(const u32*)(g_qs + ad);
            }
    }

    float ctx[8][4];
#pragma unroll
    for (int j = 0; j < 8; j++)
#pragma unroll
        for (int c = 0; c < 4; c++) ctx[j][c] = 0.f;
    float m0 = -1e30f, m1 = -1e30f, l0 = 0.f, l1 = 0.f;

    auto load_stage = [&](int it, int st) {
        const int s0 = it * 64;
        const u32 sb = sbase + st * STAGE;
#pragma unroll
        for (int p = 0; p < 6; p++) {
            int L = p * 256 + tid;
            int tile = L >> 9, rr = (L >> 3) & 63, c = L & 7;
            const __half* g;
            if (tile == 0)
                g = g_kh + ((size_t)((s0 + rr) * 8 + b)) * 1024 + h * 64 + c * 8;
            else if (tile == 1)
                g = g_ks + ((size_t)((s0 + rr) * 8 + b)) * 1024 + h * 64 + c * 8;
            else
                g = g_vh + ((size_t)((s0 + rr) * 8 + b)) * 1024 + h * 64 + c * 8;
            cpa16(sb + tile * 8192 + rr * 128 + ((c ^ (rr & 7)) << 4), g);
        }
        if (tid < 64)
            ((float*)(smem + 3 * STAGE + st * 256))[tid] =
                mask[b * 1024 + s0 + tid] ? -1e30f : 0.f;
    };

    load_stage(0, 0);
    asm volatile("cp.async.commit_group;");
    load_stage(1, 1);
    asm volatile("cp.async.commit_group;");
    int s_cur = 0, s_pre = 2;
    for (int it = 0; it < 16; it++) {
        asm volatile("cp.async.wait_group 1;");
        __syncthreads();
        if (it + 2 < 16) load_stage(it + 2, s_pre);
        asm volatile("cp.async.commit_group;");
        const u32 sb = sbase + s_cur * STAGE;

        float sc[8][4];
        const int i8 = lane & 7, seg = lane >> 3;
        // S in two 32-key halves: main (qh.kh) + corr (qs.ks), combined.
#pragma unroll
        for (int hf = 0; hf < 2; hf++) {
            float mainA[4][4], corrA[4][4];
#pragma unroll
            for (int j = 0; j < 4; j++)
#pragma unroll
                for (int x = 0; x < 4; x++) { mainA[j][x] = 0.f; corrA[j][x] = 0.f; }
#pragma unroll
            for (int c = 0; c < 4; c++) {
                u32 bf[4][2];
#pragma unroll
                for (int np = 0; np < 2; np++) {
                    int row = hf * 32 + np * 16 + (seg >> 1) * 8 + i8;
                    int cc = c * 2 + (seg & 1);
                    u32 r4[4];
                    ldm4(r4, sb + row * 128 + ((cc ^ (row & 7)) << 4));
                    bf[np * 2][0] = r4[0]; bf[np * 2][1] = r4[1];
                    bf[np * 2 + 1][0] = r4[2]; bf[np * 2 + 1][1] = r4[3];
                }
#pragma unroll
                for (int j = 0; j < 4; j++) mma16816(mainA[j], qa[0][c], bf[j]);
#pragma unroll
                for (int np = 0; np < 2; np++) {
                    int row = hf * 32 + np * 16 + (seg >> 1) * 8 + i8;
                    int cc = c * 2 + (seg & 1);
                    u32 r4[4];
                    ldm4(r4, sb + 8192 + row * 128 + ((cc ^ (row & 7)) << 4));
                    bf[np * 2][0] = r4[0]; bf[np * 2][1] = r4[1];
                    bf[np * 2 + 1][0] = r4[2]; bf[np * 2 + 1][1] = r4[3];
                }
#pragma unroll
                for (int j = 0; j < 4; j++) mma16816(corrA[j], qa[1][c], bf[j]);
            }
#pragma unroll
            for (int j = 0; j < 4; j++)
#pragma unroll
                for (int x = 0; x < 4; x++)
                    sc[hf * 4 + j][x] = 0.96875f * mainA[j][x] + 32.f * corrA[j][x];
        }

        const float* bias = (const float*)(smem + 3 * STAGE + s_cur * 256);
        float mx0 = -1e30f, mx1 = -1e30f;
#pragma unroll
        for (int j = 0; j < 8; j++) {
            int col = j * 8 + cp;
            float b0 = bias[col], b1 = bias[col + 1];
            sc[j][0] += b0; sc[j][1] += b1;
            sc[j][2] += b0; sc[j][3] += b1;
            mx0 = fmaxf(mx0, fmaxf(sc[j][0], sc[j][1]));
            mx1 = fmaxf(mx1, fmaxf(sc[j][2], sc[j][3]));
        }
        mx0 = fmaxf(mx0, __shfl_xor_sync(~0u, mx0, 1));
        mx0 = fmaxf(mx0, __shfl_xor_sync(~0u, mx0, 2));
        mx1 = fmaxf(mx1, __shfl_xor_sync(~0u, mx1, 1));
        mx1 = fmaxf(mx1, __shfl_xor_sync(~0u, mx1, 2));
        float nm0 = fmaxf(m0, mx0), nm1 = fmaxf(m1, mx1);
        float cr0 = exp2f(m0 - nm0), cr1 = exp2f(m1 - nm1);
        m0 = nm0; m1 = nm1;
        float sum0 = 0.f, sum1 = 0.f;
#pragma unroll
        for (int j = 0; j < 8; j++) {
            sc[j][0] = exp2f(sc[j][0] - nm0);
            sc[j][1] = exp2f(sc[j][1] - nm0);
            sc[j][2] = exp2f(sc[j][2] - nm1);
            sc[j][3] = exp2f(sc[j][3] - nm1);
            sum0 += sc[j][0] + sc[j][1];
            sum1 += sc[j][2] + sc[j][3];
        }
        sum0 += __shfl_xor_sync(~0u, sum0, 1);
        sum0 += __shfl_xor_sync(~0u, sum0, 2);
        sum1 += __shfl_xor_sync(~0u, sum1, 1);
        sum1 += __shfl_xor_sync(~0u, sum1, 2);
        l0 = l0 * cr0 + sum0;
        l1 = l1 * cr1 + sum1;
#pragma unroll
        for (int j = 0; j < 8; j++) {
            ctx[j][0] *= cr0; ctx[j][1] *= cr0;
            ctx[j][2] *= cr1; ctx[j][3] *= cr1;
        }

        u32 pa[4][4];
#pragma unroll
        for (int c = 0; c < 4; c++) {
            pa[c][0] = pack2(sc[2 * c][0], sc[2 * c][1]);
            pa[c][1] = pack2(sc[2 * c][2], sc[2 * c][3]);
            pa[c][2] = pack2(sc[2 * c + 1][0], sc[2 * c + 1][1]);
            pa[c][3] = pack2(sc[2 * c + 1][2], sc[2 * c + 1][3]);
        }

        // ctx += P @ V ; V tile (row=s, col=d); B-frags via ldmatrix.trans
#pragma unroll
        for (int c = 0; c < 4; c++) {
            u32 bv[8][2];
#pragma unroll
            for (int jp = 0; jp < 4; jp++) {
                int srow = c * 16 + (seg & 1) * 8 + i8;
                int cseg = jp * 2 + (seg >> 1);
                u32 r4[4];
                ldm4t(r4, sb + 16384 + srow * 128 + ((cseg ^ (srow & 7)) << 4));
                bv[2 * jp][0] = r4[0]; bv[2 * jp][1] = r4[1];
                bv[2 * jp + 1][0] = r4[2]; bv[2 * jp + 1][1] = r4[3];
            }
#pragma unroll
            for (int j = 0; j < 8; j++) mma16816(ctx[j], pa[c], bv[j]);
        }
        s_cur = (s_cur == 2) ? 0 : s_cur + 1;
        s_pre = (s_pre == 2) ? 0 : s_pre + 1;
    }

    const float inv0 = 1.f / l0, inv1 = 1.f / l1;
    const int mrow = t0 + w * 16 + r;
#pragma unroll
    for (int j = 0; j < 8; j++) {
        int col = h * 64 + j * 8 + cp;
        size_t a0 = ((size_t)(mrow * 8 + b)) * 1024 + col;
        *(u32*)(g_ch + a0) = pack2(ctx[j][0] * inv0, ctx[j][1] * inv0);
        size_t a1 = ((size_t)((mrow + 8) * 8 + b)) * 1024 + col;
        *(u32*)(g_ch + a1) = pack2(ctx[j][2] * inv1, ctx[j][3] * inv1);
    }
}

// ---------------- launch ----------------
extern "C" void kernel_launch(void* const* d_in, const int* in_sizes, int n_in,
                              void* d_out, int out_size) {
    const float* query = (const float*)d_in[0];
    const float* key = (const float*)d_in[1];
    const float* tgt = (const float*)d_in[2];
    const float* src = (const float*)d_in[3];
    const float* wq_f = (const float*)d_in[4];
    const float* wkv_f = (const float*)d_in[5];
    const float* wo_f = (const float*)d_in[6];
    const unsigned char* mask = (const unsigned char*)d_in[7];
    float* out = (float*)d_out;

    const int SM4 = 3 * 4 * 128 * 64;          // 96 KB (4-tile, ring-3)
    const int SM2 = 3 * 2 * 128 * 64;          // 48 KB (2-tile, ring-3)
    const int SMATT = 3 * 3 * 8192 + 768;      // 74.25 KB (ring-3 + bias)
    cudaFuncSetAttribute(attn_fused_k,
                         cudaFuncAttributeMaxDynamicSharedMemorySize, SMATT);
    cudaFuncSetAttribute(qkv_proj_k,
                         cudaFuncAttributeMaxDynamicSharedMemorySize, SM4);
    cudaFuncSetAttribute(gemmo_k,
                         cudaFuncAttributeMaxDynamicSharedMemorySize, SM2);

    // merged input-split + weight-build (wq carries 0.125*log2e)
    prep_k<<<24576, 256>>>(query, key, wq_f, wkv_f, wo_f, tgt, src);

    // q-proj (z=0), k-proj (z=1), v-proj (z=2, single-term) in ONE launch
    qkv_proj_k<<<dim3(8, 64, 3), 256, SM4>>>();

    // fused attention: alpha-combined S + mask + exp2 softmax + P@V -> ch
    attn_fused_k<<<dim3(8, 128), 256, SMATT>>>(mask);

    // out = ch @ wo^T (single term), fp32 out
    gemmo_k<<<dim3(8, 64), 256, SM2>>>(out);
}

// round 14
// speedup vs baseline: 2.2851x; 1.1029x over previous
#include <cuda_runtime.h>
#include <cuda_fp16.h>
#include <cstdint>
#include <cstddef>

using u32 = uint32_t;
using u64 = uint64_t;
#define MTOT 8192

// ---------------- static scratch (no allocation) ----------------
__device__ __half g_xqh[MTOT * 1024], g_xqs[MTOT * 1024];
__device__ __half g_xkh[MTOT * 1024], g_xks[MTOT * 1024];
__device__ __half g_wqh[1024 * 1024], g_wqs[1024 * 1024];   // ws32 form
__device__ __half g_wkh[1024 * 1024], g_wks[1024 * 1024];   // ws32 form
__device__ __half g_wvh[1024 * 1024];
__device__ __half g_woh[1024 * 1024];
__device__ __half g_qh[MTOT * 1024], g_qs[MTOT * 1024];
__device__ __half g_kh[MTOT * 1024], g_ks[MTOT * 1024];
__device__ __half g_vh[MTOT * 1024];
__device__ __half g_ch[MTOT * 1024];

// ---------------- helpers ----------------
__device__ __forceinline__ u32 smem_u32(const void* p) {
    u32 a;
    asm("{ .reg .u64 t; cvta.to.shared.u64 t, %1; cvt.u32.u64 %0, t; }"
        : "=r"(a) : "l"(p));
    return a;
}
// alpha-combined split: s = fp16(f - (31/32)*hi)  (= hi/32 + lo)
__device__ __forceinline__ void splitA(float f0, float f1, u32& h, u32& s) {
    __half a = __float2half_rn(f0), b = __float2half_rn(f1);
    h = (u32)__half_as_ushort(a) | ((u32)__half_as_ushort(b) << 16);
    __half c = __float2half_rn(f0 - 0.96875f * __half2float(a));
    __half d = __float2half_rn(f1 - 0.96875f * __half2float(b));
    s = (u32)__half_as_ushort(c) | ((u32)__half_as_ushort(d) << 16);
}
__device__ __forceinline__ u32 pack2(float f0, float f1) {
    __half2 hh = __floats2half2_rn(f0, f1);
    return *reinterpret_cast<u32*>(&hh);
}
__device__ __forceinline__ void cpa16(u32 s, const void* g) {
    asm volatile("cp.async.cg.shared.global [%0], [%1], 16;"
                 :: "r"(s), "l"((u64)__cvta_generic_to_global(g)));
}
__device__ __forceinline__ void ldm4(u32* r, u32 addr) {
    asm volatile("ldmatrix.sync.aligned.m8n8.x4.shared.b16 {%0,%1,%2,%3}, [%4];"
                 : "=r"(r[0]), "=r"(r[1]), "=r"(r[2]), "=r"(r[3]) : "r"(addr));
}
__device__ __forceinline__ void ldm4t(u32* r, u32 addr) {
    asm volatile("ldmatrix.sync.aligned.m8n8.x4.trans.shared.b16 {%0,%1,%2,%3}, [%4];"
                 : "=r"(r[0]), "=r"(r[1]), "=r"(r[2]), "=r"(r[3]) : "r"(addr));
}
__device__ __forceinline__ void mma16816(float* d, const u32* a, const u32* b) {
    asm volatile(
        "mma.sync.aligned.m16n8k16.row.col.f32.f16.f16.f32 "
        "{%0,%1,%2,%3},{%4,%5,%6,%7},{%8,%9},{%0,%1,%2,%3};"
        : "+f"(d[0]), "+f"(d[1]), "+f"(d[2]), "+f"(d[3])
        : "r"(a[0]), "r"(a[1]), "r"(a[2]), "r"(a[3]), "r"(b[0]), "r"(b[1]));
}

// ---------------- merged prep: input split + weight build -------------------
// Inputs: xh = fp16(x), xs = fp16(x - (31/32) xh)            (alpha split)
// Weights q/k: wh = fp16(w), ws32 = fp16(32 w - 31 wh)       (= wh + 32 wl)
__global__ __launch_bounds__(256) void prep_k(
    const float* __restrict__ q, const float* __restrict__ kk,
    const float* __restrict__ wq_f, const float* __restrict__ wkv_f,
    const float* __restrict__ wo_f, const float* __restrict__ tgt,
    const float* __restrict__ src) {
    const u32 bid = blockIdx.x;
    if (bid < 8192) {
        size_t idx = (size_t)bid * 256 + threadIdx.x;  // 0..2M-1
        size_t i = idx & ((1u << 20) - 1);
        const float* sp = (idx < (1u << 20)) ? q : kk;
        __half* dh = (idx < (1u << 20)) ? g_xqh : g_xkh;
        __half* ds = (idx < (1u << 20)) ? g_xqs : g_xks;
        size_t e = i * 8;
        float4 a = ((const float4*)(sp + e))[0];
        float4 b = ((const float4*)(sp + e))[1];
        float f[8] = {a.x, a.y, a.z, a.w, b.x, b.y, b.z, b.w};
        u32 ph[4], ps[4];
#pragma unroll
        for (int j = 0; j < 4; j++) splitA(f[2 * j], f[2 * j + 1], ph[j], ps[j]);
        *(uint4*)(dh + e) = make_uint4(ph[0], ph[1], ph[2], ph[3]);
        *(uint4*)(ds + e) = make_uint4(ps[0], ps[1], ps[2], ps[3]);
    } else {
        u32 n = (bid - 8192) * 256 + threadIdx.x;  // 0..4M-1
        u32 seg = n >> 20, m = n & 1048575;
        const float* w;
        const float* f;
        __half *dh, *ds = nullptr;
        float scale = 1.f;
        if (seg == 0) {
            w = wq_f + (size_t)m * 8; f = tgt; dh = g_wqh; ds = g_wqs;
            scale = 0.125f * 1.44269504088896f;   // fold log2(e): exp2 softmax
        }
        else if (seg == 1) { w = wkv_f + (size_t)m * 8; f = src; dh = g_wkh; ds = g_wks; }
        else if (seg == 2) { w = wkv_f + ((size_t)1048576 + m) * 8; f = src; dh = g_wvh; }
        else { w = wo_f + (size_t)m * 8; f = tgt; dh = g_woh; }
        float acc = 0.f;
#pragma unroll
        for (int r = 0; r < 8; r++) acc += w[r] * f[r];
        acc *= scale;
        __half h = __float2half_rn(acc);
        dh[m] = h;
        if (ds) ds[m] = __float2half_rn(32.f * acc - 31.f * __half2float(h));
    }
}

// ---------------- merged q/k/v projection (one launch) ----------------------
// z=0: q: acc = xh.wh + xs.ws32; out = (32/33)*acc -> qh + qs (alpha split)
// z=1: k: same with k tensors -> kh + ks
// z=2: v = xkh.wvh (single term) -> plain vh
// BM=128, BN=128, BK=32. Stage: {xh, xs, wh, ws32} 32KB. Ring-3, depth-2.
__global__ __launch_bounds__(256, 2) void qkv_proj_k() {
    constexpr int STAGE = 4 * 128 * 64;
    extern __shared__ char smem[];
    const u32 sbase = smem_u32(smem);

    const int tid = threadIdx.x, lane = tid & 31, wid = tid >> 5;
    const int m0 = blockIdx.y * 128, n0 = blockIdx.x * 128;
    const int z = blockIdx.z;
    const __half *Ah, *As, *Bh, *Bs;
    __half *CH, *CL;
    if (z == 0) { Ah = g_xqh; As = g_xqs; Bh = g_wqh; Bs = g_wqs; CH = g_qh; CL = g_qs; }
    else if (z == 1) { Ah = g_xkh; As = g_xks; Bh = g_wkh; Bs = g_wks; CH = g_kh; CL = g_ks; }
    else { Ah = g_xkh; As = g_xkh; Bh = g_wvh; Bs = g_wvh; CH = g_vh; CL = nullptr; }
    const bool full = (z < 2);
    const __half* tiles[4];
    tiles[0] = Ah + (size_t)m0 * 1024;
    tiles[1] = As + (size_t)m0 * 1024;
    tiles[2] = Bh + (size_t)n0 * 1024;
    tiles[3] = Bs + (size_t)n0 * 1024;

    float acc[2][8][4];
#pragma unroll
    for (int a = 0; a < 2; a++)
#pragma unroll
        for (int b = 0; b < 8; b++)
#pragma unroll
            for (int c = 0; c < 4; c++) acc[a][b][c] = 0.f;

    auto load_stage = [&](int kc, int bufi) {
        const u32 sb = sbase + bufi * STAGE;
#pragma unroll
        for (int p = 0; p < 8; p++) {
            if (!full && ((p >> 1) == 1 || (p >> 1) == 3)) continue;
            const int L = p * 256 + tid;
            const int row = L >> 2, c = L & 3;
            const __half* g = tiles[row >> 7] + (size_t)(row & 127) * 1024 +
                              kc * 32 + c * 8;
            cpa16(sb + row * 64 + ((c ^ ((row >> 1) & 3)) << 4), g);
        }
    };

    load_stage(0, 0);
    asm volatile("cp.async.commit_group;");
    load_stage(1, 1);
    asm volatile("cp.async.commit_group;");
    int s_cur = 0, s_pre = 2;
    const int wm = wid >> 1, wn = wid & 1;
    for (int kc = 0; kc < 32; kc++) {
        asm volatile("cp.async.wait_group 1;");
        __syncthreads();
        if (kc + 2 < 32) load_stage(kc + 2, s_pre);
        asm volatile("cp.async.commit_group;");
        const u32 sb = sbase + s_cur * STAGE;
        const int i8 = lane & 7, seg = lane >> 3;
#pragma unroll
        for (int kstep = 0; kstep < 2; kstep++) {
            u32 ra0[2][4], ra1[2][4];
#pragma unroll
            for (int mt = 0; mt < 2; mt++) {
                int row = wm * 32 + mt * 16 + (lane & 15);
                int c = kstep * 2 + (lane >> 4);
                u32 sw = (u32)((c ^ ((row >> 1) & 3)) << 4);
                ldm4(ra0[mt], sb + row * 64 + sw);
                if (full) ldm4(ra1[mt], sb + (row + 128) * 64 + sw);
            }
            u32 rb[8][2];
            // pass 1: xh . wh  (B rows 256..383)
#pragma unroll
            for (int np = 0; np < 4; np++) {
                int row = 256 + wn * 64 + np * 16 + (seg >> 1) * 8 + i8;
                int c = kstep * 2 + (seg & 1);
                u32 r4[4];
                ldm4(r4, sb + row * 64 + ((c ^ ((row >> 1) & 3)) << 4));
                rb[np * 2][0] = r4[0]; rb[np * 2][1] = r4[1];
                rb[np * 2 + 1][0] = r4[2]; rb[np * 2 + 1][1] = r4[3];
            }
#pragma unroll
            for (int mt = 0; mt < 2; mt++)
#pragma unroll
                for (int nt = 0; nt < 8; nt++)
                    mma16816(acc[mt][nt], ra0[mt], rb[nt]);
            if (full) {
                // pass 2: xs . ws32  (B rows 384+)
#pragma unroll
                for (int np = 0; np < 4; np++) {
                    int row = 384 + wn * 64 + np * 16 + (seg >> 1) * 8 + i8;
                    int c = kstep * 2 + (seg & 1);
                    u32 r4[4];
                    ldm4(r4, sb + row * 64 + ((c ^ ((row >> 1) & 3)) << 4));
                    rb[np * 2][0] = r4[0]; rb[np * 2][1] = r4[1];
                    rb[np * 2 + 1][0] = r4[2]; rb[np * 2 + 1][1] = r4[3];
                }
#pragma unroll
                for (int mt = 0; mt < 2; mt++)
#pragma unroll
                    for (int nt = 0; nt < 8; nt++)
                        mma16816(acc[mt][nt], ra1[mt], rb[nt]);
            }
        }
        s_cur = (s_cur == 2) ? 0 : s_cur + 1;
        s_pre = (s_pre == 2) ? 0 : s_pre + 1;
    }

    const int r0 = m0 + wm * 32 + (lane >> 2);
    const int cb = n0 + wn * 64 + (lane & 3) * 2;
    const float RS = 32.f / 33.f;
#pragma unroll
    for (int mt = 0; mt < 2; mt++)
#pragma unroll
        for (int nt = 0; nt < 8; nt++) {
            int col = cb + nt * 8;
#pragma unroll
            for (int hh = 0; hh < 2; hh++) {
                int rr = r0 + mt * 16 + hh * 8;
                float f0 = acc[mt][nt][hh * 2], f1 = acc[mt][nt][hh * 2 + 1];
                size_t addr = (size_t)rr * 1024 + col;
                if (CL) {
                    f0 *= RS; f1 *= RS;
                    u32 h, s;
                    splitA(f0, f1, h, s);
                    *(u32*)(CH + addr) = h;
                    *(u32*)(CL + addr) = s;
                } else {
                    *(u32*)(CH + addr) = pack2(f0, f1);
                }
            }
        }
}

// ---------------- out-projection: out = ch @ woh^T (single term, fp32 out) --
__global__ __launch_bounds__(256, 2) void gemmo_k(float* __restrict__ CF) {
    constexpr int STAGE = 2 * 128 * 64;
    extern __shared__ char smem[];
    const u32 sbase = smem_u32(smem);

    const int tid = threadIdx.x, lane = tid & 31, wid = tid >> 5;
    const int m0 = blockIdx.y * 128, n0 = blockIdx.x * 128;
    const __half* tiles[2];
    tiles[0] = g_ch + (size_t)m0 * 1024;
    tiles[1] = g_woh + (size_t)n0 * 1024;

    float acc[2][8][4];
#pragma unroll
    for (int a = 0; a < 2; a++)
#pragma unroll
        for (int b = 0; b < 8; b++)
#pragma unroll
            for (int c = 0; c < 4; c++) acc[a][b][c] = 0.f;

    auto load_stage = [&](int kc, int bufi) {
        const u32 sb = sbase + bufi * STAGE;
#pragma unroll
        for (int p = 0; p < 4; p++) {
            const int L = p * 256 + tid;
            const int row = L >> 2, c = L & 3;
            const __half* g = tiles[row >> 7] + (size_t)(row & 127) * 1024 +
                              kc * 32 + c * 8;
            cpa16(sb + row * 64 + ((c ^ ((row >> 1) & 3)) << 4), g);
        }
    };

    load_stage(0, 0);
    asm volatile("cp.async.commit_group;");
    load_stage(1, 1);
    asm volatile("cp.async.commit_group;");
    int s_cur = 0, s_pre = 2;
    const int wm = wid >> 1, wn = wid & 1;
    for (int kc = 0; kc < 32; kc++) {
        asm volatile("cp.async.wait_group 1;");
        __syncthreads();
        if (kc + 2 < 32) load_stage(kc + 2, s_pre);
        asm volatile("cp.async.commit_group;");
        const u32 sb = sbase + s_cur * STAGE;
        const int i8 = lane & 7, seg = lane >> 3;
#pragma unroll
        for (int kstep = 0; kstep < 2; kstep++) {
            u32 ra0[2][4];
#pragma unroll
            for (int mt = 0; mt < 2; mt++) {
                int row = wm * 32 + mt * 16 + (lane & 15);
                int c = kstep * 2 + (lane >> 4);
                ldm4(ra0[mt], sb + row * 64 + ((c ^ ((row >> 1) & 3)) << 4));
            }
            u32 rb[8][2];
#pragma unroll
            for (int np = 0; np < 4; np++) {
                int row = 128 + wn * 64 + np * 16 + (seg >> 1) * 8 + i8;
                int c = kstep * 2 + (seg & 1);
                u32 r4[4];
                ldm4(r4, sb + row * 64 + ((c ^ ((row >> 1) & 3)) << 4));
                rb[np * 2][0] = r4[0]; rb[np * 2][1] = r4[1];
                rb[np * 2 + 1][0] = r4[2]; rb[np * 2 + 1][1] = r4[3];
            }
#pragma unroll
            for (int mt = 0; mt < 2; mt++)
#pragma unroll
                for (int nt = 0; nt < 8; nt++)
                    mma16816(acc[mt][nt], ra0[mt], rb[nt]);
        }
        s_cur = (s_cur == 2) ? 0 : s_cur + 1;
        s_pre = (s_pre == 2) ? 0 : s_pre + 1;
    }

    const int r0 = m0 + wm * 32 + (lane >> 2);
    const int cb = n0 + wn * 64 + (lane & 3) * 2;
#pragma unroll
    for (int mt = 0; mt < 2; mt++)
#pragma unroll
        for (int nt = 0; nt < 8; nt++) {
            int col = cb + nt * 8;
#pragma unroll
            for (int hh = 0; hh < 2; hh++) {
                int rr = r0 + mt * 16 + hh * 8;
                *(float2*)(CF + (size_t)rr * 1024 + col) =
                    make_float2(acc[mt][nt][hh * 2], acc[mt][nt][hh * 2 + 1]);
            }
        }
}

// ---------------- fused flash attention ----------------
// S via alpha-combined split: sc = 0.96875*(qh.kh) + 32*(qs.ks)  (2 mma terms)
// Tiles: kh, ks, v (64x64 each). Ring-3, depth-2 prefetch, one barrier/iter.
// exp2-domain softmax (log2e folded into wq). ctx += P.V (trans-ldmatrix V).
__global__ __launch_bounds__(256, 2) void attn_fused_k(const unsigned char* __restrict__ mask) {
    extern __shared__ char smem[];
    const u32 sbase = smem_u32(smem);
    const int tid = threadIdx.x, lane = tid & 31, w = tid >> 5;
    const int z = blockIdx.y, b = z >> 4, h = z & 15;
    const int t0 = blockIdx.x * 128;
    const int r = lane >> 2, cp = (lane & 3) * 2;
    constexpr int STAGE = 3 * 8192;   // kh + ks + v

    u32 qa[2][4][4];
    {
        const int mrow = t0 + w * 16 + r;
#pragma unroll
        for (int c = 0; c < 4; c++)
#pragma unroll
            for (int i = 0; i < 4; i++) {
                int mm = mrow + (i & 1) * 8;
                int col = h * 64 + c * 16 + cp + (i >> 1) * 8;
                size_t ad = ((size_t)(mm * 8 + b)) * 1024 + col;
                qa[0][c][i] = *(const u32*)(g_qh + ad);
                qa[1][c][i] = *(const u32*)(g_qs + ad);
            }
    }

    float ctx[8][4];
#pragma unroll
    for (int j = 0; j < 8; j++)
#pragma unroll
        for (int c = 0; c < 4; c++) ctx[j][c] = 0.f;
    float m0 = -1e30f, m1 = -1e30f, l0 = 0.f, l1 = 0.f;

    auto load_stage = [&](int it, int st) {
        const int s0 = it * 64;
        const u32 sb = sbase + st * STAGE;
#pragma unroll
        for (int p = 0; p < 6; p++) {
            int L = p * 256 + tid;
            int tile = L >> 9, rr = (L >> 3) & 63, c = L & 7;
            const __half* g;
            if (tile == 0)
                g = g_kh + ((size_t)((s0 + rr) * 8 + b)) * 1024 + h * 64 + c * 8;
            else if (tile == 1)
                g = g_ks + ((size_t)((s0 + rr) * 8 + b)) * 1024 + h * 64 + c * 8;
            else
                g = g_vh + ((size_t)((s0 + rr) * 8 + b)) * 1024 + h * 64 + c * 8;
            cpa16(sb + tile * 8192 + rr * 128 + ((c ^ (rr & 7)) << 4), g);
        }
        if (tid < 64)
            ((float*)(smem + 3 * STAGE + st * 256))[tid] =
                mask[b * 1024 + s0 + tid] ? -1e30f : 0.f;
    };

    load_stage(0, 0);
    asm volatile("cp.async.commit_group;");
    load_stage(1, 1);
    asm volatile("cp.async.commit_group;");
    int s_cur = 0, s_pre = 2;
    for (int it = 0; it < 16; it++) {
        asm volatile("cp.async.wait_group 1;");
        __syncthreads();
        if (it + 2 < 16) load_stage(it + 2, s_pre);
        asm volatile("cp.async.commit_group;");
        const u32 sb = sbase + s_cur * STAGE;

        float sc[8][4];
        const int i8 = lane & 7, seg = lane >> 3;
#pragma unroll
        for (int hf = 0; hf < 2; hf++) {
            float mainA[4][4], corrA[4][4];
#pragma unroll
            for (int j = 0; j < 4; j++)
#pragma unroll
                for (int x = 0; x < 4; x++) { mainA[j][x] = 0.f; corrA[j][x] = 0.f; }
#pragma unroll
            for (int c = 0; c < 4; c++) {
                u32 bf[4][2];
#pragma unroll
                for (int np = 0; np < 2; np++) {
                    int row = hf * 32 + np * 16 + (seg >> 1) * 8 + i8;
                    int cc = c * 2 + (seg & 1);
                    u32 r4[4];
                    ldm4(r4, sb + row * 128 + ((cc ^ (row & 7)) << 4));
                    bf[np * 2][0] = r4[0]; bf[np * 2][1] = r4[1];
                    bf[np * 2 + 1][0] = r4[2]; bf[np * 2 + 1][1] = r4[3];
                }
#pragma unroll
                for (int j = 0; j < 4; j++) mma16816(mainA[j], qa[0][c], bf[j]);
#pragma unroll
                for (int np = 0; np < 2; np++) {
                    int row = hf * 32 + np * 16 + (seg >> 1) * 8 + i8;
                    int cc = c * 2 + (seg & 1);
                    u32 r4[4];
                    ldm4(r4, sb + 8192 + row * 128 + ((cc ^ (row & 7)) << 4));
                    bf[np * 2][0] = r4[0]; bf[np * 2][1] = r4[1];
                    bf[np * 2 + 1][0] = r4[2]; bf[np * 2 + 1][1] = r4[3];
                }
#pragma unroll
                for (int j = 0; j < 4; j++) mma16816(corrA[j], qa[1][c], bf[j]);
            }
#pragma unroll
            for (int j = 0; j < 4; j++)
#pragma unroll
                for (int x = 0; x < 4; x++)
                    sc[hf * 4 + j][x] = 0.96875f * mainA[j][x] + 32.f * corrA[j][x];
        }

        const float* bias = (const float*)(smem + 3 * STAGE + s_cur * 256);
        float mx0 = -1e30f, mx1 = -1e30f;
#pragma unroll
        for (int j = 0; j < 8; j++) {
            int col = j * 8 + cp;
            float b0 = bias[col], b1 = bias[col + 1];
            sc[j][0] += b0; sc[j][1] += b1;
            sc[j][2] += b0; sc[j][3] += b1;
            mx0 = fmaxf(mx0, fmaxf(sc[j][0], sc[j][1]));
            mx1 = fmaxf(mx1, fmaxf(sc[j][2], sc[j][3]));
        }
        mx0 = fmaxf(mx0, __shfl_xor_sync(~0u, mx0, 1));
        mx0 = fmaxf(mx0, __shfl_xor_sync(~0u, mx0, 2));
        mx1 = fmaxf(mx1, __shfl_xor_sync(~0u, mx1, 1));
        mx1 = fmaxf(mx1, __shfl_xor_sync(~0u, mx1, 2));
        float nm0 = fmaxf(m0, mx0), nm1 = fmaxf(m1, mx1);
        float cr0 = exp2f(m0 - nm0), cr1 = exp2f(m1 - nm1);
        m0 = nm0; m1 = nm1;
        float sum0 = 0.f, sum1 = 0.f;
#pragma unroll
        for (int j = 0; j < 8; j++) {
            sc[j][0] = exp2f(sc[j][0] - nm0);
            sc[j][1] = exp2f(sc[j][1] - nm0);
            sc[j][2] = exp2f(sc[j][2] - nm1);
            sc[j][3] = exp2f(sc[j][3] - nm1);
            sum0 += sc[j][0] + sc[j][1];
            sum1 += sc[j][2] + sc[j][3];
        }
        sum0 += __shfl_xor_sync(~0u, sum0, 1);
        sum0 += __shfl_xor_sync(~0u, sum0, 2);
        sum1 += __shfl_xor_sync(~0u, sum1, 1);
        sum1 += __shfl_xor_sync(~0u, sum1, 2);
        l0 = l0 * cr0 + sum0;
        l1 = l1 * cr1 + sum1;
#pragma unroll
        for (int j = 0; j < 8; j++) {
            ctx[j][0] *= cr0; ctx[j][1] *= cr0;
            ctx[j][2] *= cr1; ctx[j][3] *= cr1;
        }

        u32 pa[4][4];
#pragma unroll
        for (int c = 0; c < 4; c++) {
            pa[c][0] = pack2(sc[2 * c][0], sc[2 * c][1]);
            pa[c][1] = pack2(sc[2 * c][2], sc[2 * c][3]);
            pa[c][2] = pack2(sc[2 * c + 1][0], sc[2 * c + 1][1]);
            pa[c][3] = pack2(sc[2 * c + 1][2], sc[2 * c + 1][3]);
        }

#pragma unroll
        for (int c = 0; c < 4; c++) {
            u32 bv[8][2];
#pragma unroll
            for (int jp = 0; jp < 4; jp++) {
                int srow = c * 16 + (seg & 1) * 8 + i8;
                int cseg = jp * 2 + (seg >> 1);
                u32 r4[4];
                ldm4t(r4, sb + 16384 + srow * 128 + ((cseg ^ (srow & 7)) << 4));
                bv[2 * jp][0] = r4[0]; bv[2 * jp][1] = r4[1];
                bv[2 * jp + 1][0] = r4[2]; bv[2 * jp + 1][1] = r4[3];
            }
#pragma unroll
            for (int j = 0; j < 8; j++) mma16816(ctx[j], pa[c], bv[j]);
        }
        s_cur = (s_cur == 2) ? 0 : s_cur + 1;
        s_pre = (s_pre == 2) ? 0 : s_pre + 1;
    }

    const float inv0 = 1.f / l0, inv1 = 1.f / l1;
    const int mrow = t0 + w * 16 + r;
#pragma unroll
    for (int j = 0; j < 8; j++) {
        int col = h * 64 + j * 8 + cp;
        size_t a0 = ((size_t)(mrow * 8 + b)) * 1024 + col;
        *(u32*)(g_ch + a0) = pack2(ctx[j][0] * inv0, ctx[j][1] * inv0);
        size_t a1 = ((size_t)((mrow + 8) * 8 + b)) * 1024 + col;
        *(u32*)(g_ch + a1) = pack2(ctx[j][2] * inv1, ctx[j][3] * inv1);
    }
}

// ---------------- launch ----------------
extern "C" void kernel_launch(void* const* d_in, const int* in_sizes, int n_in,
                              void* d_out, int out_size) {
    const float* query = (const float*)d_in[0];
    const float* key = (const float*)d_in[1];
    const float* tgt = (const float*)d_in[2];
    const float* src = (const float*)d_in[3];
    const float* wq_f = (const float*)d_in[4];
    const float* wkv_f = (const float*)d_in[5];
    const float* wo_f = (const float*)d_in[6];
    const unsigned char* mask = (const unsigned char*)d_in[7];
    float* out = (float*)d_out;

    const int SM4 = 3 * 4 * 128 * 64;          // 96 KB (4-tile, ring-3)
    const int SM2 = 3 * 2 * 128 * 64;          // 48 KB (2-tile, ring-3)
    const int SMATT = 3 * 3 * 8192 + 768;      // 74.25 KB (ring-3 + bias)
    cudaFuncSetAttribute(attn_fused_k,
                         cudaFuncAttributeMaxDynamicSharedMemorySize, SMATT);
    cudaFuncSetAttribute(qkv_proj_k,
                         cudaFuncAttributeMaxDynamicSharedMemorySize, SM4);
    cudaFuncSetAttribute(gemmo_k,
                         cudaFuncAttributeMaxDynamicSharedMemorySize, SM2);

    // merged input-split + weight-build (wq carries 0.125*log2e; ws32 weights)
    prep_k<<<24576, 256>>>(query, key, wq_f, wkv_f, wo_f, tgt, src);

    // q-proj (z=0), k-proj (z=1): 2-pass alpha-combined; v-proj (z=2): 1-pass
    qkv_proj_k<<<dim3(8, 64, 3), 256, SM4>>>();

    // fused attention: alpha-combined S + mask + exp2 softmax + P@V -> ch
    attn_fused_k<<<dim3(8, 128), 256, SMATT>>>(mask);

    // out = ch @ wo^T (single term), fp32 out
    gemmo_k<<<dim3(8, 64), 256, SM2>>>(out);
}

// round 15
// speedup vs baseline: 2.3441x; 1.0258x over previous
#include <cuda_runtime.h>
#include <cuda_fp16.h>
#include <cstdint>
#include <cstddef>

using u32 = uint32_t;
using u64 = uint64_t;
#define MTOT 8192

// ---------------- static scratch (no allocation) ----------------
__device__ __half g_xqh[MTOT * 1024], g_xqs[MTOT * 1024];
__device__ __half g_xkh[MTOT * 1024], g_xks[MTOT * 1024];
__device__ __half g_wqh[1024 * 1024], g_wqs[1024 * 1024];   // ws32 form
__device__ __half g_wkh[1024 * 1024], g_wks[1024 * 1024];   // ws32 form
__device__ __half g_wvh[1024 * 1024];
__device__ __half g_woh[1024 * 1024];
__device__ __half g_qh[MTOT * 1024], g_qs[MTOT * 1024];     // q scaled by (32/33)
__device__ __half g_kh[MTOT * 1024], g_ks[MTOT * 1024];     // ks in ks32 form
__device__ __half g_vh[MTOT * 1024];
__device__ __half g_ch[MTOT * 1024];

// ---------------- helpers ----------------
__device__ __forceinline__ u32 smem_u32(const void* p) {
    u32 a;
    asm("{ .reg .u64 t; cvta.to.shared.u64 t, %1; cvt.u32.u64 %0, t; }"
        : "=r"(a) : "l"(p));
    return a;
}
// alpha split: s = fp16(f - (31/32)*hi)  (= hi/32 + lo)
__device__ __forceinline__ void splitA(float f0, float f1, u32& h, u32& s) {
    __half a = __float2half_rn(f0), b = __float2half_rn(f1);
    h = (u32)__half_as_ushort(a) | ((u32)__half_as_ushort(b) << 16);
    __half c = __float2half_rn(f0 - 0.96875f * __half2float(a));
    __half d = __float2half_rn(f1 - 0.96875f * __half2float(b));
    s = (u32)__half_as_ushort(c) | ((u32)__half_as_ushort(d) << 16);
}
// ws32 split: s = fp16(32*f - 31*hi)  (= hi + 32*lo)
__device__ __forceinline__ void splitW(float f0, float f1, u32& h, u32& s) {
    __half a = __float2half_rn(f0), b = __float2half_rn(f1);
    h = (u32)__half_as_ushort(a) | ((u32)__half_as_ushort(b) << 16);
    __half c = __float2half_rn(32.f * f0 - 31.f * __half2float(a));
    __half d = __float2half_rn(32.f * f1 - 31.f * __half2float(b));
    s = (u32)__half_as_ushort(c) | ((u32)__half_as_ushort(d) << 16);
}
__device__ __forceinline__ u32 pack2(float f0, float f1) {
    __half2 hh = __floats2half2_rn(f0, f1);
    return *reinterpret_cast<u32*>(&hh);
}
__device__ __forceinline__ void cpa16(u32 s, const void* g) {
    asm volatile("cp.async.cg.shared.global [%0], [%1], 16;"
                 :: "r"(s), "l"((u64)__cvta_generic_to_global(g)));
}
__device__ __forceinline__ void ldm4(u32* r, u32 addr) {
    asm volatile("ldmatrix.sync.aligned.m8n8.x4.shared.b16 {%0,%1,%2,%3}, [%4];"
                 : "=r"(r[0]), "=r"(r[1]), "=r"(r[2]), "=r"(r[3]) : "r"(addr));
}
__device__ __forceinline__ void ldm4t(u32* r, u32 addr) {
    asm volatile("ldmatrix.sync.aligned.m8n8.x4.trans.shared.b16 {%0,%1,%2,%3}, [%4];"
                 : "=r"(r[0]), "=r"(r[1]), "=r"(r[2]), "=r"(r[3]) : "r"(addr));
}
__device__ __forceinline__ void mma16816(float* d, const u32* a, const u32* b) {
    asm volatile(
        "mma.sync.aligned.m16n8k16.row.col.f32.f16.f16.f32 "
        "{%0,%1,%2,%3},{%4,%5,%6,%7},{%8,%9},{%0,%1,%2,%3};"
        : "+f"(d[0]), "+f"(d[1]), "+f"(d[2]), "+f"(d[3])
        : "r"(a[0]), "r"(a[1]), "r"(a[2]), "r"(a[3]), "r"(b[0]), "r"(b[1]));
}

// ---------------- merged prep: input split + weight build -------------------
// Inputs: xh = fp16(x), xs = fp16(x - (31/32) xh)
// Weights q/k: wh = fp16(w), ws32 = fp16(32 w - 31 wh)
__global__ __launch_bounds__(256) void prep_k(
    const float* __restrict__ q, const float* __restrict__ kk,
    const float* __restrict__ wq_f, const float* __restrict__ wkv_f,
    const float* __restrict__ wo_f, const float* __restrict__ tgt,
    const float* __restrict__ src) {
    const u32 bid = blockIdx.x;
    if (bid < 8192) {
        size_t idx = (size_t)bid * 256 + threadIdx.x;  // 0..2M-1
        size_t i = idx & ((1u << 20) - 1);
        const float* sp = (idx < (1u << 20)) ? q : kk;
        __half* dh = (idx < (1u << 20)) ? g_xqh : g_xkh;
        __half* ds = (idx < (1u << 20)) ? g_xqs : g_xks;
        size_t e = i * 8;
        float4 a = ((const float4*)(sp + e))[0];
        float4 b = ((const float4*)(sp + e))[1];
        float f[8] = {a.x, a.y, a.z, a.w, b.x, b.y, b.z, b.w};
        u32 ph[4], ps[4];
#pragma unroll
        for (int j = 0; j < 4; j++) splitA(f[2 * j], f[2 * j + 1], ph[j], ps[j]);
        *(uint4*)(dh + e) = make_uint4(ph[0], ph[1], ph[2], ph[3]);
        *(uint4*)(ds + e) = make_uint4(ps[0], ps[1], ps[2], ps[3]);
    } else {
        u32 n = (bid - 8192) * 256 + threadIdx.x;  // 0..4M-1
        u32 seg = n >> 20, m = n & 1048575;
        const float* w;
        const float* f;
        __half *dh, *ds = nullptr;
        float scale = 1.f;
        if (seg == 0) {
            w = wq_f + (size_t)m * 8; f = tgt; dh = g_wqh; ds = g_wqs;
            scale = 0.125f * 1.44269504088896f;   // fold log2(e): exp2 softmax
        }
        else if (seg == 1) { w = wkv_f + (size_t)m * 8; f = src; dh = g_wkh; ds = g_wks; }
        else if (seg == 2) { w = wkv_f + ((size_t)1048576 + m) * 8; f = src; dh = g_wvh; }
        else { w = wo_f + (size_t)m * 8; f = tgt; dh = g_woh; }
        float acc = 0.f;
#pragma unroll
        for (int r = 0; r < 8; r++) acc += w[r] * f[r];
        acc *= scale;
        __half h = __float2half_rn(acc);
        dh[m] = h;
        if (ds) ds[m] = __float2half_rn(32.f * acc - 31.f * __half2float(h));
    }
}

// ---------------- merged q/k/v projection (one launch) ----------------------
// z=0: q: acc = xh.wh + xs.ws32; out = (32/33)^2 * acc -> qh + qs (alpha split)
//      (one 32/33 cancels the projection trick, the second pre-cancels the
//       attention S trick's 33/32)
// z=1: k: acc same; out = (32/33)*acc -> kh + ks32 (splitW)
// z=2: v = xkh.wvh (single term) -> plain vh
__global__ __launch_bounds__(256, 2) void qkv_proj_k() {
    constexpr int STAGE = 4 * 128 * 64;
    extern __shared__ char smem[];
    const u32 sbase = smem_u32(smem);

    const int tid = threadIdx.x, lane = tid & 31, wid = tid >> 5;
    const int m0 = blockIdx.y * 128, n0 = blockIdx.x * 128;
    const int z = blockIdx.z;
    const __half *Ah, *As, *Bh, *Bs;
    __half *CH, *CL;
    if (z == 0) { Ah = g_xqh; As = g_xqs; Bh = g_wqh; Bs = g_wqs; CH = g_qh; CL = g_qs; }
    else if (z == 1) { Ah = g_xkh; As = g_xks; Bh = g_wkh; Bs = g_wks; CH = g_kh; CL = g_ks; }
    else { Ah = g_xkh; As = g_xkh; Bh = g_wvh; Bs = g_wvh; CH = g_vh; CL = nullptr; }
    const bool full = (z < 2);
    const __half* tiles[4];
    tiles[0] = Ah + (size_t)m0 * 1024;
    tiles[1] = As + (size_t)m0 * 1024;
    tiles[2] = Bh + (size_t)n0 * 1024;
    tiles[3] = Bs + (size_t)n0 * 1024;

    float acc[2][8][4];
#pragma unroll
    for (int a = 0; a < 2; a++)
#pragma unroll
        for (int b = 0; b < 8; b++)
#pragma unroll
            for (int c = 0; c < 4; c++) acc[a][b][c] = 0.f;

    auto load_stage = [&](int kc, int bufi) {
        const u32 sb = sbase + bufi * STAGE;
#pragma unroll
        for (int p = 0; p < 8; p++) {
            if (!full && ((p >> 1) == 1 || (p >> 1) == 3)) continue;
            const int L = p * 256 + tid;
            const int row = L >> 2, c = L & 3;
            const __half* g = tiles[row >> 7] + (size_t)(row & 127) * 1024 +
                              kc * 32 + c * 8;
            cpa16(sb + row * 64 + ((c ^ ((row >> 1) & 3)) << 4), g);
        }
    };

    load_stage(0, 0);
    asm volatile("cp.async.commit_group;");
    load_stage(1, 1);
    asm volatile("cp.async.commit_group;");
    int s_cur = 0, s_pre = 2;
    const int wm = wid >> 1, wn = wid & 1;
    for (int kc = 0; kc < 32; kc++) {
        asm volatile("cp.async.wait_group 1;");
        __syncthreads();
        if (kc + 2 < 32) load_stage(kc + 2, s_pre);
        asm volatile("cp.async.commit_group;");
        const u32 sb = sbase + s_cur * STAGE;
        const int i8 = lane & 7, seg = lane >> 3;
#pragma unroll
        for (int kstep = 0; kstep < 2; kstep++) {
            u32 ra0[2][4], ra1[2][4];
#pragma unroll
            for (int mt = 0; mt < 2; mt++) {
                int row = wm * 32 + mt * 16 + (lane & 15);
                int c = kstep * 2 + (lane >> 4);
                u32 sw = (u32)((c ^ ((row >> 1) & 3)) << 4);
                ldm4(ra0[mt], sb + row * 64 + sw);
                if (full) ldm4(ra1[mt], sb + (row + 128) * 64 + sw);
            }
            u32 rb[8][2];
#pragma unroll
            for (int np = 0; np < 4; np++) {
                int row = 256 + wn * 64 + np * 16 + (seg >> 1) * 8 + i8;
                int c = kstep * 2 + (seg & 1);
                u32 r4[4];
                ldm4(r4, sb + row * 64 + ((c ^ ((row >> 1) & 3)) << 4));
                rb[np * 2][0] = r4[0]; rb[np * 2][1] = r4[1];
                rb[np * 2 + 1][0] = r4[2]; rb[np * 2 + 1][1] = r4[3];
            }
#pragma unroll
            for (int mt = 0; mt < 2; mt++)
#pragma unroll
                for (int nt = 0; nt < 8; nt++)
                    mma16816(acc[mt][nt], ra0[mt], rb[nt]);
            if (full) {
#pragma unroll
                for (int np = 0; np < 4; np++) {
                    int row = 384 + wn * 64 + np * 16 + (seg >> 1) * 8 + i8;
                    int c = kstep * 2 + (seg & 1);
                    u32 r4[4];
                    ldm4(r4, sb + row * 64 + ((c ^ ((row >> 1) & 3)) << 4));
                    rb[np * 2][0] = r4[0]; rb[np * 2][1] = r4[1];
                    rb[np * 2 + 1][0] = r4[2]; rb[np * 2 + 1][1] = r4[3];
                }
#pragma unroll
                for (int mt = 0; mt < 2; mt++)
#pragma unroll
                    for (int nt = 0; nt < 8; nt++)
                        mma16816(acc[mt][nt], ra1[mt], rb[nt]);
            }
        }
        s_cur = (s_cur == 2) ? 0 : s_cur + 1;
        s_pre = (s_pre == 2) ? 0 : s_pre + 1;
    }

    const int r0 = m0 + wm * 32 + (lane >> 2);
    const int cb = n0 + wn * 64 + (lane & 3) * 2;
    const float RS = (z == 0) ? (32.f / 33.f) * (32.f / 33.f) : (32.f / 33.f);
#pragma unroll
    for (int mt = 0; mt < 2; mt++)
#pragma unroll
        for (int nt = 0; nt < 8; nt++) {
            int col = cb + nt * 8;
#pragma unroll
            for (int hh = 0; hh < 2; hh++) {
                int rr = r0 + mt * 16 + hh * 8;
                float f0 = acc[mt][nt][hh * 2], f1 = acc[mt][nt][hh * 2 + 1];
                size_t addr = (size_t)rr * 1024 + col;
                if (CL) {
                    f0 *= RS; f1 *= RS;
                    u32 h, s;
                    if (z == 0) splitA(f0, f1, h, s);
                    else        splitW(f0, f1, h, s);
                    *(u32*)(CH + addr) = h;
                    *(u32*)(CL + addr) = s;
                } else {
                    *(u32*)(CH + addr) = pack2(f0, f1);
                }
            }
        }
}

// ---------------- out-projection: out = ch @ woh^T (single term, fp32 out) --
__global__ __launch_bounds__(256, 2) void gemmo_k(float* __restrict__ CF) {
    constexpr int STAGE = 2 * 128 * 64;
    extern __shared__ char smem[];
    const u32 sbase = smem_u32(smem);

    const int tid = threadIdx.x, lane = tid & 31, wid = tid >> 5;
    const int m0 = blockIdx.y * 128, n0 = blockIdx.x * 128;
    const __half* tiles[2];
    tiles[0] = g_ch + (size_t)m0 * 1024;
    tiles[1] = g_woh + (size_t)n0 * 1024;

    float acc[2][8][4];
#pragma unroll
    for (int a = 0; a < 2; a++)
#pragma unroll
        for (int b = 0; b < 8; b++)
#pragma unroll
            for (int c = 0; c < 4; c++) acc[a][b][c] = 0.f;

    auto load_stage = [&](int kc, int bufi) {
        const u32 sb = sbase + bufi * STAGE;
#pragma unroll
        for (int p = 0; p < 4; p++) {
            const int L = p * 256 + tid;
            const int row = L >> 2, c = L & 3;
            const __half* g = tiles[row >> 7] + (size_t)(row & 127) * 1024 +
                              kc * 32 + c * 8;
            cpa16(sb + row * 64 + ((c ^ ((row >> 1) & 3)) << 4), g);
        }
    };

    load_stage(0, 0);
    asm volatile("cp.async.commit_group;");
    load_stage(1, 1);
    asm volatile("cp.async.commit_group;");
    int s_cur = 0, s_pre = 2;
    const int wm = wid >> 1, wn = wid & 1;
    for (int kc = 0; kc < 32; kc++) {
        asm volatile("cp.async.wait_group 1;");
        __syncthreads();
        if (kc + 2 < 32) load_stage(kc + 2, s_pre);
        asm volatile("cp.async.commit_group;");
        const u32 sb = sbase + s_cur * STAGE;
        const int i8 = lane & 7, seg = lane >> 3;
#pragma unroll
        for (int kstep = 0; kstep < 2; kstep++) {
            u32 ra0[2][4];
#pragma unroll
            for (int mt = 0; mt < 2; mt++) {
                int row = wm * 32 + mt * 16 + (lane & 15);
                int c = kstep * 2 + (lane >> 4);
                ldm4(ra0[mt], sb + row * 64 + ((c ^ ((row >> 1) & 3)) << 4));
            }
            u32 rb[8][2];
#pragma unroll
            for (int np = 0; np < 4; np++) {
                int row = 128 + wn * 64 + np * 16 + (seg >> 1) * 8 + i8;
                int c = kstep * 2 + (seg & 1);
                u32 r4[4];
                ldm4(r4, sb + row * 64 + ((c ^ ((row >> 1) & 3)) << 4));
                rb[np * 2][0] = r4[0]; rb[np * 2][1] = r4[1];
                rb[np * 2 + 1][0] = r4[2]; rb[np * 2 + 1][1] = r4[3];
            }
#pragma unroll
            for (int mt = 0; mt < 2; mt++)
#pragma unroll
                for (int nt = 0; nt < 8; nt++)
                    mma16816(acc[mt][nt], ra0[mt], rb[nt]);
        }
        s_cur = (s_cur == 2) ? 0 : s_cur + 1;
        s_pre = (s_pre == 2) ? 0 : s_pre + 1;
    }

    const int r0 = m0 + wm * 32 + (lane >> 2);
    const int cb = n0 + wn * 64 + (lane & 3) * 2;
#pragma unroll
    for (int mt = 0; mt < 2; mt++)
#pragma unroll
        for (int nt = 0; nt < 8; nt++) {
            int col = cb + nt * 8;
#pragma unroll
            for (int hh = 0; hh < 2; hh++) {
                int rr = r0 + mt * 16 + hh * 8;
                *(float2*)(CF + (size_t)rr * 1024 + col) =
                    make_float2(acc[mt][nt][hh * 2], acc[mt][nt][hh * 2 + 1]);
            }
        }
}

// ---------------- fused flash attention ----------------
// S = qh.kh + qs.ks32  (single accumulator; scales pre-folded into q).
// Tiles: kh, ks32, v (64x64 each). Ring-3, depth-2 prefetch, one barrier/iter.
// exp2-domain softmax (log2e folded into wq). ctx += P.V (trans-ldmatrix V).
__global__ __launch_bounds__(256, 2) void attn_fused_k(const unsigned char* __restrict__ mask) {
    extern __shared__ char smem[];
    const u32 sbase = smem_u32(smem);
    const int tid = threadIdx.x, lane = tid & 31, w = tid >> 5;
    const int z = blockIdx.y, b = z >> 4, h = z & 15;
    const int t0 = blockIdx.x * 128;
    const int r = lane >> 2, cp = (lane & 3) * 2;
    constexpr int STAGE = 3 * 8192;   // kh + ks32 + v

    u32 qa[2][4][4];
    {
        const int mrow = t0 + w * 16 + r;
#pragma unroll
        for (int c = 0; c < 4; c++)
#pragma unroll
            for (int i = 0; i < 4; i++) {
                int mm = mrow + (i & 1) * 8;
                int col = h * 64 + c * 16 + cp + (i >> 1) * 8;
                size_t ad = ((size_t)(mm * 8 + b)) * 1024 + col;
                qa[0][c][i] = *(const u32*)(g_qh + ad);
                qa[1][c][i] = *(const u32*)(g_qs + ad);
            }
    }

    float ctx[8][4];
#pragma unroll
    for (int j = 0; j < 8; j++)
#pragma unroll
        for (int c = 0; c < 4; c++) ctx[j][c] = 0.f;
    float m0 = -1e30f, m1 = -1e30f, l0 = 0.f, l1 = 0.f;

    auto load_stage = [&](int it, int st) {
        const int s0 = it * 64;
        const u32 sb = sbase + st * STAGE;
#pragma unroll
        for (int p = 0; p < 6; p++) {
            int L = p * 256 + tid;
            int tile = L >> 9, rr = (L >> 3) & 63, c = L & 7;
            const __half* g;
            if (tile == 0)
                g = g_kh + ((size_t)((s0 + rr) * 8 + b)) * 1024 + h * 64 + c * 8;
            else if (tile == 1)
                g = g_ks + ((size_t)((s0 + rr) * 8 + b)) * 1024 + h * 64 + c * 8;
            else
                g = g_vh + ((size_t)((s0 + rr) * 8 + b)) * 1024 + h * 64 + c * 8;
            cpa16(sb + tile * 8192 + rr * 128 + ((c ^ (rr & 7)) << 4), g);
        }
        if (tid < 64)
            ((float*)(smem + 3 * STAGE + st * 256))[tid] =
                mask[b * 1024 + s0 + tid] ? -1e30f : 0.f;
    };

    load_stage(0, 0);
    asm volatile("cp.async.commit_group;");
    load_stage(1, 1);
    asm volatile("cp.async.commit_group;");
    int s_cur = 0, s_pre = 2;
    for (int it = 0; it < 16; it++) {
        asm volatile("cp.async.wait_group 1;");
        __syncthreads();
        if (it + 2 < 16) load_stage(it + 2, s_pre);
        asm volatile("cp.async.commit_group;");
        const u32 sb = sbase + s_cur * STAGE;

        float sc[8][4];
#pragma unroll
        for (int j = 0; j < 8; j++)
#pragma unroll
            for (int c = 0; c < 4; c++) sc[j][c] = 0.f;

        const int i8 = lane & 7, seg = lane >> 3;
#pragma unroll
        for (int c = 0; c < 4; c++) {
            u32 bf[8][2];
            // pass 1: qh . kh
#pragma unroll
            for (int np = 0; np < 4; np++) {
                int row = np * 16 + (seg >> 1) * 8 + i8;
                int cc = c * 2 + (seg & 1);
                u32 r4[4];
                ldm4(r4, sb + row * 128 + ((cc ^ (row & 7)) << 4));
                bf[np * 2][0] = r4[0]; bf[np * 2][1] = r4[1];
                bf[np * 2 + 1][0] = r4[2]; bf[np * 2 + 1][1] = r4[3];
            }
#pragma unroll
            for (int j = 0; j < 8; j++) mma16816(sc[j], qa[0][c], bf[j]);
            // pass 2: qs . ks32 (same accumulator)
#pragma unroll
            for (int np = 0; np < 4; np++) {
                int row = np * 16 + (seg >> 1) * 8 + i8;
                int cc = c * 2 + (seg & 1);
                u32 r4[4];
                ldm4(r4, sb + 8192 + row * 128 + ((cc ^ (row & 7)) << 4));
                bf[np * 2][0] = r4[0]; bf[np * 2][1] = r4[1];
                bf[np * 2 + 1][0] = r4[2]; bf[np * 2 + 1][1] = r4[3];
            }
#pragma unroll
            for (int j = 0; j < 8; j++) mma16816(sc[j], qa[1][c], bf[j]);
        }

        const float* bias = (const float*)(smem + 3 * STAGE + s_cur * 256);
        float mx0 = -1e30f, mx1 = -1e30f;
#pragma unroll
        for (int j = 0; j < 8; j++) {
            int col = j * 8 + cp;
            float b0 = bias[col], b1 = bias[col + 1];
            sc[j][0] += b0; sc[j][1] += b1;
            sc[j][2] += b0; sc[j][3] += b1;
            mx0 = fmaxf(mx0, fmaxf(sc[j][0], sc[j][1]));
            mx1 = fmaxf(mx1, fmaxf(sc[j][2], sc[j][3]));
        }
        mx0 = fmaxf(mx0, __shfl_xor_sync(~0u, mx0, 1));
        mx0 = fmaxf(mx0, __shfl_xor_sync(~0u, mx0, 2));
        mx1 = fmaxf(mx1, __shfl_xor_sync(~0u, mx1, 1));
        mx1 = fmaxf(mx1, __shfl_xor_sync(~0u, mx1, 2));
        float nm0 = fmaxf(m0, mx0), nm1 = fmaxf(m1, mx1);
        float cr0 = exp2f(m0 - nm0), cr1 = exp2f(m1 - nm1);
        m0 = nm0; m1 = nm1;
        float sum0 = 0.f, sum1 = 0.f;
#pragma unroll
        for (int j = 0; j < 8; j++) {
            sc[j][0] = exp2f(sc[j][0] - nm0);
            sc[j][1] = exp2f(sc[j][1] - nm0);
            sc[j][2] = exp2f(sc[j][2] - nm1);
            sc[j][3] = exp2f(sc[j][3] - nm1);
            sum0 += sc[j][0] + sc[j][1];
            sum1 += sc[j][2] + sc[j][3];
        }
        sum0 += __shfl_xor_sync(~0u, sum0, 1);
        sum0 += __shfl_xor_sync(~0u, sum0, 2);
        sum1 += __shfl_xor_sync(~0u, sum1, 1);
        sum1 += __shfl_xor_sync(~0u, sum1, 2);
        l0 = l0 * cr0 + sum0;
        l1 = l1 * cr1 + sum1;
#pragma unroll
        for (int j = 0; j < 8; j++) {
            ctx[j][0] *= cr0; ctx[j][1] *= cr0;
            ctx[j][2] *= cr1; ctx[j][3] *= cr1;
        }

        u32 pa[4][4];
#pragma unroll
        for (int c = 0; c < 4; c++) {
            pa[c][0] = pack2(sc[2 * c][0], sc[2 * c][1]);
            pa[c][1] = pack2(sc[2 * c][2], sc[2 * c][3]);
            pa[c][2] = pack2(sc[2 * c + 1][0], sc[2 * c + 1][1]);
            pa[c][3] = pack2(sc[2 * c + 1][2], sc[2 * c + 1][3]);
        }

#pragma unroll
        for (int c = 0; c < 4; c++) {
            u32 bv[8][2];
#pragma unroll
            for (int jp = 0; jp < 4; jp++) {
                int srow = c * 16 + (seg & 1) * 8 + i8;
                int cseg = jp * 2 + (seg >> 1);
                u32 r4[4];
                ldm4t(r4, sb + 16384 + srow * 128 + ((cseg ^ (srow & 7)) << 4));
                bv[2 * jp][0] = r4[0]; bv[2 * jp][1] = r4[1];
                bv[2 * jp + 1][0] = r4[2]; bv[2 * jp + 1][1] = r4[3];
            }
#pragma unroll
            for (int j = 0; j < 8; j++) mma16816(ctx[j], pa[c], bv[j]);
        }
        s_cur = (s_cur == 2) ? 0 : s_cur + 1;
        s_pre = (s_pre == 2) ? 0 : s_pre + 1;
    }

    const float inv0 = 1.f / l0, inv1 = 1.f / l1;
    const int mrow = t0 + w * 16 + r;
#pragma unroll
    for (int j = 0; j < 8; j++) {
        int col = h * 64 + j * 8 + cp;
        size_t a0 = ((size_t)(mrow * 8 + b)) * 1024 + col;
        *(u32*)(g_ch + a0) = pack2(ctx[j][0] * inv0, ctx[j][1] * inv0);
        size_t a1 = ((size_t)((mrow + 8) * 8 + b)) * 1024 + col;
        *(u32*)(g_ch + a1) = pack2(ctx[j][2] * inv1, ctx[j][3] * inv1);
    }
}

// ---------------- launch ----------------
extern "C" void kernel_launch(void* const* d_in, const int* in_sizes, int n_in,
                              void* d_out, int out_size) {
    const float* query = (const float*)d_in[0];
    const float* key = (const float*)d_in[1];
    const float* tgt = (const float*)d_in[2];
    const float* src = (const float*)d_in[3];
    const float* wq_f = (const float*)d_in[4];
    const float* wkv_f = (const float*)d_in[5];
    const float* wo_f = (const float*)d_in[6];
    const unsigned char* mask = (const unsigned char*)d_in[7];
    float* out = (float*)d_out;

    const int SM4 = 3 * 4 * 128 * 64;          // 96 KB (4-tile, ring-3)
    const int SM2 = 3 * 2 * 128 * 64;          // 48 KB (2-tile, ring-3)
    const int SMATT = 3 * 3 * 8192 + 768;      // 74.25 KB (ring-3 + bias)
    cudaFuncSetAttribute(attn_fused_k,
                         cudaFuncAttributeMaxDynamicSharedMemorySize, SMATT);
    cudaFuncSetAttribute(qkv_proj_k,
                         cudaFuncAttributeMaxDynamicSharedMemorySize, SM4);
    cudaFuncSetAttribute(gemmo_k,
                         cudaFuncAttributeMaxDynamicSharedMemorySize, SM2);

    // merged input-split + weight-build
    prep_k<<<24576, 256>>>(query, key, wq_f, wkv_f, wo_f, tgt, src);

    // q-proj (z=0), k-proj (z=1): 2-pass alpha-combined; v-proj (z=2): 1-pass
    qkv_proj_k<<<dim3(8, 64, 3), 256, SM4>>>();

    // fused attention: single-accumulator S + mask + exp2 softmax + P@V -> ch
    attn_fused_k<<<dim3(8, 128), 256, SMATT>>>(mask);

    // out = ch @ wo^T (single term), fp32 out
    gemmo_k<<<dim3(8, 64), 256, SM2>>>(out);
}

// round 16
// speedup vs baseline: 2.4137x; 1.0297x over previous
#include <cuda_runtime.h>
#include <cuda_fp16.h>
#include <cstdint>
#include <cstddef>

using u32 = uint32_t;
using u64 = uint64_t;
#define MTOT 8192

// ---------------- static scratch (no allocation) ----------------
__device__ __half g_xqh[MTOT * 1024], g_xqs[MTOT * 1024];
__device__ __half g_xkh[MTOT * 1024], g_xks[MTOT * 1024];
__device__ __half g_wqh[1024 * 1024], g_wqs[1024 * 1024];   // ws32 form
__device__ __half g_wkh[1024 * 1024], g_wks[1024 * 1024];   // ws32 form
__device__ __half g_wvh[1024 * 1024];
__device__ __half g_woh[1024 * 1024];
__device__ __half g_qh[MTOT * 1024], g_qs[MTOT * 1024];     // q scaled by (32/33)^2
__device__ __half g_kh[MTOT * 1024], g_ks[MTOT * 1024];     // ks in ks32 form
__device__ __half g_vh[MTOT * 1024];
__device__ __half g_ch[MTOT * 1024];

// ---------------- helpers ----------------
__device__ __forceinline__ u32 smem_u32(const void* p) {
    u32 a;
    asm("{ .reg .u64 t; cvta.to.shared.u64 t, %1; cvt.u32.u64 %0, t; }"
        : "=r"(a) : "l"(p));
    return a;
}
__device__ __forceinline__ float ex2f(float x) {
    float y;
    asm("ex2.approx.ftz.f32 %0, %1;" : "=f"(y) : "f"(x));
    return y;
}
// alpha split: s = fp16(f - (31/32)*hi)  (= hi/32 + lo)
__device__ __forceinline__ void splitA(float f0, float f1, u32& h, u32& s) {
    __half a = __float2half_rn(f0), b = __float2half_rn(f1);
    h = (u32)__half_as_ushort(a) | ((u32)__half_as_ushort(b) << 16);
    __half c = __float2half_rn(f0 - 0.96875f * __half2float(a));
    __half d = __float2half_rn(f1 - 0.96875f * __half2float(b));
    s = (u32)__half_as_ushort(c) | ((u32)__half_as_ushort(d) << 16);
}
// ws32 split: s = fp16(32*f - 31*hi)  (= hi + 32*lo)
__device__ __forceinline__ void splitW(float f0, float f1, u32& h, u32& s) {
    __half a = __float2half_rn(f0), b = __float2half_rn(f1);
    h = (u32)__half_as_ushort(a) | ((u32)__half_as_ushort(b) << 16);
    __half c = __float2half_rn(32.f * f0 - 31.f * __half2float(a));
    __half d = __float2half_rn(32.f * f1 - 31.f * __half2float(b));
    s = (u32)__half_as_ushort(c) | ((u32)__half_as_ushort(d) << 16);
}
__device__ __forceinline__ u32 pack2(float f0, float f1) {
    __half2 hh = __floats2half2_rn(f0, f1);
    return *reinterpret_cast<u32*>(&hh);
}
__device__ __forceinline__ void cpa16(u32 s, const void* g) {
    asm volatile("cp.async.cg.shared.global [%0], [%1], 16;"
                 :: "r"(s), "l"((u64)__cvta_generic_to_global(g)));
}
__device__ __forceinline__ void ldm4(u32* r, u32 addr) {
    asm volatile("ldmatrix.sync.aligned.m8n8.x4.shared.b16 {%0,%1,%2,%3}, [%4];"
                 : "=r"(r[0]), "=r"(r[1]), "=r"(r[2]), "=r"(r[3]) : "r"(addr));
}
__device__ __forceinline__ void ldm4t(u32* r, u32 addr) {
    asm volatile("ldmatrix.sync.aligned.m8n8.x4.trans.shared.b16 {%0,%1,%2,%3}, [%4];"
                 : "=r"(r[0]), "=r"(r[1]), "=r"(r[2]), "=r"(r[3]) : "r"(addr));
}
__device__ __forceinline__ void mma16816(float* d, const u32* a, const u32* b) {
    asm volatile(
        "mma.sync.aligned.m16n8k16.row.col.f32.f16.f16.f32 "
        "{%0,%1,%2,%3},{%4,%5,%6,%7},{%8,%9},{%0,%1,%2,%3};"
        : "+f"(d[0]), "+f"(d[1]), "+f"(d[2]), "+f"(d[3])
        : "r"(a[0]), "r"(a[1]), "r"(a[2]), "r"(a[3]), "r"(b[0]), "r"(b[1]));
}

// ---------------- merged prep: input split + weight build -------------------
__global__ __launch_bounds__(256) void prep_k(
    const float* __restrict__ q, const float* __restrict__ kk,
    const float* __restrict__ wq_f, const float* __restrict__ wkv_f,
    const float* __restrict__ wo_f, const float* __restrict__ tgt,
    const float* __restrict__ src) {
    const u32 bid = blockIdx.x;
    if (bid < 8192) {
        size_t idx = (size_t)bid * 256 + threadIdx.x;  // 0..2M-1
        size_t i = idx & ((1u << 20) - 1);
        const float* sp = (idx < (1u << 20)) ? q : kk;
        __half* dh = (idx < (1u << 20)) ? g_xqh : g_xkh;
        __half* ds = (idx < (1u << 20)) ? g_xqs : g_xks;
        size_t e = i * 8;
        float4 a = ((const float4*)(sp + e))[0];
        float4 b = ((const float4*)(sp + e))[1];
        float f[8] = {a.x, a.y, a.z, a.w, b.x, b.y, b.z, b.w};
        u32 ph[4], ps[4];
#pragma unroll
        for (int j = 0; j < 4; j++) splitA(f[2 * j], f[2 * j + 1], ph[j], ps[j]);
        *(uint4*)(dh + e) = make_uint4(ph[0], ph[1], ph[2], ph[3]);
        *(uint4*)(ds + e) = make_uint4(ps[0], ps[1], ps[2], ps[3]);
    } else {
        u32 n = (bid - 8192) * 256 + threadIdx.x;  // 0..4M-1
        u32 seg = n >> 20, m = n & 1048575;
        const float* w;
        const float* f;
        __half *dh, *ds = nullptr;
        float scale = 1.f;
        if (seg == 0) {
            w = wq_f + (size_t)m * 8; f = tgt; dh = g_wqh; ds = g_wqs;
            scale = 0.125f * 1.44269504088896f;   // fold log2(e): exp2 softmax
        }
        else if (seg == 1) { w = wkv_f + (size_t)m * 8; f = src; dh = g_wkh; ds = g_wks; }
        else if (seg == 2) { w = wkv_f + ((size_t)1048576 + m) * 8; f = src; dh = g_wvh; }
        else { w = wo_f + (size_t)m * 8; f = tgt; dh = g_woh; }
        float acc = 0.f;
#pragma unroll
        for (int r = 0; r < 8; r++) acc += w[r] * f[r];
        acc *= scale;
        __half h = __float2half_rn(acc);
        dh[m] = h;
        if (ds) ds[m] = __float2half_rn(32.f * acc - 31.f * __half2float(h));
    }
}

// ---------------- merged q/k/v projection (one launch) ----------------------
// z=0: q: acc = xh.wh + xs.ws32; out = (32/33)^2 * acc -> qh + qs (alpha split)
// z=1: k: acc same; out = (32/33)*acc -> kh + ks32 (splitW)
// z=2: v = xkh.wvh (single term) -> plain vh
__global__ __launch_bounds__(256, 2) void qkv_proj_k() {
    constexpr int STAGE = 4 * 128 * 64;
    extern __shared__ char smem[];
    const u32 sbase = smem_u32(smem);

    const int tid = threadIdx.x, lane = tid & 31, wid = tid >> 5;
    const int m0 = blockIdx.y * 128, n0 = blockIdx.x * 128;
    const int z = blockIdx.z;
    const __half *Ah, *As, *Bh, *Bs;
    __half *CH, *CL;
    if (z == 0) { Ah = g_xqh; As = g_xqs; Bh = g_wqh; Bs = g_wqs; CH = g_qh; CL = g_qs; }
    else if (z == 1) { Ah = g_xkh; As = g_xks; Bh = g_wkh; Bs = g_wks; CH = g_kh; CL = g_ks; }
    else { Ah = g_xkh; As = g_xkh; Bh = g_wvh; Bs = g_wvh; CH = g_vh; CL = nullptr; }
    const bool full = (z < 2);
    const __half* tiles[4];
    tiles[0] = Ah + (size_t)m0 * 1024;
    tiles[1] = As + (size_t)m0 * 1024;
    tiles[2] = Bh + (size_t)n0 * 1024;
    tiles[3] = Bs + (size_t)n0 * 1024;

    float acc[2][8][4];
#pragma unroll
    for (int a = 0; a < 2; a++)
#pragma unroll
        for (int b = 0; b < 8; b++)
#pragma unroll
            for (int c = 0; c < 4; c++) acc[a][b][c] = 0.f;

    auto load_stage = [&](int kc, int bufi) {
        const u32 sb = sbase + bufi * STAGE;
#pragma unroll
        for (int p = 0; p < 8; p++) {
            if (!full && ((p >> 1) == 1 || (p >> 1) == 3)) continue;
            const int L = p * 256 + tid;
            const int row = L >> 2, c = L & 3;
            const __half* g = tiles[row >> 7] + (size_t)(row & 127) * 1024 +
                              kc * 32 + c * 8;
            cpa16(sb + row * 64 + ((c ^ ((row >> 1) & 3)) << 4), g);
        }
    };

    load_stage(0, 0);
    asm volatile("cp.async.commit_group;");
    load_stage(1, 1);
    asm volatile("cp.async.commit_group;");
    int s_cur = 0, s_pre = 2;
    const int wm = wid >> 1, wn = wid & 1;
    for (int kc = 0; kc < 32; kc++) {
        asm volatile("cp.async.wait_group 1;");
        __syncthreads();
        if (kc + 2 < 32) load_stage(kc + 2, s_pre);
        asm volatile("cp.async.commit_group;");
        const u32 sb = sbase + s_cur * STAGE;
        const int i8 = lane & 7, seg = lane >> 3;
#pragma unroll
        for (int kstep = 0; kstep < 2; kstep++) {
            u32 ra0[2][4], ra1[2][4];
#pragma unroll
            for (int mt = 0; mt < 2; mt++) {
                int row = wm * 32 + mt * 16 + (lane & 15);
                int c = kstep * 2 + (lane >> 4);
                u32 sw = (u32)((c ^ ((row >> 1) & 3)) << 4);
                ldm4(ra0[mt], sb + row * 64 + sw);
                if (full) ldm4(ra1[mt], sb + (row + 128) * 64 + sw);
            }
            u32 rb[8][2];
#pragma unroll
            for (int np = 0; np < 4; np++) {
                int row = 256 + wn * 64 + np * 16 + (seg >> 1) * 8 + i8;
                int c = kstep * 2 + (seg & 1);
                u32 r4[4];
                ldm4(r4, sb + row * 64 + ((c ^ ((row >> 1) & 3)) << 4));
                rb[np * 2][0] = r4[0]; rb[np * 2][1] = r4[1];
                rb[np * 2 + 1][0] = r4[2]; rb[np * 2 + 1][1] = r4[3];
            }
#pragma unroll
            for (int mt = 0; mt < 2; mt++)
#pragma unroll
                for (int nt = 0; nt < 8; nt++)
                    mma16816(acc[mt][nt], ra0[mt], rb[nt]);
            if (full) {
#pragma unroll
                for (int np = 0; np < 4; np++) {
                    int row = 384 + wn * 64 + np * 16 + (seg >> 1) * 8 + i8;
                    int c = kstep * 2 + (seg & 1);
                    u32 r4[4];
                    ldm4(r4, sb + row * 64 + ((c ^ ((row >> 1) & 3)) << 4));
                    rb[np * 2][0] = r4[0]; rb[np * 2][1] = r4[1];
                    rb[np * 2 + 1][0] = r4[2]; rb[np * 2 + 1][1] = r4[3];
                }
#pragma unroll
                for (int mt = 0; mt < 2; mt++)
#pragma unroll
                    for (int nt = 0; nt < 8; nt++)
                        mma16816(acc[mt][nt], ra1[mt], rb[nt]);
            }
        }
        s_cur = (s_cur == 2) ? 0 : s_cur + 1;
        s_pre = (s_pre == 2) ? 0 : s_pre + 1;
    }

    const int r0 = m0 + wm * 32 + (lane >> 2);
    const int cb = n0 + wn * 64 + (lane & 3) * 2;
    const float RS = (z == 0) ? (32.f / 33.f) * (32.f / 33.f) : (32.f / 33.f);
#pragma unroll
    for (int mt = 0; mt < 2; mt++)
#pragma unroll
        for (int nt = 0; nt < 8; nt++) {
            int col = cb + nt * 8;
#pragma unroll
            for (int hh = 0; hh < 2; hh++) {
                int rr = r0 + mt * 16 + hh * 8;
                float f0 = acc[mt][nt][hh * 2], f1 = acc[mt][nt][hh * 2 + 1];
                size_t addr = (size_t)rr * 1024 + col;
                if (CL) {
                    f0 *= RS; f1 *= RS;
                    u32 h, s;
                    if (z == 0) splitA(f0, f1, h, s);
                    else        splitW(f0, f1, h, s);
                    *(u32*)(CH + addr) = h;
                    *(u32*)(CL + addr) = s;
                } else {
                    *(u32*)(CH + addr) = pack2(f0, f1);
                }
            }
        }
}

// ---------------- out-projection: out = ch @ woh^T (single term, fp32 out) --
// BM=128, BN=64, BK=32. Stage {A 128r, B 64r} = 12KB, ring-3. 3 CTAs/SM.
__global__ __launch_bounds__(256, 3) void gemmo_k(float* __restrict__ CF) {
    constexpr int STAGE = 192 * 64;
    extern __shared__ char smem[];
    const u32 sbase = smem_u32(smem);

    const int tid = threadIdx.x, lane = tid & 31, wid = tid >> 5;
    const int m0 = blockIdx.y * 128, n0 = blockIdx.x * 64;
    const __half* tiles[2];
    tiles[0] = g_ch + (size_t)m0 * 1024;
    tiles[1] = g_woh + (size_t)n0 * 1024;

    float acc[2][4][4];
#pragma unroll
    for (int a = 0; a < 2; a++)
#pragma unroll
        for (int b = 0; b < 4; b++)
#pragma unroll
            for (int c = 0; c < 4; c++) acc[a][b][c] = 0.f;

    auto load_stage = [&](int kc, int bufi) {
        const u32 sb = sbase + bufi * STAGE;
#pragma unroll
        for (int p = 0; p < 3; p++) {
            const int L = p * 256 + tid;
            const int row = L >> 2, c = L & 3;
            const __half* g = tiles[row >> 7] + (size_t)(row & 127) * 1024 +
                              kc * 32 + c * 8;
            cpa16(sb + row * 64 + ((c ^ ((row >> 1) & 3)) << 4), g);
        }
    };

    load_stage(0, 0);
    asm volatile("cp.async.commit_group;");
    load_stage(1, 1);
    asm volatile("cp.async.commit_group;");
    int s_cur = 0, s_pre = 2;
    const int wm = wid >> 1, wn = wid & 1;
    for (int kc = 0; kc < 32; kc++) {
        asm volatile("cp.async.wait_group 1;");
        __syncthreads();
        if (kc + 2 < 32) load_stage(kc + 2, s_pre);
        asm volatile("cp.async.commit_group;");
        const u32 sb = sbase + s_cur * STAGE;
        const int i8 = lane & 7, seg = lane >> 3;
#pragma unroll
        for (int kstep = 0; kstep < 2; kstep++) {
            u32 ra0[2][4];
#pragma unroll
            for (int mt = 0; mt < 2; mt++) {
                int row = wm * 32 + mt * 16 + (lane & 15);
                int c = kstep * 2 + (lane >> 4);
                ldm4(ra0[mt], sb + row * 64 + ((c ^ ((row >> 1) & 3)) << 4));
            }
            u32 rb[4][2];
#pragma unroll
            for (int np = 0; np < 2; np++) {
                int row = 128 + wn * 32 + np * 16 + (seg >> 1) * 8 + i8;
                int c = kstep * 2 + (seg & 1);
                u32 r4[4];
                ldm4(r4, sb + row * 64 + ((c ^ ((row >> 1) & 3)) << 4));
                rb[np * 2][0] = r4[0]; rb[np * 2][1] = r4[1];
                rb[np * 2 + 1][0] = r4[2]; rb[np * 2 + 1][1] = r4[3];
            }
#pragma unroll
            for (int mt = 0; mt < 2; mt++)
#pragma unroll
                for (int nt = 0; nt < 4; nt++)
                    mma16816(acc[mt][nt], ra0[mt], rb[nt]);
        }
        s_cur = (s_cur == 2) ? 0 : s_cur + 1;
        s_pre = (s_pre == 2) ? 0 : s_pre + 1;
    }

    const int r0 = m0 + wm * 32 + (lane >> 2);
    const int cb = n0 + wn * 32 + (lane & 3) * 2;
#pragma unroll
    for (int mt = 0; mt < 2; mt++)
#pragma unroll
        for (int nt = 0; nt < 4; nt++) {
            int col = cb + nt * 8;
#pragma unroll
            for (int hh = 0; hh < 2; hh++) {
                int rr = r0 + mt * 16 + hh * 8;
                *(float2*)(CF + (size_t)rr * 1024 + col) =
                    make_float2(acc[mt][nt][hh * 2], acc[mt][nt][hh * 2 + 1]);
            }
        }
}

// ---------------- fused flash attention ----------------
// S = qh.kh + qs.ks32  (single accumulator; scales pre-folded into q).
// Tiles: kh, ks32, v (64x64 each). Ring-3, depth-2 prefetch, one barrier/iter.
// ex2.approx softmax (log2e folded into wq). ctx += P.V (trans-ldmatrix V).
__global__ __launch_bounds__(256, 2) void attn_fused_k(const unsigned char* __restrict__ mask) {
    extern __shared__ char smem[];
    const u32 sbase = smem_u32(smem);
    const int tid = threadIdx.x, lane = tid & 31, w = tid >> 5;
    const int z = blockIdx.y, b = z >> 4, h = z & 15;
    const int t0 = blockIdx.x * 128;
    const int r = lane >> 2, cp = (lane & 3) * 2;
    constexpr int STAGE = 3 * 8192;   // kh + ks32 + v

    u32 qa[2][4][4];
    {
        const int mrow = t0 + w * 16 + r;
#pragma unroll
        for (int c = 0; c < 4; c++)
#pragma unroll
            for (int i = 0; i < 4; i++) {
                int mm = mrow + (i & 1) * 8;
                int col = h * 64 + c * 16 + cp + (i >> 1) * 8;
                size_t ad = ((size_t)(mm * 8 + b)) * 1024 + col;
                qa[0][c][i] = *(const u32*)(g_qh + ad);
                qa[1][c][i] = *(const u32*)(g_qs + ad);
            }
    }

    float ctx[8][4];
#pragma unroll
    for (int j = 0; j < 8; j++)
#pragma unroll
        for (int c = 0; c < 4; c++) ctx[j][c] = 0.f;
    float m0 = -1e30f, m1 = -1e30f, l0 = 0.f, l1 = 0.f;

    auto load_stage = [&](int it, int st) {
        const int s0 = it * 64;
        const u32 sb = sbase + st * STAGE;
#pragma unroll
        for (int p = 0; p < 6; p++) {
            int L = p * 256 + tid;
            int tile = L >> 9, rr = (L >> 3) & 63, c = L & 7;
            const __half* g;
            if (tile == 0)
                g = g_kh + ((size_t)((s0 + rr) * 8 + b)) * 1024 + h * 64 + c * 8;
            else if (tile == 1)
                g = g_ks + ((size_t)((s0 + rr) * 8 + b)) * 1024 + h * 64 + c * 8;
            else
                g = g_vh + ((size_t)((s0 + rr) * 8 + b)) * 1024 + h * 64 + c * 8;
            cpa16(sb + tile * 8192 + rr * 128 + ((c ^ (rr & 7)) << 4), g);
        }
        if (tid < 64)
            ((float*)(smem + 3 * STAGE + st * 256))[tid] =
                mask[b * 1024 + s0 + tid] ? -1e30f : 0.f;
    };

    load_stage(0, 0);
    asm volatile("cp.async.commit_group;");
    load_stage(1, 1);
    asm volatile("cp.async.commit_group;");
    int s_cur = 0, s_pre = 2;
    for (int it = 0; it < 16; it++) {
        asm volatile("cp.async.wait_group 1;");
        __syncthreads();
        if (it + 2 < 16) load_stage(it + 2, s_pre);
        asm volatile("cp.async.commit_group;");
        const u32 sb = sbase + s_cur * STAGE;

        float sc[8][4];
#pragma unroll
        for (int j = 0; j < 8; j++)
#pragma unroll
            for (int c = 0; c < 4; c++) sc[j][c] = 0.f;

        const int i8 = lane & 7, seg = lane >> 3;
#pragma unroll
        for (int c = 0; c < 4; c++) {
            u32 bf[8][2];
#pragma unroll
            for (int np = 0; np < 4; np++) {
                int row = np * 16 + (seg >> 1) * 8 + i8;
                int cc = c * 2 + (seg & 1);
                u32 r4[4];
                ldm4(r4, sb + row * 128 + ((cc ^ (row & 7)) << 4));
                bf[np * 2][0] = r4[0]; bf[np * 2][1] = r4[1];
                bf[np * 2 + 1][0] = r4[2]; bf[np * 2 + 1][1] = r4[3];
            }
#pragma unroll
            for (int j = 0; j < 8; j++) mma16816(sc[j], qa[0][c], bf[j]);
#pragma unroll
            for (int np = 0; np < 4; np++) {
                int row = np * 16 + (seg >> 1) * 8 + i8;
                int cc = c * 2 + (seg & 1);
                u32 r4[4];
                ldm4(r4, sb + 8192 + row * 128 + ((cc ^ (row & 7)) << 4));
                bf[np * 2][0] = r4[0]; bf[np * 2][1] = r4[1];
                bf[np * 2 + 1][0] = r4[2]; bf[np * 2 + 1][1] = r4[3];
            }
#pragma unroll
            for (int j = 0; j < 8; j++) mma16816(sc[j], qa[1][c], bf[j]);
        }

        const float* bias = (const float*)(smem + 3 * STAGE + s_cur * 256);
        float mx0 = -1e30f, mx1 = -1e30f;
#pragma unroll
        for (int j = 0; j < 8; j++) {
            int col = j * 8 + cp;
            float b0 = bias[col], b1 = bias[col + 1];
            sc[j][0] += b0; sc[j][1] += b1;
            sc[j][2] += b0; sc[j][3] += b1;
            mx0 = fmaxf(mx0, fmaxf(sc[j][0], sc[j][1]));
            mx1 = fmaxf(mx1, fmaxf(sc[j][2], sc[j][3]));
        }
        mx0 = fmaxf(mx0, __shfl_xor_sync(~0u, mx0, 1));
        mx0 = fmaxf(mx0, __shfl_xor_sync(~0u, mx0, 2));
        mx1 = fmaxf(mx1, __shfl_xor_sync(~0u, mx1, 1));
        mx1 = fmaxf(mx1, __shfl_xor_sync(~0u, mx1, 2));
        float nm0 = fmaxf(m0, mx0), nm1 = fmaxf(m1, mx1);
        float cr0 = ex2f(m0 - nm0), cr1 = ex2f(m1 - nm1);
        m0 = nm0; m1 = nm1;
        float sum0 = 0.f, sum1 = 0.f;
#pragma unroll
        for (int j = 0; j < 8; j++) {
            sc[j][0] = ex2f(sc[j][0] - nm0);
            sc[j][1] = ex2f(sc[j][1] - nm0);
            sc[j][2] = ex2f(sc[j][2] - nm1);
            sc[j][3] = ex2f(sc[j][3] - nm1);
            sum0 += sc[j][0] + sc[j][1];
            sum1 += sc[j][2] + sc[j][3];
        }
        sum0 += __shfl_xor_sync(~0u, sum0, 1);
        sum0 += __shfl_xor_sync(~0u, sum0, 2);
        sum1 += __shfl_xor_sync(~0u, sum1, 1);
        sum1 += __shfl_xor_sync(~0u, sum1, 2);
        l0 = l0 * cr0 + sum0;
        l1 = l1 * cr1 + sum1;
#pragma unroll
        for (int j = 0; j < 8; j++) {
            ctx[j][0] *= cr0; ctx[j][1] *= cr0;
            ctx[j][2] *= cr1; ctx[j][3] *= cr1;
        }

        u32 pa[4][4];
#pragma unroll
        for (int c = 0; c < 4; c++) {
            pa[c][0] = pack2(sc[2 * c][0], sc[2 * c][1]);
            pa[c][1] = pack2(sc[2 * c][2], sc[2 * c][3]);
            pa[c][2] = pack2(sc[2 * c + 1][0], sc[2 * c + 1][1]);
            pa[c][3] = pack2(sc[2 * c + 1][2], sc[2 * c + 1][3]);
        }

#pragma unroll
        for (int c = 0; c < 4; c++) {
            u32 bv[8][2];
#pragma unroll
            for (int jp = 0; jp < 4; jp++) {
                int srow = c * 16 + (seg & 1) * 8 + i8;
                int cseg = jp * 2 + (seg >> 1);
                u32 r4[4];
                ldm4t(r4, sb + 16384 + srow * 128 + ((cseg ^ (srow & 7)) << 4));
                bv[2 * jp][0] = r4[0]; bv[2 * jp][1] = r4[1];
                bv[2 * jp + 1][0] = r4[2]; bv[2 * jp + 1][1] = r4[3];
            }
#pragma unroll
            for (int j = 0; j < 8; j++) mma16816(ctx[j], pa[c], bv[j]);
        }
        s_cur = (s_cur == 2) ? 0 : s_cur + 1;
        s_pre = (s_pre == 2) ? 0 : s_pre + 1;
    }

    const float inv0 = 1.f / l0, inv1 = 1.f / l1;
    const int mrow = t0 + w * 16 + r;
#pragma unroll
    for (int j = 0; j < 8; j++) {
        int col = h * 64 + j * 8 + cp;
        size_t a0 = ((size_t)(mrow * 8 + b)) * 1024 + col;
        *(u32*)(g_ch + a0) = pack2(ctx[j][0] * inv0, ctx[j][1] * inv0);
        size_t a1 = ((size_t)((mrow + 8) * 8 + b)) * 1024 + col;
        *(u32*)(g_ch + a1) = pack2(ctx[j][2] * inv1, ctx[j][3] * inv1);
    }
}

// ---------------- launch ----------------
extern "C" void kernel_launch(void* const* d_in, const int* in_sizes, int n_in,
                              void* d_out, int out_size) {
    const float* query = (const float*)d_in[0];
    const float* key = (const float*)d_in[1];
    const float* tgt = (const float*)d_in[2];
    const float* src = (const float*)d_in[3];
    const float* wq_f = (const float*)d_in[4];
    const float* wkv_f = (const float*)d_in[5];
    const float* wo_f = (const float*)d_in[6];
    const unsigned char* mask = (const unsigned char*)d_in[7];
    float* out = (float*)d_out;

    const int SM4 = 3 * 4 * 128 * 64;          // 96 KB (4-tile, ring-3)
    const int SMO = 3 * 192 * 64;              // 36 KB (A+B, ring-3)
    const int SMATT = 3 * 3 * 8192 + 768;      // 74.25 KB (ring-3 + bias)
    cudaFuncSetAttribute(attn_fused_k,
                         cudaFuncAttributeMaxDynamicSharedMemorySize, SMATT);
    cudaFuncSetAttribute(qkv_proj_k,
                         cudaFuncAttributeMaxDynamicSharedMemorySize, SM4);
    cudaFuncSetAttribute(gemmo_k,
                         cudaFuncAttributeMaxDynamicSharedMemorySize, SMO);

    // merged input-split + weight-build
    prep_k<<<24576, 256>>>(query, key, wq_f, wkv_f, wo_f, tgt, src);

    // q-proj (z=0), k-proj (z=1): 2-pass alpha-combined; v-proj (z=2): 1-pass
    qkv_proj_k<<<dim3(8, 64, 3), 256, SM4>>>();

    // fused attention: single-accumulator S + mask + ex2 softmax + P@V -> ch
    attn_fused_k<<<dim3(8, 128), 256, SMATT>>>(mask);

    // out = ch @ wo^T (single term), fp32 out, BN=64 @ 3 CTAs/SM
    gemmo_k<<<dim3(16, 64), 256, SMO>>>(out);
}